// round 2
// baseline (speedup 1.0000x reference)
#include <cuda_runtime.h>
#include <cuda_bf16.h>
#include <cstdint>

#define SEQ  2048
#define HID  5120
#define QKVN 15360

// Scratch (device globals: allocation-free per harness rules)
__device__ float g_qkv[SEQ * QKVN];   // QKV projection output [2048][15360]
__device__ float g_attn[SEQ * HID];   // attention output      [2048][5120]

// ---------------------------------------------------------------------------
// Helpers
// ---------------------------------------------------------------------------
__device__ __forceinline__ uint32_t cvta_s(const void* p) {
    return (uint32_t)__cvta_generic_to_shared(p);
}

__device__ __forceinline__ void ldsm4(uint32_t r[4], uint32_t a) {
    asm volatile("ldmatrix.sync.aligned.m8n8.x4.shared.b16 {%0,%1,%2,%3}, [%4];"
                 : "=r"(r[0]), "=r"(r[1]), "=r"(r[2]), "=r"(r[3]) : "r"(a));
}
__device__ __forceinline__ void ldsm4t(uint32_t r[4], uint32_t a) {
    asm volatile("ldmatrix.sync.aligned.m8n8.x4.trans.shared.b16 {%0,%1,%2,%3}, [%4];"
                 : "=r"(r[0]), "=r"(r[1]), "=r"(r[2]), "=r"(r[3]) : "r"(a));
}
__device__ __forceinline__ void mma_bf16(float d[4], const uint32_t a[4], const uint32_t b[2]) {
    asm volatile("mma.sync.aligned.m16n8k16.row.col.f32.bf16.bf16.f32 "
                 "{%0,%1,%2,%3}, {%4,%5,%6,%7}, {%8,%9}, {%0,%1,%2,%3};"
                 : "+f"(d[0]), "+f"(d[1]), "+f"(d[2]), "+f"(d[3])
                 : "r"(a[0]), "r"(a[1]), "r"(a[2]), "r"(a[3]), "r"(b[0]), "r"(b[1]));
}

// Split two floats into (hi,lo) bf16 pairs packed as b32 (low half = first elem)
__device__ __forceinline__ void split2(float f0, float f1, uint32_t& h, uint32_t& l) {
    __nv_bfloat16 h0 = __float2bfloat16_rn(f0), h1 = __float2bfloat16_rn(f1);
    float r0 = f0 - __bfloat162float(h0), r1 = f1 - __bfloat162float(h1);
    __nv_bfloat16 e0 = __float2bfloat16_rn(r0), e1 = __float2bfloat16_rn(r1);
    h = (uint32_t)__bfloat16_as_ushort(h0) | ((uint32_t)__bfloat16_as_ushort(h1) << 16);
    l = (uint32_t)__bfloat16_as_ushort(e0) | ((uint32_t)__bfloat16_as_ushort(e1) << 16);
}

// Convert float4 -> hi/lo bf16 (4 each) and store 8B to smem hi + smem lo
__device__ __forceinline__ void cvst4(__nv_bfloat16* ph, __nv_bfloat16* pl, float4 v) {
    uint32_t h01, l01, h23, l23;
    split2(v.x, v.y, h01, l01);
    split2(v.z, v.w, h23, l23);
    uint2 H; H.x = h01; H.y = h23;
    uint2 L; L.x = l01; L.y = l23;
    *reinterpret_cast<uint2*>(ph) = H;
    *reinterpret_cast<uint2*>(pl) = L;
}

// ---------------------------------------------------------------------------
// GEMM: C[M,N] = A[M,K] * B[N,K]^T   (fp32 in gmem, split-bf16 mma, fp32 out)
// Tiles: BM=128, BN=128, BK=32. 256 threads = 8 warps as 4(m) x 2(n),
// warp tile = 32(m) x 64(n).
// ---------------------------------------------------------------------------
#define GPAD 40   // padded row length (bf16) -> 80B stride, ldmatrix conflict-free

__global__ __launch_bounds__(256) void gemm_abt_kernel(
    const float* __restrict__ A, const float* __restrict__ B, float* __restrict__ C,
    int M, int N, int K)
{
    __shared__ __nv_bfloat16 sAh[128 * GPAD];
    __shared__ __nv_bfloat16 sAl[128 * GPAD];
    __shared__ __nv_bfloat16 sBh[128 * GPAD];
    __shared__ __nv_bfloat16 sBl[128 * GPAD];

    const int tid = threadIdx.x;
    const int bn = blockIdx.x, bm = blockIdx.y;
    const int K4 = K >> 2;
    const int row0 = tid >> 3;   // 0..31
    const int c4   = tid & 7;    // 0..7 (float4 column within BK=32)

    const float4* A4 = reinterpret_cast<const float4*>(A) + (size_t)(bm * 128 + row0) * K4 + c4;
    const float4* B4 = reinterpret_cast<const float4*>(B) + (size_t)(bn * 128 + row0) * K4 + c4;

    const int warp = tid >> 5, lane = tid & 31;
    const int wm = warp >> 1, wn = warp & 1;
    const int la = (lane & 15) * GPAD + ((lane >> 4) << 3);
    const int lb = (((lane >> 4) << 3) + (lane & 7)) * GPAD + (((lane >> 3) & 1) << 3);
    const uint32_t sAhB = cvta_s(sAh), sAlB = cvta_s(sAl);
    const uint32_t sBhB = cvta_s(sBh), sBlB = cvta_s(sBl);

    float acc[2][8][4] = {};

    float4 ar[4], br[4];
#pragma unroll
    for (int i = 0; i < 4; i++) {
        ar[i] = A4[(size_t)i * 32 * K4];
        br[i] = B4[(size_t)i * 32 * K4];
    }

    const int nk = K / 32;
#pragma unroll 1
    for (int kt = 0; kt < nk; kt++) {
        __syncthreads();
#pragma unroll
        for (int i = 0; i < 4; i++) {
            int off = (row0 + i * 32) * GPAD + c4 * 4;
            cvst4(sAh + off, sAl + off, ar[i]);
            cvst4(sBh + off, sBl + off, br[i]);
        }
        __syncthreads();
        if (kt + 1 < nk) {
#pragma unroll
            for (int i = 0; i < 4; i++) {
                ar[i] = A4[(size_t)i * 32 * K4 + (size_t)(kt + 1) * 8];
                br[i] = B4[(size_t)i * 32 * K4 + (size_t)(kt + 1) * 8];
            }
        }
#pragma unroll
        for (int kk = 0; kk < 2; kk++) {
            uint32_t Ah[2][4], Alo[2][4];
#pragma unroll
            for (int mi = 0; mi < 2; mi++) {
                uint32_t off = (uint32_t)(((wm * 32 + mi * 16) * GPAD + kk * 16 + la) << 1);
                ldsm4(Ah[mi], sAhB + off);
                ldsm4(Alo[mi], sAlB + off);
            }
            uint32_t Bh[8][2], Blo[8][2];
#pragma unroll
            for (int ni = 0; ni < 4; ni++) {
                uint32_t t4[4];
                uint32_t off = (uint32_t)(((wn * 64 + ni * 16) * GPAD + kk * 16 + lb) << 1);
                ldsm4(t4, sBhB + off);
                Bh[2 * ni][0] = t4[0]; Bh[2 * ni][1] = t4[1];
                Bh[2 * ni + 1][0] = t4[2]; Bh[2 * ni + 1][1] = t4[3];
                ldsm4(t4, sBlB + off);
                Blo[2 * ni][0] = t4[0]; Blo[2 * ni][1] = t4[1];
                Blo[2 * ni + 1][0] = t4[2]; Blo[2 * ni + 1][1] = t4[3];
            }
#pragma unroll
            for (int mi = 0; mi < 2; mi++)
#pragma unroll
                for (int nj = 0; nj < 8; nj++) {
                    mma_bf16(acc[mi][nj], Ah[mi], Bh[nj]);
                    mma_bf16(acc[mi][nj], Ah[mi], Blo[nj]);
                    mma_bf16(acc[mi][nj], Alo[mi], Bh[nj]);
                }
        }
    }

    const int g = lane >> 2, t = lane & 3;
#pragma unroll
    for (int mi = 0; mi < 2; mi++) {
        int r = bm * 128 + wm * 32 + mi * 16 + g;
#pragma unroll
        for (int nj = 0; nj < 8; nj++) {
            int c = bn * 128 + wn * 64 + nj * 8 + t * 2;
            *reinterpret_cast<float2*>(C + (size_t)r * N + c) =
                make_float2(acc[mi][nj][0], acc[mi][nj][1]);
            *reinterpret_cast<float2*>(C + (size_t)(r + 8) * N + c) =
                make_float2(acc[mi][nj][2], acc[mi][nj][3]);
        }
    }
}

// ---------------------------------------------------------------------------
// Flash attention: causal + ALiBi, 40 heads, d=128.
// CTA = (q-block of 64 rows, head). 128 threads = 4 warps, 16 q-rows/warp.
// kv tiles of 64. Split-bf16 mma for QK^T and PV, fp32 online softmax.
// ---------------------------------------------------------------------------
#define APAD 136
#define ATTN_SMEM (6 * 64 * APAD * 2)

__global__ __launch_bounds__(128) void attn_kernel(const float* __restrict__ qkv,
                                                   float* __restrict__ out)
{
    extern __shared__ __nv_bfloat16 sm[];
    __nv_bfloat16* sQh = sm;
    __nv_bfloat16* sQl = sQh + 64 * APAD;
    __nv_bfloat16* sKh = sQl + 64 * APAD;
    __nv_bfloat16* sKl = sKh + 64 * APAD;
    __nv_bfloat16* sVh = sKl + 64 * APAD;
    __nv_bfloat16* sVl = sVh + 64 * APAD;

    const int tid = threadIdx.x, lane = tid & 31, warp = tid >> 5;
    const int qb = gridDim.x - 1 - blockIdx.x;  // heavy blocks launch first
    const int h = blockIdx.y;
    const int q0 = qb * 64;
    const float slope = (h < 32) ? exp2f(-0.25f * (float)(h + 1))
                                 : exp2f(-0.125f * (float)(2 * (h - 32) + 1));
    const float scale = 0.08838834764831845f;  // 1/sqrt(128)

    const int lr = tid >> 5;  // 0..3 (row within 4-row load group)
    const int c4 = tid & 31;  // float4 column over d=128

    // Load Q tile once (rows q0..q0+63, head h)
    {
        const float4* Q4 = reinterpret_cast<const float4*>(qkv) + (size_t)q0 * 3840 + h * 32 + c4;
#pragma unroll
        for (int i = 0; i < 16; i++) {
            int row = lr + i * 4;
            float4 v = Q4[(size_t)row * 3840];
            int off = row * APAD + c4 * 4;
            cvst4(sQh + off, sQl + off, v);
        }
    }

    float m0 = -1e30f, m1 = -1e30f, l0 = 0.f, l1 = 0.f;
    float o[16][4] = {};

    const uint32_t QhB = cvta_s(sQh), QlB = cvta_s(sQl);
    const uint32_t KhB = cvta_s(sKh), KlB = cvta_s(sKl);
    const uint32_t VhB = cvta_s(sVh), VlB = cvta_s(sVl);
    const int qm = warp * 16;
    const int g = lane >> 2, t = lane & 3;
    const int la = (lane & 15) * APAD + ((lane >> 4) << 3);
    const int lb = (((lane >> 4) << 3) + (lane & 7)) * APAD + (((lane >> 3) & 1) << 3);
    const int lv = ((((lane >> 3) & 1) << 3) + (lane & 7)) * APAD + ((lane >> 4) << 3);
    const int qpos0 = q0 + qm + g, qpos1 = qpos0 + 8;

#pragma unroll 1
    for (int kb = 0; kb <= qb; kb++) {
        __syncthreads();
        {
            const float4* K4 = reinterpret_cast<const float4*>(qkv) +
                               (size_t)(kb * 64) * 3840 + 1280 + h * 32 + c4;
            const float4* V4 = K4 + 1280;
#pragma unroll
            for (int i = 0; i < 16; i++) {
                int row = lr + i * 4;
                int off = row * APAD + c4 * 4;
                cvst4(sKh + off, sKl + off, K4[(size_t)row * 3840]);
                cvst4(sVh + off, sVl + off, V4[(size_t)row * 3840]);
            }
        }
        __syncthreads();

        // ---- S = Q K^T (split 3-term) ----
        float sc[8][4];
#pragma unroll
        for (int i = 0; i < 8; i++)
#pragma unroll
            for (int j = 0; j < 4; j++) sc[i][j] = 0.f;

#pragma unroll
        for (int kc = 0; kc < 8; kc++) {
            uint32_t qh[4], ql[4];
            ldsm4(qh, QhB + (uint32_t)((qm * APAD + kc * 16 + la) << 1));
            ldsm4(ql, QlB + (uint32_t)((qm * APAD + kc * 16 + la) << 1));
#pragma unroll
            for (int np = 0; np < 4; np++) {
                uint32_t th[4], tl[4];
                uint32_t off = (uint32_t)(((np * 16) * APAD + kc * 16 + lb) << 1);
                ldsm4(th, KhB + off);
                ldsm4(tl, KlB + off);
                uint32_t bh0[2] = {th[0], th[1]}, bh1[2] = {th[2], th[3]};
                uint32_t bl0[2] = {tl[0], tl[1]}, bl1[2] = {tl[2], tl[3]};
                mma_bf16(sc[2 * np],     qh, bh0);
                mma_bf16(sc[2 * np],     qh, bl0);
                mma_bf16(sc[2 * np],     ql, bh0);
                mma_bf16(sc[2 * np + 1], qh, bh1);
                mma_bf16(sc[2 * np + 1], qh, bl1);
                mma_bf16(sc[2 * np + 1], ql, bh1);
            }
        }

        // ---- scale + ALiBi + causal mask, online softmax ----
        float mt0 = -1e30f, mt1 = -1e30f;
#pragma unroll
        for (int nt = 0; nt < 8; nt++) {
#pragma unroll
            for (int c = 0; c < 2; c++) {
                int kv = kb * 64 + nt * 8 + t * 2 + c;
                float s0 = (kv <= qpos0) ? fmaf(sc[nt][c], scale, -slope * (float)(qpos0 - kv)) : -1e30f;
                float s1 = (kv <= qpos1) ? fmaf(sc[nt][2 + c], scale, -slope * (float)(qpos1 - kv)) : -1e30f;
                sc[nt][c] = s0; sc[nt][2 + c] = s1;
                mt0 = fmaxf(mt0, s0); mt1 = fmaxf(mt1, s1);
            }
        }
        mt0 = fmaxf(mt0, __shfl_xor_sync(0xffffffffu, mt0, 1));
        mt0 = fmaxf(mt0, __shfl_xor_sync(0xffffffffu, mt0, 2));
        mt1 = fmaxf(mt1, __shfl_xor_sync(0xffffffffu, mt1, 1));
        mt1 = fmaxf(mt1, __shfl_xor_sync(0xffffffffu, mt1, 2));
        float mn0 = fmaxf(m0, mt0), mn1 = fmaxf(m1, mt1);
        float f0 = __expf(m0 - mn0), f1 = __expf(m1 - mn1);
        m0 = mn0; m1 = mn1;

        float s0 = 0.f, s1 = 0.f;
#pragma unroll
        for (int nt = 0; nt < 8; nt++) {
            float p0 = __expf(sc[nt][0] - m0), p1 = __expf(sc[nt][1] - m0);
            float p2 = __expf(sc[nt][2] - m1), p3 = __expf(sc[nt][3] - m1);
            sc[nt][0] = p0; sc[nt][1] = p1; sc[nt][2] = p2; sc[nt][3] = p3;
            s0 += p0 + p1; s1 += p2 + p3;
        }
        s0 += __shfl_xor_sync(0xffffffffu, s0, 1);
        s0 += __shfl_xor_sync(0xffffffffu, s0, 2);
        s1 += __shfl_xor_sync(0xffffffffu, s1, 1);
        s1 += __shfl_xor_sync(0xffffffffu, s1, 2);
        l0 = l0 * f0 + s0;
        l1 = l1 * f1 + s1;
#pragma unroll
        for (int db = 0; db < 16; db++) {
            o[db][0] *= f0; o[db][1] *= f0; o[db][2] *= f1; o[db][3] *= f1;
        }

        // ---- O += P V (P split hi/lo, V split hi/lo: 3 terms) ----
#pragma unroll
        for (int kc2 = 0; kc2 < 4; kc2++) {
            uint32_t ph[4], pl[4];
            split2(sc[2 * kc2][0],     sc[2 * kc2][1],     ph[0], pl[0]);
            split2(sc[2 * kc2][2],     sc[2 * kc2][3],     ph[1], pl[1]);
            split2(sc[2 * kc2 + 1][0], sc[2 * kc2 + 1][1], ph[2], pl[2]);
            split2(sc[2 * kc2 + 1][2], sc[2 * kc2 + 1][3], ph[3], pl[3]);
#pragma unroll
            for (int d16 = 0; d16 < 8; d16++) {
                uint32_t vh[4], vl[4];
                uint32_t off = (uint32_t)((kc2 * 16 * APAD + d16 * 16 + lv) << 1);
                ldsm4t(vh, VhB + off);
                ldsm4t(vl, VlB + off);
                uint32_t bh0[2] = {vh[0], vh[1]}, bh1[2] = {vh[2], vh[3]};
                uint32_t bl0[2] = {vl[0], vl[1]}, bl1[2] = {vl[2], vl[3]};
                mma_bf16(o[2 * d16],     ph, bh0);
                mma_bf16(o[2 * d16],     ph, bl0);
                mma_bf16(o[2 * d16],     pl, bh0);
                mma_bf16(o[2 * d16 + 1], ph, bh1);
                mma_bf16(o[2 * d16 + 1], ph, bl1);
                mma_bf16(o[2 * d16 + 1], pl, bh1);
            }
        }
    }

    // ---- epilogue: normalize, write [s][h*128+d] ----
    float inv0 = 1.f / l0, inv1 = 1.f / l1;
#pragma unroll
    for (int db = 0; db < 16; db++) {
        int col = h * 128 + db * 8 + t * 2;
        int r0 = q0 + qm + g;
        *reinterpret_cast<float2*>(out + (size_t)r0 * HID + col) =
            make_float2(o[db][0] * inv0, o[db][1] * inv0);
        *reinterpret_cast<float2*>(out + (size_t)(r0 + 8) * HID + col) =
            make_float2(o[db][2] * inv1, o[db][3] * inv1);
    }
}

// ---------------------------------------------------------------------------
extern "C" void kernel_launch(void* const* d_in, const int* in_sizes, int n_in,
                              void* d_out, int out_size) {
    const float* hs = (const float*)d_in[0];   // [1,2048,5120]
    const float* wp = (const float*)d_in[1];   // [15360,5120]
    const float* wo = (const float*)d_in[2];   // [5120,5120]
    float* out = (float*)d_out;                // [1,2048,5120]

    float* qkv = nullptr;
    float* attn = nullptr;
    cudaGetSymbolAddress((void**)&qkv, g_qkv);
    cudaGetSymbolAddress((void**)&attn, g_attn);

    // QKV projection: [2048,5120] x [15360,5120]^T -> [2048,15360]
    gemm_abt_kernel<<<dim3(QKVN / 128, SEQ / 128), 256>>>(hs, wp, qkv, SEQ, QKVN, HID);

    // Attention
    cudaFuncSetAttribute(attn_kernel, cudaFuncAttributeMaxDynamicSharedMemorySize, ATTN_SMEM);
    attn_kernel<<<dim3(SEQ / 64, 40), 128, ATTN_SMEM>>>(qkv, attn);

    // o_proj: [2048,5120] x [5120,5120]^T -> [2048,5120]
    gemm_abt_kernel<<<dim3(HID / 128, SEQ / 128), 256>>>(attn, wo, out, SEQ, HID, HID);
}

// round 4
// speedup vs baseline: 1.2414x; 1.2414x over previous
#include <cuda_runtime.h>
#include <cuda_bf16.h>
#include <cstdint>

#define SEQ  2048
#define HID  5120
#define QKVN 15360

// ---------------- scratch (device globals; allocation-free) ----------------
__device__ __align__(256) float g_qkv[SEQ * QKVN];            // 126MB
__device__ __align__(256) __nv_bfloat16 g_hs_h[SEQ * HID];
__device__ __align__(256) __nv_bfloat16 g_hs_l[SEQ * HID];
__device__ __align__(256) __nv_bfloat16 g_wp_h[QKVN * HID];
__device__ __align__(256) __nv_bfloat16 g_wp_l[QKVN * HID];
__device__ __align__(256) __nv_bfloat16 g_wo_h[HID * HID];
__device__ __align__(256) __nv_bfloat16 g_wo_l[HID * HID];
__device__ __align__(256) __nv_bfloat16 g_at_h[SEQ * HID];
__device__ __align__(256) __nv_bfloat16 g_at_l[SEQ * HID];

// ---------------- helpers ----------------
__device__ __forceinline__ uint32_t cvta_s(const void* p) {
    return (uint32_t)__cvta_generic_to_shared(p);
}
__device__ __forceinline__ void split2(float f0, float f1, uint32_t& h, uint32_t& l) {
    __nv_bfloat16 h0 = __float2bfloat16_rn(f0), h1 = __float2bfloat16_rn(f1);
    float r0 = f0 - __bfloat162float(h0), r1 = f1 - __bfloat162float(h1);
    __nv_bfloat16 e0 = __float2bfloat16_rn(r0), e1 = __float2bfloat16_rn(r1);
    h = (uint32_t)__bfloat16_as_ushort(h0) | ((uint32_t)__bfloat16_as_ushort(h1) << 16);
    l = (uint32_t)__bfloat16_as_ushort(e0) | ((uint32_t)__bfloat16_as_ushort(e1) << 16);
}
__device__ __forceinline__ void cvst4(__nv_bfloat16* ph, __nv_bfloat16* pl, float4 v) {
    uint32_t h01, l01, h23, l23;
    split2(v.x, v.y, h01, l01);
    split2(v.z, v.w, h23, l23);
    uint2 H; H.x = h01; H.y = h23;
    uint2 L; L.x = l01; L.y = l23;
    *reinterpret_cast<uint2*>(ph) = H;
    *reinterpret_cast<uint2*>(pl) = L;
}
__device__ __forceinline__ void ldsm4(uint32_t r[4], uint32_t a) {
    asm volatile("ldmatrix.sync.aligned.m8n8.x4.shared.b16 {%0,%1,%2,%3}, [%4];"
                 : "=r"(r[0]), "=r"(r[1]), "=r"(r[2]), "=r"(r[3]) : "r"(a));
}
__device__ __forceinline__ void ldsm4t(uint32_t r[4], uint32_t a) {
    asm volatile("ldmatrix.sync.aligned.m8n8.x4.trans.shared.b16 {%0,%1,%2,%3}, [%4];"
                 : "=r"(r[0]), "=r"(r[1]), "=r"(r[2]), "=r"(r[3]) : "r"(a));
}
__device__ __forceinline__ void mma_bf16(float d[4], const uint32_t a[4], const uint32_t b[2]) {
    asm volatile("mma.sync.aligned.m16n8k16.row.col.f32.bf16.bf16.f32 "
                 "{%0,%1,%2,%3}, {%4,%5,%6,%7}, {%8,%9}, {%0,%1,%2,%3};"
                 : "+f"(d[0]), "+f"(d[1]), "+f"(d[2]), "+f"(d[3])
                 : "r"(a[0]), "r"(a[1]), "r"(a[2]), "r"(a[3]), "r"(b[0]), "r"(b[1]));
}
__device__ __forceinline__ void cp16(uint32_t dst, const void* src) {
    asm volatile("cp.async.cg.shared.global [%0], [%1], 16;" :: "r"(dst), "l"(src));
}

// ---------------- prepass: fp32 -> (hi, lo) bf16 ----------------
__global__ __launch_bounds__(256) void split_kernel(const float4* __restrict__ src,
                                                    uint2* __restrict__ hi,
                                                    uint2* __restrict__ lo, int n4) {
    int i = blockIdx.x * blockDim.x + threadIdx.x;
    if (i >= n4) return;
    float4 v = src[i];
    uint32_t h01, l01, h23, l23;
    split2(v.x, v.y, h01, l01);
    split2(v.z, v.w, h23, l23);
    hi[i] = make_uint2(h01, h23);
    lo[i] = make_uint2(l01, l23);
}

// ---------------- GEMM: C[M,N] = A[M,K] * B[N,K]^T (split-bf16, cp.async) ----
// BM=128, BN=128, BK=64, 2 stages. 256 threads = 8 warps 4(m) x 2(n),
// warp tile 32(m) x 64(n). Smem rows padded to 72 bf16 (144B) -> conflict-free.
#define GPAD 72
#define ARR_BYTES (128 * GPAD * 2)            // 18432 B per array
#define STAGE_BYTES (4 * ARR_BYTES)           // Ah, Al, Bh, Bl
#define GEMM_SMEM (2 * STAGE_BYTES)           // 147456 B

__global__ __launch_bounds__(256) void gemm_cp_kernel(
    const __nv_bfloat16* __restrict__ Ah, const __nv_bfloat16* __restrict__ Al,
    const __nv_bfloat16* __restrict__ Bh, const __nv_bfloat16* __restrict__ Bl,
    float* __restrict__ C, int N, int K)
{
    extern __shared__ char smem[];
    const uint32_t sb = cvta_s(smem);

    const int tid = threadIdx.x, warp = tid >> 5, lane = tid & 31;
    const int m0 = blockIdx.x * 128;
    const int n0 = blockIdx.y * 128;

    const int wm = warp >> 1, wn = warp & 1;
    const int la = (lane & 15) * GPAD + ((lane >> 4) << 3);
    const int lb = (((lane >> 4) << 3) + (lane & 7)) * GPAD + (((lane >> 3) & 1) << 3);

    // per-thread load coords: 1024 chunks per array, 4 per thread
    const int lrow[4] = { (tid + 0) >> 3, (tid + 256) >> 3, (tid + 512) >> 3, (tid + 768) >> 3 };
    const int lc = tid & 7;

    const int nk = K >> 6;  // K / 64

    auto load_stage = [&](int s, int kt) {
        const uint32_t base = sb + s * STAGE_BYTES;
        const int k0 = kt << 6;
#pragma unroll
        for (int t = 0; t < 4; t++) {
            const int r = lrow[t];
            const uint32_t off = (uint32_t)(r * (GPAD * 2) + lc * 16);
            const size_t ga = (size_t)(m0 + r) * K + k0 + lc * 8;
            const size_t gb = (size_t)(n0 + r) * K + k0 + lc * 8;
            cp16(base + off,                 Ah + ga);
            cp16(base + ARR_BYTES + off,     Al + ga);
            cp16(base + 2 * ARR_BYTES + off, Bh + gb);
            cp16(base + 3 * ARR_BYTES + off, Bl + gb);
        }
        asm volatile("cp.async.commit_group;" ::: "memory");
    };

    float acc[2][8][4] = {};

    load_stage(0, 0);

#pragma unroll 1
    for (int kt = 0; kt < nk; kt++) {
        const int cur = kt & 1;
        __syncthreads();  // all warps done computing on buffer cur^1
        if (kt + 1 < nk) {
            load_stage(cur ^ 1, kt + 1);
            asm volatile("cp.async.wait_group 1;" ::: "memory");
        } else {
            asm volatile("cp.async.wait_group 0;" ::: "memory");
        }
        __syncthreads();  // stage cur visible to all

        const uint32_t bAh = sb + cur * STAGE_BYTES;
        const uint32_t bAl = bAh + ARR_BYTES;
        const uint32_t bBh = bAh + 2 * ARR_BYTES;
        const uint32_t bBl = bAh + 3 * ARR_BYTES;

#pragma unroll
        for (int kk = 0; kk < 4; kk++) {
            uint32_t Afh[2][4], Afl[2][4];
#pragma unroll
            for (int mi = 0; mi < 2; mi++) {
                uint32_t off = (uint32_t)(((wm * 32 + mi * 16) * GPAD + kk * 16 + la) << 1);
                ldsm4(Afh[mi], bAh + off);
                ldsm4(Afl[mi], bAl + off);
            }
            uint32_t Bfh[8][2], Bfl[8][2];
#pragma unroll
            for (int ni = 0; ni < 4; ni++) {
                uint32_t t4[4];
                uint32_t off = (uint32_t)(((wn * 64 + ni * 16) * GPAD + kk * 16 + lb) << 1);
                ldsm4(t4, bBh + off);
                Bfh[2 * ni][0] = t4[0]; Bfh[2 * ni][1] = t4[1];
                Bfh[2 * ni + 1][0] = t4[2]; Bfh[2 * ni + 1][1] = t4[3];
                ldsm4(t4, bBl + off);
                Bfl[2 * ni][0] = t4[0]; Bfl[2 * ni][1] = t4[1];
                Bfl[2 * ni + 1][0] = t4[2]; Bfl[2 * ni + 1][1] = t4[3];
            }
#pragma unroll
            for (int mi = 0; mi < 2; mi++)
#pragma unroll
                for (int nj = 0; nj < 8; nj++) {
                    mma_bf16(acc[mi][nj], Afh[mi], Bfh[nj]);
                    mma_bf16(acc[mi][nj], Afh[mi], Bfl[nj]);
                    mma_bf16(acc[mi][nj], Afl[mi], Bfh[nj]);
                }
        }
    }

    const int g = lane >> 2, t = lane & 3;
#pragma unroll
    for (int mi = 0; mi < 2; mi++) {
        int r = m0 + wm * 32 + mi * 16 + g;
#pragma unroll
        for (int nj = 0; nj < 8; nj++) {
            int c = n0 + wn * 64 + nj * 8 + t * 2;
            *reinterpret_cast<float2*>(C + (size_t)r * N + c) =
                make_float2(acc[mi][nj][0], acc[mi][nj][1]);
            *reinterpret_cast<float2*>(C + (size_t)(r + 8) * N + c) =
                make_float2(acc[mi][nj][2], acc[mi][nj][3]);
        }
    }
}

// ---------------- flash attention (mma.sync, split-bf16) ----------------
#define APAD 136
#define ATTN_SMEM (6 * 64 * APAD * 2)

__global__ __launch_bounds__(128) void attn_kernel(const float* __restrict__ qkv,
                                                   __nv_bfloat16* __restrict__ ath,
                                                   __nv_bfloat16* __restrict__ atl)
{
    extern __shared__ __nv_bfloat16 smA[];
    __nv_bfloat16* sQh = smA;
    __nv_bfloat16* sQl = sQh + 64 * APAD;
    __nv_bfloat16* sKh = sQl + 64 * APAD;
    __nv_bfloat16* sKl = sKh + 64 * APAD;
    __nv_bfloat16* sVh = sKl + 64 * APAD;
    __nv_bfloat16* sVl = sVh + 64 * APAD;

    const int tid = threadIdx.x, lane = tid & 31, warp = tid >> 5;
    const int qb = gridDim.x - 1 - blockIdx.x;
    const int h = blockIdx.y;
    const int q0 = qb * 64;
    const float slope = (h < 32) ? exp2f(-0.25f * (float)(h + 1))
                                 : exp2f(-0.125f * (float)(2 * (h - 32) + 1));
    const float scale = 0.08838834764831845f;

    const int lr = tid >> 5;
    const int c4 = tid & 31;

    {
        const float4* Q4 = reinterpret_cast<const float4*>(qkv) + (size_t)q0 * 3840 + h * 32 + c4;
#pragma unroll
        for (int i = 0; i < 16; i++) {
            int row = lr + i * 4;
            float4 v = Q4[(size_t)row * 3840];
            int off = row * APAD + c4 * 4;
            cvst4(sQh + off, sQl + off, v);
        }
    }

    float m0 = -1e30f, m1 = -1e30f, l0 = 0.f, l1 = 0.f;
    float o[16][4] = {};

    const uint32_t QhB = cvta_s(sQh), QlB = cvta_s(sQl);
    const uint32_t KhB = cvta_s(sKh), KlB = cvta_s(sKl);
    const uint32_t VhB = cvta_s(sVh), VlB = cvta_s(sVl);
    const int qm = warp * 16;
    const int g = lane >> 2, t = lane & 3;
    const int la = (lane & 15) * APAD + ((lane >> 4) << 3);
    const int lb = (((lane >> 4) << 3) + (lane & 7)) * APAD + (((lane >> 3) & 1) << 3);
    const int lv = ((((lane >> 3) & 1) << 3) + (lane & 7)) * APAD + ((lane >> 4) << 3);
    const int qpos0 = q0 + qm + g, qpos1 = qpos0 + 8;

#pragma unroll 1
    for (int kb = 0; kb <= qb; kb++) {
        __syncthreads();
        {
            const float4* K4 = reinterpret_cast<const float4*>(qkv) +
                               (size_t)(kb * 64) * 3840 + 1280 + h * 32 + c4;
            const float4* V4 = K4 + 1280;
#pragma unroll
            for (int i = 0; i < 16; i++) {
                int row = lr + i * 4;
                int off = row * APAD + c4 * 4;
                cvst4(sKh + off, sKl + off, K4[(size_t)row * 3840]);
                cvst4(sVh + off, sVl + off, V4[(size_t)row * 3840]);
            }
        }
        __syncthreads();

        float sc[8][4];
#pragma unroll
        for (int i = 0; i < 8; i++)
#pragma unroll
            for (int j = 0; j < 4; j++) sc[i][j] = 0.f;

#pragma unroll
        for (int kc = 0; kc < 8; kc++) {
            uint32_t qh[4], ql[4];
            ldsm4(qh, QhB + (uint32_t)((qm * APAD + kc * 16 + la) << 1));
            ldsm4(ql, QlB + (uint32_t)((qm * APAD + kc * 16 + la) << 1));
#pragma unroll
            for (int np = 0; np < 4; np++) {
                uint32_t th[4], tl[4];
                uint32_t off = (uint32_t)(((np * 16) * APAD + kc * 16 + lb) << 1);
                ldsm4(th, KhB + off);
                ldsm4(tl, KlB + off);
                uint32_t bh0[2] = {th[0], th[1]}, bh1[2] = {th[2], th[3]};
                uint32_t bl0[2] = {tl[0], tl[1]}, bl1[2] = {tl[2], tl[3]};
                mma_bf16(sc[2 * np],     qh, bh0);
                mma_bf16(sc[2 * np],     qh, bl0);
                mma_bf16(sc[2 * np],     ql, bh0);
                mma_bf16(sc[2 * np + 1], qh, bh1);
                mma_bf16(sc[2 * np + 1], qh, bl1);
                mma_bf16(sc[2 * np + 1], ql, bh1);
            }
        }

        float mt0 = -1e30f, mt1 = -1e30f;
#pragma unroll
        for (int nt = 0; nt < 8; nt++) {
#pragma unroll
            for (int c = 0; c < 2; c++) {
                int kv = kb * 64 + nt * 8 + t * 2 + c;
                float s0 = (kv <= qpos0) ? fmaf(sc[nt][c], scale, -slope * (float)(qpos0 - kv)) : -1e30f;
                float s1 = (kv <= qpos1) ? fmaf(sc[nt][2 + c], scale, -slope * (float)(qpos1 - kv)) : -1e30f;
                sc[nt][c] = s0; sc[nt][2 + c] = s1;
                mt0 = fmaxf(mt0, s0); mt1 = fmaxf(mt1, s1);
            }
        }
        mt0 = fmaxf(mt0, __shfl_xor_sync(0xffffffffu, mt0, 1));
        mt0 = fmaxf(mt0, __shfl_xor_sync(0xffffffffu, mt0, 2));
        mt1 = fmaxf(mt1, __shfl_xor_sync(0xffffffffu, mt1, 1));
        mt1 = fmaxf(mt1, __shfl_xor_sync(0xffffffffu, mt1, 2));
        float mn0 = fmaxf(m0, mt0), mn1 = fmaxf(m1, mt1);
        float f0 = __expf(m0 - mn0), f1 = __expf(m1 - mn1);
        m0 = mn0; m1 = mn1;

        float s0 = 0.f, s1 = 0.f;
#pragma unroll
        for (int nt = 0; nt < 8; nt++) {
            float p0 = __expf(sc[nt][0] - m0), p1 = __expf(sc[nt][1] - m0);
            float p2 = __expf(sc[nt][2] - m1), p3 = __expf(sc[nt][3] - m1);
            sc[nt][0] = p0; sc[nt][1] = p1; sc[nt][2] = p2; sc[nt][3] = p3;
            s0 += p0 + p1; s1 += p2 + p3;
        }
        s0 += __shfl_xor_sync(0xffffffffu, s0, 1);
        s0 += __shfl_xor_sync(0xffffffffu, s0, 2);
        s1 += __shfl_xor_sync(0xffffffffu, s1, 1);
        s1 += __shfl_xor_sync(0xffffffffu, s1, 2);
        l0 = l0 * f0 + s0;
        l1 = l1 * f1 + s1;
#pragma unroll
        for (int db = 0; db < 16; db++) {
            o[db][0] *= f0; o[db][1] *= f0; o[db][2] *= f1; o[db][3] *= f1;
        }

#pragma unroll
        for (int kc2 = 0; kc2 < 4; kc2++) {
            uint32_t ph2[4], pl2[4];
            split2(sc[2 * kc2][0],     sc[2 * kc2][1],     ph2[0], pl2[0]);
            split2(sc[2 * kc2][2],     sc[2 * kc2][3],     ph2[1], pl2[1]);
            split2(sc[2 * kc2 + 1][0], sc[2 * kc2 + 1][1], ph2[2], pl2[2]);
            split2(sc[2 * kc2 + 1][2], sc[2 * kc2 + 1][3], ph2[3], pl2[3]);
#pragma unroll
            for (int d16 = 0; d16 < 8; d16++) {
                uint32_t vh[4], vl[4];
                uint32_t off = (uint32_t)((kc2 * 16 * APAD + d16 * 16 + lv) << 1);
                ldsm4t(vh, VhB + off);
                ldsm4t(vl, VlB + off);
                uint32_t bh0[2] = {vh[0], vh[1]}, bh1[2] = {vh[2], vh[3]};
                uint32_t bl0[2] = {vl[0], vl[1]}, bl1[2] = {vl[2], vl[3]};
                mma_bf16(o[2 * d16],     ph2, bh0);
                mma_bf16(o[2 * d16],     ph2, bl0);
                mma_bf16(o[2 * d16],     pl2, bh0);
                mma_bf16(o[2 * d16 + 1], ph2, bh1);
                mma_bf16(o[2 * d16 + 1], ph2, bl1);
                mma_bf16(o[2 * d16 + 1], pl2, bh1);
            }
        }
    }

    // epilogue: normalize and write split hi/lo bf16 for o_proj GEMM
    float inv0 = 1.f / l0, inv1 = 1.f / l1;
#pragma unroll
    for (int db = 0; db < 16; db++) {
        int col = h * 128 + db * 8 + t * 2;
        int r0 = q0 + qm + g;
        uint32_t hh, ll;
        split2(o[db][0] * inv0, o[db][1] * inv0, hh, ll);
        *reinterpret_cast<uint32_t*>(ath + (size_t)r0 * HID + col) = hh;
        *reinterpret_cast<uint32_t*>(atl + (size_t)r0 * HID + col) = ll;
        split2(o[db][2] * inv1, o[db][3] * inv1, hh, ll);
        *reinterpret_cast<uint32_t*>(ath + (size_t)(r0 + 8) * HID + col) = hh;
        *reinterpret_cast<uint32_t*>(atl + (size_t)(r0 + 8) * HID + col) = ll;
    }
}

// ---------------------------------------------------------------------------
extern "C" void kernel_launch(void* const* d_in, const int* in_sizes, int n_in,
                              void* d_out, int out_size) {
    const float* hs = (const float*)d_in[0];   // [1,2048,5120]
    const float* wp = (const float*)d_in[1];   // [15360,5120]
    const float* wo = (const float*)d_in[2];   // [5120,5120]
    float* out = (float*)d_out;                // [1,2048,5120]

    float* qkv;          cudaGetSymbolAddress((void**)&qkv, g_qkv);
    __nv_bfloat16 *hsh, *hsl, *wph, *wpl, *woh, *wol, *ath, *atl;
    cudaGetSymbolAddress((void**)&hsh, g_hs_h);
    cudaGetSymbolAddress((void**)&hsl, g_hs_l);
    cudaGetSymbolAddress((void**)&wph, g_wp_h);
    cudaGetSymbolAddress((void**)&wpl, g_wp_l);
    cudaGetSymbolAddress((void**)&woh, g_wo_h);
    cudaGetSymbolAddress((void**)&wol, g_wo_l);
    cudaGetSymbolAddress((void**)&ath, g_at_h);
    cudaGetSymbolAddress((void**)&atl, g_at_l);

    // prepass splits
    {
        int n4 = SEQ * HID / 4;
        split_kernel<<<(n4 + 255) / 256, 256>>>((const float4*)hs, (uint2*)hsh, (uint2*)hsl, n4);
        n4 = QKVN * HID / 4;
        split_kernel<<<(n4 + 255) / 256, 256>>>((const float4*)wp, (uint2*)wph, (uint2*)wpl, n4);
        n4 = HID * HID / 4;
        split_kernel<<<(n4 + 255) / 256, 256>>>((const float4*)wo, (uint2*)woh, (uint2*)wol, n4);
    }

    cudaFuncSetAttribute(gemm_cp_kernel, cudaFuncAttributeMaxDynamicSharedMemorySize, GEMM_SMEM);

    // QKV projection: [2048,5120] x [15360,5120]^T -> [2048,15360]
    gemm_cp_kernel<<<dim3(SEQ / 128, QKVN / 128), 256, GEMM_SMEM>>>(
        hsh, hsl, wph, wpl, qkv, QKVN, HID);

    // attention (writes split hi/lo output)
    cudaFuncSetAttribute(attn_kernel, cudaFuncAttributeMaxDynamicSharedMemorySize, ATTN_SMEM);
    attn_kernel<<<dim3(SEQ / 64, 40), 128, ATTN_SMEM>>>(qkv, ath, atl);

    // o_proj: [2048,5120] x [5120,5120]^T -> [2048,5120]
    gemm_cp_kernel<<<dim3(SEQ / 128, HID / 128), 256, GEMM_SMEM>>>(
        ath, atl, woh, wol, out, HID, HID);
}

// round 5
// speedup vs baseline: 1.2672x; 1.0208x over previous
#include <cuda_runtime.h>
#include <cuda_bf16.h>
#include <cstdint>

#define SEQ  2048
#define HID  5120
#define QKVN 15360

// ---------------- scratch (device globals; allocation-free) ----------------
__device__ __align__(256) __nv_bfloat16 g_qk_h[SEQ * QKVN];   // qkv hi (63MB)
__device__ __align__(256) __nv_bfloat16 g_qk_l[SEQ * QKVN];   // qkv lo
__device__ __align__(256) __nv_bfloat16 g_hs_h[SEQ * HID];
__device__ __align__(256) __nv_bfloat16 g_hs_l[SEQ * HID];
__device__ __align__(256) __nv_bfloat16 g_wp_h[QKVN * HID];
__device__ __align__(256) __nv_bfloat16 g_wp_l[QKVN * HID];
__device__ __align__(256) __nv_bfloat16 g_wo_h[HID * HID];
__device__ __align__(256) __nv_bfloat16 g_wo_l[HID * HID];
__device__ __align__(256) __nv_bfloat16 g_at_h[SEQ * HID];
__device__ __align__(256) __nv_bfloat16 g_at_l[SEQ * HID];

// ---------------- helpers ----------------
__device__ __forceinline__ uint32_t cvta_s(const void* p) {
    return (uint32_t)__cvta_generic_to_shared(p);
}
__device__ __forceinline__ void split2(float f0, float f1, uint32_t& h, uint32_t& l) {
    __nv_bfloat16 h0 = __float2bfloat16_rn(f0), h1 = __float2bfloat16_rn(f1);
    float r0 = f0 - __bfloat162float(h0), r1 = f1 - __bfloat162float(h1);
    __nv_bfloat16 e0 = __float2bfloat16_rn(r0), e1 = __float2bfloat16_rn(r1);
    h = (uint32_t)__bfloat16_as_ushort(h0) | ((uint32_t)__bfloat16_as_ushort(h1) << 16);
    l = (uint32_t)__bfloat16_as_ushort(e0) | ((uint32_t)__bfloat16_as_ushort(e1) << 16);
}
__device__ __forceinline__ void ldsm4(uint32_t r[4], uint32_t a) {
    asm volatile("ldmatrix.sync.aligned.m8n8.x4.shared.b16 {%0,%1,%2,%3}, [%4];"
                 : "=r"(r[0]), "=r"(r[1]), "=r"(r[2]), "=r"(r[3]) : "r"(a));
}
__device__ __forceinline__ void ldsm4t(uint32_t r[4], uint32_t a) {
    asm volatile("ldmatrix.sync.aligned.m8n8.x4.trans.shared.b16 {%0,%1,%2,%3}, [%4];"
                 : "=r"(r[0]), "=r"(r[1]), "=r"(r[2]), "=r"(r[3]) : "r"(a));
}
__device__ __forceinline__ void mma_bf16(float d[4], const uint32_t a[4], const uint32_t b[2]) {
    asm volatile("mma.sync.aligned.m16n8k16.row.col.f32.bf16.bf16.f32 "
                 "{%0,%1,%2,%3}, {%4,%5,%6,%7}, {%8,%9}, {%0,%1,%2,%3};"
                 : "+f"(d[0]), "+f"(d[1]), "+f"(d[2]), "+f"(d[3])
                 : "r"(a[0]), "r"(a[1]), "r"(a[2]), "r"(a[3]), "r"(b[0]), "r"(b[1]));
}
__device__ __forceinline__ void cp16(uint32_t dst, const void* src) {
    asm volatile("cp.async.cg.shared.global [%0], [%1], 16;" :: "r"(dst), "l"(src));
}

// ---------------- prepass: fp32 -> (hi, lo) bf16 ----------------
__global__ __launch_bounds__(256) void split_kernel(const float4* __restrict__ src,
                                                    uint2* __restrict__ hi,
                                                    uint2* __restrict__ lo, int n4) {
    int i = blockIdx.x * blockDim.x + threadIdx.x;
    if (i >= n4) return;
    float4 v = src[i];
    uint32_t h01, l01, h23, l23;
    split2(v.x, v.y, h01, l01);
    split2(v.z, v.w, h23, l23);
    hi[i] = make_uint2(h01, h23);
    lo[i] = make_uint2(l01, l23);
}

// ---------------- GEMM: C[M,N] = A[M,K] * B[N,K]^T (split-bf16, cp.async) ----
// BM=128, BN=128, BK=64, 3 stages, one __syncthreads per chunk.
// 256 threads = 8 warps 4(m) x 2(n), warp tile 32(m) x 64(n).
#define GPAD 72
#define ARR_BYTES (128 * GPAD * 2)            // 18432 B per array
#define STAGE_BYTES (4 * ARR_BYTES)           // Ah, Al, Bh, Bl = 73728 B
#define GEMM_SMEM (3 * STAGE_BYTES)           // 221184 B

template <bool SPLIT_OUT>
__global__ __launch_bounds__(256) void gemm_cp_kernel(
    const __nv_bfloat16* __restrict__ Ah, const __nv_bfloat16* __restrict__ Al,
    const __nv_bfloat16* __restrict__ Bh, const __nv_bfloat16* __restrict__ Bl,
    float* __restrict__ C, __nv_bfloat16* __restrict__ Ch, __nv_bfloat16* __restrict__ Cl,
    int N, int K)
{
    extern __shared__ char smem[];
    const uint32_t sb = cvta_s(smem);

    const int tid = threadIdx.x, warp = tid >> 5, lane = tid & 31;
    const int m0 = blockIdx.x * 128;
    const int n0 = blockIdx.y * 128;

    const int wm = warp >> 1, wn = warp & 1;
    const int la = (lane & 15) * GPAD + ((lane >> 4) << 3);
    const int lb = (((lane >> 4) << 3) + (lane & 7)) * GPAD + (((lane >> 3) & 1) << 3);

    const int lrow[4] = { (tid + 0) >> 3, (tid + 256) >> 3, (tid + 512) >> 3, (tid + 768) >> 3 };
    const int lc = tid & 7;

    const int nk = K >> 6;  // K / 64

    auto load_stage = [&](int s, int kt) {
        const uint32_t base = sb + s * STAGE_BYTES;
        const int k0 = kt << 6;
#pragma unroll
        for (int t = 0; t < 4; t++) {
            const int r = lrow[t];
            const uint32_t off = (uint32_t)(r * (GPAD * 2) + lc * 16);
            const size_t ga = (size_t)(m0 + r) * K + k0 + lc * 8;
            const size_t gb = (size_t)(n0 + r) * K + k0 + lc * 8;
            cp16(base + off,                 Ah + ga);
            cp16(base + ARR_BYTES + off,     Al + ga);
            cp16(base + 2 * ARR_BYTES + off, Bh + gb);
            cp16(base + 3 * ARR_BYTES + off, Bl + gb);
        }
        asm volatile("cp.async.commit_group;" ::: "memory");
    };

    float acc[2][8][4] = {};

    load_stage(0, 0);
    load_stage(1, 1);

#pragma unroll 1
    for (int kt = 0; kt < nk; kt++) {
        // retire stage kt (leave the newest group, if any, in flight)
        if (kt + 1 < nk) {
            asm volatile("cp.async.wait_group 1;" ::: "memory");
        } else {
            asm volatile("cp.async.wait_group 0;" ::: "memory");
        }
        __syncthreads();  // stage kt visible; buffer (kt-1)%3 free for reuse

        if (kt + 2 < nk) load_stage((kt + 2) % 3, kt + 2);

        const uint32_t bAh = sb + (kt % 3) * STAGE_BYTES;
        const uint32_t bAl = bAh + ARR_BYTES;
        const uint32_t bBh = bAh + 2 * ARR_BYTES;
        const uint32_t bBl = bAh + 3 * ARR_BYTES;

#pragma unroll
        for (int kk = 0; kk < 4; kk++) {
            uint32_t Afh[2][4], Afl[2][4];
#pragma unroll
            for (int mi = 0; mi < 2; mi++) {
                uint32_t off = (uint32_t)(((wm * 32 + mi * 16) * GPAD + kk * 16 + la) << 1);
                ldsm4(Afh[mi], bAh + off);
                ldsm4(Afl[mi], bAl + off);
            }
            uint32_t Bfh[8][2], Bfl[8][2];
#pragma unroll
            for (int ni = 0; ni < 4; ni++) {
                uint32_t t4[4];
                uint32_t off = (uint32_t)(((wn * 64 + ni * 16) * GPAD + kk * 16 + lb) << 1);
                ldsm4(t4, bBh + off);
                Bfh[2 * ni][0] = t4[0]; Bfh[2 * ni][1] = t4[1];
                Bfh[2 * ni + 1][0] = t4[2]; Bfh[2 * ni + 1][1] = t4[3];
                ldsm4(t4, bBl + off);
                Bfl[2 * ni][0] = t4[0]; Bfl[2 * ni][1] = t4[1];
                Bfl[2 * ni + 1][0] = t4[2]; Bfl[2 * ni + 1][1] = t4[3];
            }
#pragma unroll
            for (int mi = 0; mi < 2; mi++)
#pragma unroll
                for (int nj = 0; nj < 8; nj++) {
                    mma_bf16(acc[mi][nj], Afh[mi], Bfh[nj]);
                    mma_bf16(acc[mi][nj], Afh[mi], Bfl[nj]);
                    mma_bf16(acc[mi][nj], Afl[mi], Bfh[nj]);
                }
        }
    }

    const int g = lane >> 2, t = lane & 3;
#pragma unroll
    for (int mi = 0; mi < 2; mi++) {
        int r = m0 + wm * 32 + mi * 16 + g;
#pragma unroll
        for (int nj = 0; nj < 8; nj++) {
            int c = n0 + wn * 64 + nj * 8 + t * 2;
            if (SPLIT_OUT) {
                uint32_t hh, ll;
                split2(acc[mi][nj][0], acc[mi][nj][1], hh, ll);
                __stcs(reinterpret_cast<uint32_t*>(Ch + (size_t)r * N + c), hh);
                __stcs(reinterpret_cast<uint32_t*>(Cl + (size_t)r * N + c), ll);
                split2(acc[mi][nj][2], acc[mi][nj][3], hh, ll);
                __stcs(reinterpret_cast<uint32_t*>(Ch + (size_t)(r + 8) * N + c), hh);
                __stcs(reinterpret_cast<uint32_t*>(Cl + (size_t)(r + 8) * N + c), ll);
            } else {
                __stcs(reinterpret_cast<float2*>(C + (size_t)r * N + c),
                       make_float2(acc[mi][nj][0], acc[mi][nj][1]));
                __stcs(reinterpret_cast<float2*>(C + (size_t)(r + 8) * N + c),
                       make_float2(acc[mi][nj][2], acc[mi][nj][3]));
            }
        }
    }
}

// ---------------- flash attention (mma.sync, split-bf16, cp.async loads) ----
#define APAD 136
#define ATTN_SMEM (6 * 64 * APAD * 2)

__global__ __launch_bounds__(128) void attn_kernel(const __nv_bfloat16* __restrict__ qh,
                                                   const __nv_bfloat16* __restrict__ ql,
                                                   __nv_bfloat16* __restrict__ ath,
                                                   __nv_bfloat16* __restrict__ atl)
{
    extern __shared__ __nv_bfloat16 smA[];
    __nv_bfloat16* sQh = smA;
    __nv_bfloat16* sQl = sQh + 64 * APAD;
    __nv_bfloat16* sKh = sQl + 64 * APAD;
    __nv_bfloat16* sKl = sKh + 64 * APAD;
    __nv_bfloat16* sVh = sKl + 64 * APAD;
    __nv_bfloat16* sVl = sVh + 64 * APAD;

    const int tid = threadIdx.x, lane = tid & 31, warp = tid >> 5;
    const int qb = gridDim.x - 1 - blockIdx.x;
    const int h = blockIdx.y;
    const int q0 = qb * 64;
    const float slope = (h < 32) ? exp2f(-0.25f * (float)(h + 1))
                                 : exp2f(-0.125f * (float)(2 * (h - 32) + 1));
    const float scale = 0.08838834764831845f;

    const uint32_t QhB = cvta_s(sQh), QlB = cvta_s(sQl);
    const uint32_t KhB = cvta_s(sKh), KlB = cvta_s(sKl);
    const uint32_t VhB = cvta_s(sVh), VlB = cvta_s(sVl);

    // async Q tile load (64 x 128 bf16 hi + lo)
#pragma unroll
    for (int j = 0; j < 8; j++) {
        int c = tid + j * 128;
        int row = c >> 4, col8 = c & 15;
        uint32_t off = (uint32_t)((row * APAD + col8 * 8) * 2);
        size_t g = (size_t)(q0 + row) * QKVN + h * 128 + col8 * 8;
        cp16(QhB + off, qh + g);
        cp16(QlB + off, ql + g);
    }
    asm volatile("cp.async.commit_group;" ::: "memory");

    float m0 = -1e30f, m1 = -1e30f, l0 = 0.f, l1 = 0.f;
    float o[16][4] = {};

    const int qm = warp * 16;
    const int g = lane >> 2, t = lane & 3;
    const int la = (lane & 15) * APAD + ((lane >> 4) << 3);
    const int lb = (((lane >> 4) << 3) + (lane & 7)) * APAD + (((lane >> 3) & 1) << 3);
    const int lv = ((((lane >> 3) & 1) << 3) + (lane & 7)) * APAD + ((lane >> 4) << 3);
    const int qpos0 = q0 + qm + g, qpos1 = qpos0 + 8;

#pragma unroll 1
    for (int kb = 0; kb <= qb; kb++) {
        __syncthreads();  // previous tile fully consumed
#pragma unroll
        for (int j = 0; j < 8; j++) {
            int c = tid + j * 128;
            int row = c >> 4, col8 = c & 15;
            uint32_t off = (uint32_t)((row * APAD + col8 * 8) * 2);
            size_t gk = (size_t)(kb * 64 + row) * QKVN + HID + h * 128 + col8 * 8;
            size_t gv = gk + HID;
            cp16(KhB + off, qh + gk);
            cp16(KlB + off, ql + gk);
            cp16(VhB + off, qh + gv);
            cp16(VlB + off, ql + gv);
        }
        asm volatile("cp.async.commit_group;" ::: "memory");
        asm volatile("cp.async.wait_group 0;" ::: "memory");
        __syncthreads();

        float sc[8][4];
#pragma unroll
        for (int i = 0; i < 8; i++)
#pragma unroll
            for (int j = 0; j < 4; j++) sc[i][j] = 0.f;

#pragma unroll
        for (int kc = 0; kc < 8; kc++) {
            uint32_t qfh[4], qfl[4];
            ldsm4(qfh, QhB + (uint32_t)((qm * APAD + kc * 16 + la) << 1));
            ldsm4(qfl, QlB + (uint32_t)((qm * APAD + kc * 16 + la) << 1));
#pragma unroll
            for (int np = 0; np < 4; np++) {
                uint32_t th[4], tl[4];
                uint32_t off = (uint32_t)(((np * 16) * APAD + kc * 16 + lb) << 1);
                ldsm4(th, KhB + off);
                ldsm4(tl, KlB + off);
                uint32_t bh0[2] = {th[0], th[1]}, bh1[2] = {th[2], th[3]};
                uint32_t bl0[2] = {tl[0], tl[1]}, bl1[2] = {tl[2], tl[3]};
                mma_bf16(sc[2 * np],     qfh, bh0);
                mma_bf16(sc[2 * np],     qfh, bl0);
                mma_bf16(sc[2 * np],     qfl, bh0);
                mma_bf16(sc[2 * np + 1], qfh, bh1);
                mma_bf16(sc[2 * np + 1], qfh, bl1);
                mma_bf16(sc[2 * np + 1], qfl, bh1);
            }
        }

        float mt0 = -1e30f, mt1 = -1e30f;
#pragma unroll
        for (int nt = 0; nt < 8; nt++) {
#pragma unroll
            for (int c = 0; c < 2; c++) {
                int kv = kb * 64 + nt * 8 + t * 2 + c;
                float s0 = (kv <= qpos0) ? fmaf(sc[nt][c], scale, -slope * (float)(qpos0 - kv)) : -1e30f;
                float s1 = (kv <= qpos1) ? fmaf(sc[nt][2 + c], scale, -slope * (float)(qpos1 - kv)) : -1e30f;
                sc[nt][c] = s0; sc[nt][2 + c] = s1;
                mt0 = fmaxf(mt0, s0); mt1 = fmaxf(mt1, s1);
            }
        }
        mt0 = fmaxf(mt0, __shfl_xor_sync(0xffffffffu, mt0, 1));
        mt0 = fmaxf(mt0, __shfl_xor_sync(0xffffffffu, mt0, 2));
        mt1 = fmaxf(mt1, __shfl_xor_sync(0xffffffffu, mt1, 1));
        mt1 = fmaxf(mt1, __shfl_xor_sync(0xffffffffu, mt1, 2));
        float mn0 = fmaxf(m0, mt0), mn1 = fmaxf(m1, mt1);
        float f0 = __expf(m0 - mn0), f1 = __expf(m1 - mn1);
        m0 = mn0; m1 = mn1;

        float s0 = 0.f, s1 = 0.f;
#pragma unroll
        for (int nt = 0; nt < 8; nt++) {
            float p0 = __expf(sc[nt][0] - m0), p1 = __expf(sc[nt][1] - m0);
            float p2 = __expf(sc[nt][2] - m1), p3 = __expf(sc[nt][3] - m1);
            sc[nt][0] = p0; sc[nt][1] = p1; sc[nt][2] = p2; sc[nt][3] = p3;
            s0 += p0 + p1; s1 += p2 + p3;
        }
        s0 += __shfl_xor_sync(0xffffffffu, s0, 1);
        s0 += __shfl_xor_sync(0xffffffffu, s0, 2);
        s1 += __shfl_xor_sync(0xffffffffu, s1, 1);
        s1 += __shfl_xor_sync(0xffffffffu, s1, 2);
        l0 = l0 * f0 + s0;
        l1 = l1 * f1 + s1;
#pragma unroll
        for (int db = 0; db < 16; db++) {
            o[db][0] *= f0; o[db][1] *= f0; o[db][2] *= f1; o[db][3] *= f1;
        }

#pragma unroll
        for (int kc2 = 0; kc2 < 4; kc2++) {
            uint32_t ph2[4], pl2[4];
            split2(sc[2 * kc2][0],     sc[2 * kc2][1],     ph2[0], pl2[0]);
            split2(sc[2 * kc2][2],     sc[2 * kc2][3],     ph2[1], pl2[1]);
            split2(sc[2 * kc2 + 1][0], sc[2 * kc2 + 1][1], ph2[2], pl2[2]);
            split2(sc[2 * kc2 + 1][2], sc[2 * kc2 + 1][3], ph2[3], pl2[3]);
#pragma unroll
            for (int d16 = 0; d16 < 8; d16++) {
                uint32_t vh[4], vl[4];
                uint32_t off = (uint32_t)((kc2 * 16 * APAD + d16 * 16 + lv) << 1);
                ldsm4t(vh, VhB + off);
                ldsm4t(vl, VlB + off);
                uint32_t bh0[2] = {vh[0], vh[1]}, bh1[2] = {vh[2], vh[3]};
                uint32_t bl0[2] = {vl[0], vl[1]}, bl1[2] = {vl[2], vl[3]};
                mma_bf16(o[2 * d16],     ph2, bh0);
                mma_bf16(o[2 * d16],     ph2, bl0);
                mma_bf16(o[2 * d16],     pl2, bh0);
                mma_bf16(o[2 * d16 + 1], ph2, bh1);
                mma_bf16(o[2 * d16 + 1], ph2, bl1);
                mma_bf16(o[2 * d16 + 1], pl2, bh1);
            }
        }
    }

    // epilogue: normalize and write split hi/lo bf16 for o_proj GEMM
    float inv0 = 1.f / l0, inv1 = 1.f / l1;
#pragma unroll
    for (int db = 0; db < 16; db++) {
        int col = h * 128 + db * 8 + t * 2;
        int r0 = q0 + qm + g;
        uint32_t hh, ll;
        split2(o[db][0] * inv0, o[db][1] * inv0, hh, ll);
        __stcs(reinterpret_cast<uint32_t*>(ath + (size_t)r0 * HID + col), hh);
        __stcs(reinterpret_cast<uint32_t*>(atl + (size_t)r0 * HID + col), ll);
        split2(o[db][2] * inv1, o[db][3] * inv1, hh, ll);
        __stcs(reinterpret_cast<uint32_t*>(ath + (size_t)(r0 + 8) * HID + col), hh);
        __stcs(reinterpret_cast<uint32_t*>(atl + (size_t)(r0 + 8) * HID + col), ll);
    }
}

// ---------------------------------------------------------------------------
extern "C" void kernel_launch(void* const* d_in, const int* in_sizes, int n_in,
                              void* d_out, int out_size) {
    const float* hs = (const float*)d_in[0];   // [1,2048,5120]
    const float* wp = (const float*)d_in[1];   // [15360,5120]
    const float* wo = (const float*)d_in[2];   // [5120,5120]
    float* out = (float*)d_out;                // [1,2048,5120]

    __nv_bfloat16 *qkh, *qkl, *hsh, *hsl, *wph, *wpl, *woh, *wol, *ath, *atl;
    cudaGetSymbolAddress((void**)&qkh, g_qk_h);
    cudaGetSymbolAddress((void**)&qkl, g_qk_l);
    cudaGetSymbolAddress((void**)&hsh, g_hs_h);
    cudaGetSymbolAddress((void**)&hsl, g_hs_l);
    cudaGetSymbolAddress((void**)&wph, g_wp_h);
    cudaGetSymbolAddress((void**)&wpl, g_wp_l);
    cudaGetSymbolAddress((void**)&woh, g_wo_h);
    cudaGetSymbolAddress((void**)&wol, g_wo_l);
    cudaGetSymbolAddress((void**)&ath, g_at_h);
    cudaGetSymbolAddress((void**)&atl, g_at_l);

    // prepass splits
    {
        int n4 = SEQ * HID / 4;
        split_kernel<<<(n4 + 255) / 256, 256>>>((const float4*)hs, (uint2*)hsh, (uint2*)hsl, n4);
        n4 = QKVN * HID / 4;
        split_kernel<<<(n4 + 255) / 256, 256>>>((const float4*)wp, (uint2*)wph, (uint2*)wpl, n4);
        n4 = HID * HID / 4;
        split_kernel<<<(n4 + 255) / 256, 256>>>((const float4*)wo, (uint2*)woh, (uint2*)wol, n4);
    }

    cudaFuncSetAttribute(gemm_cp_kernel<true>, cudaFuncAttributeMaxDynamicSharedMemorySize, GEMM_SMEM);
    cudaFuncSetAttribute(gemm_cp_kernel<false>, cudaFuncAttributeMaxDynamicSharedMemorySize, GEMM_SMEM);

    // QKV projection: [2048,5120] x [15360,5120]^T -> split bf16 [2048,15360]
    gemm_cp_kernel<true><<<dim3(SEQ / 128, QKVN / 128), 256, GEMM_SMEM>>>(
        hsh, hsl, wph, wpl, nullptr, qkh, qkl, QKVN, HID);

    // attention (reads split qkv, writes split hi/lo output)
    cudaFuncSetAttribute(attn_kernel, cudaFuncAttributeMaxDynamicSharedMemorySize, ATTN_SMEM);
    attn_kernel<<<dim3(SEQ / 64, 40), 128, ATTN_SMEM>>>(qkh, qkl, ath, atl);

    // o_proj: [2048,5120] x [5120,5120]^T -> [2048,5120] fp32
    gemm_cp_kernel<false><<<dim3(SEQ / 128, HID / 128), 256, GEMM_SMEM>>>(
        ath, atl, woh, wol, out, nullptr, nullptr, HID, HID);
}

// round 6
// speedup vs baseline: 1.3013x; 1.0270x over previous
#include <cuda_runtime.h>
#include <cuda_bf16.h>
#include <cstdint>

#define SEQ  2048
#define HID  5120
#define QKVN 15360

// ---------------- scratch (device globals; allocation-free) ----------------
__device__ __align__(256) __nv_bfloat16 g_qk_h[SEQ * QKVN];   // qkv hi (63MB)
__device__ __align__(256) __nv_bfloat16 g_qk_l[SEQ * QKVN];   // qkv lo
__device__ __align__(256) __nv_bfloat16 g_hs_h[SEQ * HID];
__device__ __align__(256) __nv_bfloat16 g_hs_l[SEQ * HID];
__device__ __align__(256) __nv_bfloat16 g_wp_h[QKVN * HID];
__device__ __align__(256) __nv_bfloat16 g_wp_l[QKVN * HID];
__device__ __align__(256) __nv_bfloat16 g_wo_h[HID * HID];
__device__ __align__(256) __nv_bfloat16 g_wo_l[HID * HID];
__device__ __align__(256) __nv_bfloat16 g_at_h[SEQ * HID];
__device__ __align__(256) __nv_bfloat16 g_at_l[SEQ * HID];

// ---------------- helpers ----------------
__device__ __forceinline__ uint32_t cvta_s(const void* p) {
    return (uint32_t)__cvta_generic_to_shared(p);
}
__device__ __forceinline__ void split2(float f0, float f1, uint32_t& h, uint32_t& l) {
    __nv_bfloat16 h0 = __float2bfloat16_rn(f0), h1 = __float2bfloat16_rn(f1);
    float r0 = f0 - __bfloat162float(h0), r1 = f1 - __bfloat162float(h1);
    __nv_bfloat16 e0 = __float2bfloat16_rn(r0), e1 = __float2bfloat16_rn(r1);
    h = (uint32_t)__bfloat16_as_ushort(h0) | ((uint32_t)__bfloat16_as_ushort(h1) << 16);
    l = (uint32_t)__bfloat16_as_ushort(e0) | ((uint32_t)__bfloat16_as_ushort(e1) << 16);
}
__device__ __forceinline__ void ldsm4(uint32_t r[4], uint32_t a) {
    asm volatile("ldmatrix.sync.aligned.m8n8.x4.shared.b16 {%0,%1,%2,%3}, [%4];"
                 : "=r"(r[0]), "=r"(r[1]), "=r"(r[2]), "=r"(r[3]) : "r"(a));
}
__device__ __forceinline__ void ldsm4t(uint32_t r[4], uint32_t a) {
    asm volatile("ldmatrix.sync.aligned.m8n8.x4.trans.shared.b16 {%0,%1,%2,%3}, [%4];"
                 : "=r"(r[0]), "=r"(r[1]), "=r"(r[2]), "=r"(r[3]) : "r"(a));
}
__device__ __forceinline__ void mma_bf16(float d[4], const uint32_t a[4], const uint32_t b[2]) {
    asm volatile("mma.sync.aligned.m16n8k16.row.col.f32.bf16.bf16.f32 "
                 "{%0,%1,%2,%3}, {%4,%5,%6,%7}, {%8,%9}, {%0,%1,%2,%3};"
                 : "+f"(d[0]), "+f"(d[1]), "+f"(d[2]), "+f"(d[3])
                 : "r"(a[0]), "r"(a[1]), "r"(a[2]), "r"(a[3]), "r"(b[0]), "r"(b[1]));
}
__device__ __forceinline__ void cp16(uint32_t dst, const void* src) {
    asm volatile("cp.async.cg.shared.global [%0], [%1], 16;" :: "r"(dst), "l"(src));
}

// ---------------- prepass: fp32 -> (hi, lo) bf16 ----------------
__global__ __launch_bounds__(256) void split_kernel(const float4* __restrict__ src,
                                                    uint2* __restrict__ hi,
                                                    uint2* __restrict__ lo, int n4) {
    int i = blockIdx.x * blockDim.x + threadIdx.x;
    if (i >= n4) return;
    float4 v = src[i];
    uint32_t h01, l01, h23, l23;
    split2(v.x, v.y, h01, l01);
    split2(v.z, v.w, h23, l23);
    hi[i] = make_uint2(h01, h23);
    lo[i] = make_uint2(l01, l23);
}

// ---------------- GEMM: C[M,N] = A[M,K] * B[N,K]^T (split-bf16, cp.async) ----
// BM=128, BN=128, BK=32, 2 stages, 2 CTAs/SM. 256 threads = 8 warps 4(m)x2(n),
// warp tile 32(m) x 64(n). Rows padded to 40 bf16 (80B) -> ldmatrix conflict-free.
#define GPAD 40
#define ARR_BYTES (128 * GPAD * 2)            // 10240 B per array
#define STAGE_BYTES (4 * ARR_BYTES)           // Ah, Al, Bh, Bl = 40960 B
#define GEMM_SMEM (2 * STAGE_BYTES)           // 81920 B -> 2 CTAs/SM

template <bool SPLIT_OUT>
__global__ __launch_bounds__(256, 2) void gemm_cp_kernel(
    const __nv_bfloat16* __restrict__ Ah, const __nv_bfloat16* __restrict__ Al,
    const __nv_bfloat16* __restrict__ Bh, const __nv_bfloat16* __restrict__ Bl,
    float* __restrict__ C, __nv_bfloat16* __restrict__ Ch, __nv_bfloat16* __restrict__ Cl,
    int N, int K)
{
    extern __shared__ char smem[];
    const uint32_t sb = cvta_s(smem);

    const int tid = threadIdx.x, warp = tid >> 5, lane = tid & 31;
    const int m0 = blockIdx.x * 128;
    const int n0 = blockIdx.y * 128;

    const int wm = warp >> 1, wn = warp & 1;
    const int la = (lane & 15) * GPAD + ((lane >> 4) << 3);
    const int lb = (((lane >> 4) << 3) + (lane & 7)) * GPAD + (((lane >> 3) & 1) << 3);

    // per-stage: 512 16B-chunks per array, 2 per thread
    const int r0c = tid >> 2, r1c = (tid + 256) >> 2;
    const int lc = tid & 3;

    const int nk = K >> 5;  // K / 32

    auto load_stage = [&](int s, int kt) {
        const uint32_t base = sb + s * STAGE_BYTES;
        const int k0 = kt << 5;
        const uint32_t o0 = (uint32_t)(r0c * (GPAD * 2) + lc * 16);
        const uint32_t o1 = (uint32_t)(r1c * (GPAD * 2) + lc * 16);
        const size_t ga0 = (size_t)(m0 + r0c) * K + k0 + lc * 8;
        const size_t ga1 = (size_t)(m0 + r1c) * K + k0 + lc * 8;
        const size_t gb0 = (size_t)(n0 + r0c) * K + k0 + lc * 8;
        const size_t gb1 = (size_t)(n0 + r1c) * K + k0 + lc * 8;
        cp16(base + o0,                 Ah + ga0);
        cp16(base + o1,                 Ah + ga1);
        cp16(base + ARR_BYTES + o0,     Al + ga0);
        cp16(base + ARR_BYTES + o1,     Al + ga1);
        cp16(base + 2 * ARR_BYTES + o0, Bh + gb0);
        cp16(base + 2 * ARR_BYTES + o1, Bh + gb1);
        cp16(base + 3 * ARR_BYTES + o0, Bl + gb0);
        cp16(base + 3 * ARR_BYTES + o1, Bl + gb1);
        asm volatile("cp.async.commit_group;" ::: "memory");
    };

    float acc[2][8][4] = {};

    load_stage(0, 0);

#pragma unroll 1
    for (int kt = 0; kt < nk; kt++) {
        const int cur = kt & 1;
        __syncthreads();  // buffer cur^1 fully consumed by all warps
        if (kt + 1 < nk) {
            load_stage(cur ^ 1, kt + 1);
            asm volatile("cp.async.wait_group 1;" ::: "memory");
        } else {
            asm volatile("cp.async.wait_group 0;" ::: "memory");
        }
        __syncthreads();  // stage cur visible

        const uint32_t bAh = sb + cur * STAGE_BYTES;
        const uint32_t bAl = bAh + ARR_BYTES;
        const uint32_t bBh = bAh + 2 * ARR_BYTES;
        const uint32_t bBl = bAh + 3 * ARR_BYTES;

#pragma unroll
        for (int kk = 0; kk < 2; kk++) {
            uint32_t Afh[2][4], Afl[2][4];
#pragma unroll
            for (int mi = 0; mi < 2; mi++) {
                uint32_t off = (uint32_t)(((wm * 32 + mi * 16) * GPAD + kk * 16 + la) << 1);
                ldsm4(Afh[mi], bAh + off);
                ldsm4(Afl[mi], bAl + off);
            }
            uint32_t Bfh[8][2], Bfl[8][2];
#pragma unroll
            for (int ni = 0; ni < 4; ni++) {
                uint32_t t4[4];
                uint32_t off = (uint32_t)(((wn * 64 + ni * 16) * GPAD + kk * 16 + lb) << 1);
                ldsm4(t4, bBh + off);
                Bfh[2 * ni][0] = t4[0]; Bfh[2 * ni][1] = t4[1];
                Bfh[2 * ni + 1][0] = t4[2]; Bfh[2 * ni + 1][1] = t4[3];
                ldsm4(t4, bBl + off);
                Bfl[2 * ni][0] = t4[0]; Bfl[2 * ni][1] = t4[1];
                Bfl[2 * ni + 1][0] = t4[2]; Bfl[2 * ni + 1][1] = t4[3];
            }
#pragma unroll
            for (int mi = 0; mi < 2; mi++)
#pragma unroll
                for (int nj = 0; nj < 8; nj++) {
                    mma_bf16(acc[mi][nj], Afh[mi], Bfh[nj]);
                    mma_bf16(acc[mi][nj], Afh[mi], Bfl[nj]);
                    mma_bf16(acc[mi][nj], Afl[mi], Bfh[nj]);
                }
        }
    }

    const int g = lane >> 2, t = lane & 3;
#pragma unroll
    for (int mi = 0; mi < 2; mi++) {
        int r = m0 + wm * 32 + mi * 16 + g;
#pragma unroll
        for (int nj = 0; nj < 8; nj++) {
            int c = n0 + wn * 64 + nj * 8 + t * 2;
            if (SPLIT_OUT) {
                uint32_t hh, ll;
                split2(acc[mi][nj][0], acc[mi][nj][1], hh, ll);
                __stcs(reinterpret_cast<uint32_t*>(Ch + (size_t)r * N + c), hh);
                __stcs(reinterpret_cast<uint32_t*>(Cl + (size_t)r * N + c), ll);
                split2(acc[mi][nj][2], acc[mi][nj][3], hh, ll);
                __stcs(reinterpret_cast<uint32_t*>(Ch + (size_t)(r + 8) * N + c), hh);
                __stcs(reinterpret_cast<uint32_t*>(Cl + (size_t)(r + 8) * N + c), ll);
            } else {
                __stcs(reinterpret_cast<float2*>(C + (size_t)r * N + c),
                       make_float2(acc[mi][nj][0], acc[mi][nj][1]));
                __stcs(reinterpret_cast<float2*>(C + (size_t)(r + 8) * N + c),
                       make_float2(acc[mi][nj][2], acc[mi][nj][3]));
            }
        }
    }
}

// ---------------- flash attention (mma.sync, split-bf16, cp.async loads) ----
#define APAD 136
#define ATTN_SMEM (6 * 64 * APAD * 2)

__global__ __launch_bounds__(128) void attn_kernel(const __nv_bfloat16* __restrict__ qh,
                                                   const __nv_bfloat16* __restrict__ ql,
                                                   __nv_bfloat16* __restrict__ ath,
                                                   __nv_bfloat16* __restrict__ atl)
{
    extern __shared__ __nv_bfloat16 smA[];
    __nv_bfloat16* sQh = smA;
    __nv_bfloat16* sQl = sQh + 64 * APAD;
    __nv_bfloat16* sKh = sQl + 64 * APAD;
    __nv_bfloat16* sKl = sKh + 64 * APAD;
    __nv_bfloat16* sVh = sKl + 64 * APAD;
    __nv_bfloat16* sVl = sVh + 64 * APAD;

    const int tid = threadIdx.x, lane = tid & 31, warp = tid >> 5;
    const int qb = gridDim.x - 1 - blockIdx.x;
    const int h = blockIdx.y;
    const int q0 = qb * 64;
    const float slope = (h < 32) ? exp2f(-0.25f * (float)(h + 1))
                                 : exp2f(-0.125f * (float)(2 * (h - 32) + 1));
    const float scale = 0.08838834764831845f;

    const uint32_t QhB = cvta_s(sQh), QlB = cvta_s(sQl);
    const uint32_t KhB = cvta_s(sKh), KlB = cvta_s(sKl);
    const uint32_t VhB = cvta_s(sVh), VlB = cvta_s(sVl);

    // async Q tile load (64 x 128 bf16 hi + lo)
#pragma unroll
    for (int j = 0; j < 8; j++) {
        int c = tid + j * 128;
        int row = c >> 4, col8 = c & 15;
        uint32_t off = (uint32_t)((row * APAD + col8 * 8) * 2);
        size_t g = (size_t)(q0 + row) * QKVN + h * 128 + col8 * 8;
        cp16(QhB + off, qh + g);
        cp16(QlB + off, ql + g);
    }
    asm volatile("cp.async.commit_group;" ::: "memory");

    float m0 = -1e30f, m1 = -1e30f, l0 = 0.f, l1 = 0.f;
    float o[16][4] = {};

    const int qm = warp * 16;
    const int g = lane >> 2, t = lane & 3;
    const int la = (lane & 15) * APAD + ((lane >> 4) << 3);
    const int lb = (((lane >> 4) << 3) + (lane & 7)) * APAD + (((lane >> 3) & 1) << 3);
    const int lv = ((((lane >> 3) & 1) << 3) + (lane & 7)) * APAD + ((lane >> 4) << 3);
    const int qpos0 = q0 + qm + g, qpos1 = qpos0 + 8;

#pragma unroll 1
    for (int kb = 0; kb <= qb; kb++) {
        __syncthreads();  // previous tile fully consumed
#pragma unroll
        for (int j = 0; j < 8; j++) {
            int c = tid + j * 128;
            int row = c >> 4, col8 = c & 15;
            uint32_t off = (uint32_t)((row * APAD + col8 * 8) * 2);
            size_t gk = (size_t)(kb * 64 + row) * QKVN + HID + h * 128 + col8 * 8;
            size_t gv = gk + HID;
            cp16(KhB + off, qh + gk);
            cp16(KlB + off, ql + gk);
            cp16(VhB + off, qh + gv);
            cp16(VlB + off, ql + gv);
        }
        asm volatile("cp.async.commit_group;" ::: "memory");
        asm volatile("cp.async.wait_group 0;" ::: "memory");
        __syncthreads();

        float sc[8][4];
#pragma unroll
        for (int i = 0; i < 8; i++)
#pragma unroll
            for (int j = 0; j < 4; j++) sc[i][j] = 0.f;

#pragma unroll
        for (int kc = 0; kc < 8; kc++) {
            uint32_t qfh[4], qfl[4];
            ldsm4(qfh, QhB + (uint32_t)((qm * APAD + kc * 16 + la) << 1));
            ldsm4(qfl, QlB + (uint32_t)((qm * APAD + kc * 16 + la) << 1));
#pragma unroll
            for (int np = 0; np < 4; np++) {
                uint32_t th[4], tl[4];
                uint32_t off = (uint32_t)(((np * 16) * APAD + kc * 16 + lb) << 1);
                ldsm4(th, KhB + off);
                ldsm4(tl, KlB + off);
                uint32_t bh0[2] = {th[0], th[1]}, bh1[2] = {th[2], th[3]};
                uint32_t bl0[2] = {tl[0], tl[1]}, bl1[2] = {tl[2], tl[3]};
                mma_bf16(sc[2 * np],     qfh, bh0);
                mma_bf16(sc[2 * np],     qfh, bl0);
                mma_bf16(sc[2 * np],     qfl, bh0);
                mma_bf16(sc[2 * np + 1], qfh, bh1);
                mma_bf16(sc[2 * np + 1], qfh, bl1);
                mma_bf16(sc[2 * np + 1], qfl, bh1);
            }
        }

        float mt0 = -1e30f, mt1 = -1e30f;
#pragma unroll
        for (int nt = 0; nt < 8; nt++) {
#pragma unroll
            for (int c = 0; c < 2; c++) {
                int kv = kb * 64 + nt * 8 + t * 2 + c;
                float s0 = (kv <= qpos0) ? fmaf(sc[nt][c], scale, -slope * (float)(qpos0 - kv)) : -1e30f;
                float s1 = (kv <= qpos1) ? fmaf(sc[nt][2 + c], scale, -slope * (float)(qpos1 - kv)) : -1e30f;
                sc[nt][c] = s0; sc[nt][2 + c] = s1;
                mt0 = fmaxf(mt0, s0); mt1 = fmaxf(mt1, s1);
            }
        }
        mt0 = fmaxf(mt0, __shfl_xor_sync(0xffffffffu, mt0, 1));
        mt0 = fmaxf(mt0, __shfl_xor_sync(0xffffffffu, mt0, 2));
        mt1 = fmaxf(mt1, __shfl_xor_sync(0xffffffffu, mt1, 1));
        mt1 = fmaxf(mt1, __shfl_xor_sync(0xffffffffu, mt1, 2));
        float mn0 = fmaxf(m0, mt0), mn1 = fmaxf(m1, mt1);
        float f0 = __expf(m0 - mn0), f1 = __expf(m1 - mn1);
        m0 = mn0; m1 = mn1;

        float s0 = 0.f, s1 = 0.f;
#pragma unroll
        for (int nt = 0; nt < 8; nt++) {
            float p0 = __expf(sc[nt][0] - m0), p1 = __expf(sc[nt][1] - m0);
            float p2 = __expf(sc[nt][2] - m1), p3 = __expf(sc[nt][3] - m1);
            sc[nt][0] = p0; sc[nt][1] = p1; sc[nt][2] = p2; sc[nt][3] = p3;
            s0 += p0 + p1; s1 += p2 + p3;
        }
        s0 += __shfl_xor_sync(0xffffffffu, s0, 1);
        s0 += __shfl_xor_sync(0xffffffffu, s0, 2);
        s1 += __shfl_xor_sync(0xffffffffu, s1, 1);
        s1 += __shfl_xor_sync(0xffffffffu, s1, 2);
        l0 = l0 * f0 + s0;
        l1 = l1 * f1 + s1;
#pragma unroll
        for (int db = 0; db < 16; db++) {
            o[db][0] *= f0; o[db][1] *= f0; o[db][2] *= f1; o[db][3] *= f1;
        }

#pragma unroll
        for (int kc2 = 0; kc2 < 4; kc2++) {
            uint32_t ph2[4], pl2[4];
            split2(sc[2 * kc2][0],     sc[2 * kc2][1],     ph2[0], pl2[0]);
            split2(sc[2 * kc2][2],     sc[2 * kc2][3],     ph2[1], pl2[1]);
            split2(sc[2 * kc2 + 1][0], sc[2 * kc2 + 1][1], ph2[2], pl2[2]);
            split2(sc[2 * kc2 + 1][2], sc[2 * kc2 + 1][3], ph2[3], pl2[3]);
#pragma unroll
            for (int d16 = 0; d16 < 8; d16++) {
                uint32_t vh[4], vl[4];
                uint32_t off = (uint32_t)((kc2 * 16 * APAD + d16 * 16 + lv) << 1);
                ldsm4t(vh, VhB + off);
                ldsm4t(vl, VlB + off);
                uint32_t bh0[2] = {vh[0], vh[1]}, bh1[2] = {vh[2], vh[3]};
                uint32_t bl0[2] = {vl[0], vl[1]}, bl1[2] = {vl[2], vl[3]};
                mma_bf16(o[2 * d16],     ph2, bh0);
                mma_bf16(o[2 * d16],     ph2, bl0);
                mma_bf16(o[2 * d16],     pl2, bh0);
                mma_bf16(o[2 * d16 + 1], ph2, bh1);
                mma_bf16(o[2 * d16 + 1], ph2, bl1);
                mma_bf16(o[2 * d16 + 1], pl2, bh1);
            }
        }
    }

    // epilogue: normalize and write split hi/lo bf16 for o_proj GEMM
    float inv0 = 1.f / l0, inv1 = 1.f / l1;
#pragma unroll
    for (int db = 0; db < 16; db++) {
        int col = h * 128 + db * 8 + t * 2;
        int r0 = q0 + qm + g;
        uint32_t hh, ll;
        split2(o[db][0] * inv0, o[db][1] * inv0, hh, ll);
        __stcs(reinterpret_cast<uint32_t*>(ath + (size_t)r0 * HID + col), hh);
        __stcs(reinterpret_cast<uint32_t*>(atl + (size_t)r0 * HID + col), ll);
        split2(o[db][2] * inv1, o[db][3] * inv1, hh, ll);
        __stcs(reinterpret_cast<uint32_t*>(ath + (size_t)(r0 + 8) * HID + col), hh);
        __stcs(reinterpret_cast<uint32_t*>(atl + (size_t)(r0 + 8) * HID + col), ll);
    }
}

// ---------------------------------------------------------------------------
extern "C" void kernel_launch(void* const* d_in, const int* in_sizes, int n_in,
                              void* d_out, int out_size) {
    const float* hs = (const float*)d_in[0];   // [1,2048,5120]
    const float* wp = (const float*)d_in[1];   // [15360,5120]
    const float* wo = (const float*)d_in[2];   // [5120,5120]
    float* out = (float*)d_out;                // [1,2048,5120]

    __nv_bfloat16 *qkh, *qkl, *hsh, *hsl, *wph, *wpl, *woh, *wol, *ath, *atl;
    cudaGetSymbolAddress((void**)&qkh, g_qk_h);
    cudaGetSymbolAddress((void**)&qkl, g_qk_l);
    cudaGetSymbolAddress((void**)&hsh, g_hs_h);
    cudaGetSymbolAddress((void**)&hsl, g_hs_l);
    cudaGetSymbolAddress((void**)&wph, g_wp_h);
    cudaGetSymbolAddress((void**)&wpl, g_wp_l);
    cudaGetSymbolAddress((void**)&woh, g_wo_h);
    cudaGetSymbolAddress((void**)&wol, g_wo_l);
    cudaGetSymbolAddress((void**)&ath, g_at_h);
    cudaGetSymbolAddress((void**)&atl, g_at_l);

    // prepass splits
    {
        int n4 = SEQ * HID / 4;
        split_kernel<<<(n4 + 255) / 256, 256>>>((const float4*)hs, (uint2*)hsh, (uint2*)hsl, n4);
        n4 = QKVN * HID / 4;
        split_kernel<<<(n4 + 255) / 256, 256>>>((const float4*)wp, (uint2*)wph, (uint2*)wpl, n4);
        n4 = HID * HID / 4;
        split_kernel<<<(n4 + 255) / 256, 256>>>((const float4*)wo, (uint2*)woh, (uint2*)wol, n4);
    }

    cudaFuncSetAttribute(gemm_cp_kernel<true>, cudaFuncAttributeMaxDynamicSharedMemorySize, GEMM_SMEM);
    cudaFuncSetAttribute(gemm_cp_kernel<false>, cudaFuncAttributeMaxDynamicSharedMemorySize, GEMM_SMEM);

    // QKV projection: [2048,5120] x [15360,5120]^T -> split bf16 [2048,15360]
    gemm_cp_kernel<true><<<dim3(SEQ / 128, QKVN / 128), 256, GEMM_SMEM>>>(
        hsh, hsl, wph, wpl, nullptr, qkh, qkl, QKVN, HID);

    // attention (reads split qkv, writes split hi/lo output)
    cudaFuncSetAttribute(attn_kernel, cudaFuncAttributeMaxDynamicSharedMemorySize, ATTN_SMEM);
    attn_kernel<<<dim3(SEQ / 64, 40), 128, ATTN_SMEM>>>(qkh, qkl, ath, atl);

    // o_proj: [2048,5120] x [5120,5120]^T -> [2048,5120] fp32
    gemm_cp_kernel<false><<<dim3(SEQ / 128, HID / 128), 256, GEMM_SMEM>>>(
        ath, atl, woh, wol, out, nullptr, nullptr, HID, HID);
}

// round 7
// speedup vs baseline: 1.4072x; 1.0813x over previous
#include <cuda_runtime.h>
#include <cuda_bf16.h>
#include <cuda_fp16.h>
#include <cstdint>

#define SEQ  2048
#define HID  5120
#define QKVN 15360

// ---------------- scratch (device globals; allocation-free) ----------------
__device__ __align__(256) __nv_bfloat16 g_qk_h[SEQ * QKVN];   // qkv hi (63MB)
__device__ __align__(256) __nv_bfloat16 g_qk_l[SEQ * QKVN];   // qkv lo
__device__ __align__(256) __nv_bfloat16 g_hs_h[SEQ * HID];
__device__ __align__(256) __nv_bfloat16 g_hs_l[SEQ * HID];
__device__ __align__(256) __nv_bfloat16 g_wp_h[QKVN * HID];
__device__ __align__(256) __nv_bfloat16 g_wp_l[QKVN * HID];
__device__ __align__(256) __half g_wo_h[HID * HID];           // fp16 hi only
__device__ __align__(256) __half g_at_h[SEQ * HID];           // attn out fp16 hi
__device__ __align__(256) __half g_at_l[SEQ * HID];           // attn out fp16 lo

// ---------------- helpers ----------------
__device__ __forceinline__ uint32_t cvta_s(const void* p) {
    return (uint32_t)__cvta_generic_to_shared(p);
}
__device__ __forceinline__ void split2(float f0, float f1, uint32_t& h, uint32_t& l) {
    __nv_bfloat16 h0 = __float2bfloat16_rn(f0), h1 = __float2bfloat16_rn(f1);
    float r0 = f0 - __bfloat162float(h0), r1 = f1 - __bfloat162float(h1);
    __nv_bfloat16 e0 = __float2bfloat16_rn(r0), e1 = __float2bfloat16_rn(r1);
    h = (uint32_t)__bfloat16_as_ushort(h0) | ((uint32_t)__bfloat16_as_ushort(h1) << 16);
    l = (uint32_t)__bfloat16_as_ushort(e0) | ((uint32_t)__bfloat16_as_ushort(e1) << 16);
}
__device__ __forceinline__ void split2h(float f0, float f1, uint32_t& h, uint32_t& l) {
    __half h0 = __float2half_rn(f0), h1 = __float2half_rn(f1);
    float r0 = f0 - __half2float(h0), r1 = f1 - __half2float(h1);
    __half e0 = __float2half_rn(r0), e1 = __float2half_rn(r1);
    h = (uint32_t)__half_as_ushort(h0) | ((uint32_t)__half_as_ushort(h1) << 16);
    l = (uint32_t)__half_as_ushort(e0) | ((uint32_t)__half_as_ushort(e1) << 16);
}
__device__ __forceinline__ void ldsm4(uint32_t r[4], uint32_t a) {
    asm volatile("ldmatrix.sync.aligned.m8n8.x4.shared.b16 {%0,%1,%2,%3}, [%4];"
                 : "=r"(r[0]), "=r"(r[1]), "=r"(r[2]), "=r"(r[3]) : "r"(a));
}
__device__ __forceinline__ void ldsm4t(uint32_t r[4], uint32_t a) {
    asm volatile("ldmatrix.sync.aligned.m8n8.x4.trans.shared.b16 {%0,%1,%2,%3}, [%4];"
                 : "=r"(r[0]), "=r"(r[1]), "=r"(r[2]), "=r"(r[3]) : "r"(a));
}
__device__ __forceinline__ void mma_bf16(float d[4], const uint32_t a[4], const uint32_t b[2]) {
    asm volatile("mma.sync.aligned.m16n8k16.row.col.f32.bf16.bf16.f32 "
                 "{%0,%1,%2,%3}, {%4,%5,%6,%7}, {%8,%9}, {%0,%1,%2,%3};"
                 : "+f"(d[0]), "+f"(d[1]), "+f"(d[2]), "+f"(d[3])
                 : "r"(a[0]), "r"(a[1]), "r"(a[2]), "r"(a[3]), "r"(b[0]), "r"(b[1]));
}
__device__ __forceinline__ void mma_f16(float d[4], const uint32_t a[4], const uint32_t b[2]) {
    asm volatile("mma.sync.aligned.m16n8k16.row.col.f32.f16.f16.f32 "
                 "{%0,%1,%2,%3}, {%4,%5,%6,%7}, {%8,%9}, {%0,%1,%2,%3};"
                 : "+f"(d[0]), "+f"(d[1]), "+f"(d[2]), "+f"(d[3])
                 : "r"(a[0]), "r"(a[1]), "r"(a[2]), "r"(a[3]), "r"(b[0]), "r"(b[1]));
}
__device__ __forceinline__ void cp16(uint32_t dst, const void* src) {
    asm volatile("cp.async.cg.shared.global [%0], [%1], 16;" :: "r"(dst), "l"(src));
}

// ---------------- prepasses ----------------
__global__ __launch_bounds__(256) void split_kernel(const float4* __restrict__ src,
                                                    uint2* __restrict__ hi,
                                                    uint2* __restrict__ lo, int n4) {
    int i = blockIdx.x * blockDim.x + threadIdx.x;
    if (i >= n4) return;
    float4 v = src[i];
    uint32_t h01, l01, h23, l23;
    split2(v.x, v.y, h01, l01);
    split2(v.z, v.w, h23, l23);
    hi[i] = make_uint2(h01, h23);
    lo[i] = make_uint2(l01, l23);
}
__global__ __launch_bounds__(256) void split_h16_kernel(const float4* __restrict__ src,
                                                        uint2* __restrict__ hi, int n4) {
    int i = blockIdx.x * blockDim.x + threadIdx.x;
    if (i >= n4) return;
    float4 v = src[i];
    __half2 a = __floats2half2_rn(v.x, v.y);
    __half2 b = __floats2half2_rn(v.z, v.w);
    hi[i] = make_uint2(*reinterpret_cast<uint32_t*>(&a), *reinterpret_cast<uint32_t*>(&b));
}

// ---------------- GEMM (bf16, 3-term): C = A * B^T, split outputs ----------
#define GPAD 40
#define ARR_BYTES (128 * GPAD * 2)            // 10240
#define STAGE_BYTES (4 * ARR_BYTES)           // 40960
#define GEMM_SMEM (2 * STAGE_BYTES)           // 81920

__global__ __launch_bounds__(256, 2) void gemm_cp_kernel(
    const __nv_bfloat16* __restrict__ Ah, const __nv_bfloat16* __restrict__ Al,
    const __nv_bfloat16* __restrict__ Bh, const __nv_bfloat16* __restrict__ Bl,
    __nv_bfloat16* __restrict__ Ch, __nv_bfloat16* __restrict__ Cl,
    int N, int K)
{
    extern __shared__ char smem[];
    const uint32_t sb = cvta_s(smem);

    const int tid = threadIdx.x, warp = tid >> 5, lane = tid & 31;
    const int m0 = blockIdx.x * 128;
    const int n0 = blockIdx.y * 128;

    const int wm = warp >> 1, wn = warp & 1;
    const int la = (lane & 15) * GPAD + ((lane >> 4) << 3);
    const int lb = (((lane >> 4) << 3) + (lane & 7)) * GPAD + (((lane >> 3) & 1) << 3);

    const int r0c = tid >> 2, r1c = (tid + 256) >> 2;
    const int lc = tid & 3;
    const int nk = K >> 5;

    auto load_stage = [&](int s, int kt) {
        const uint32_t base = sb + s * STAGE_BYTES;
        const int k0 = kt << 5;
        const uint32_t o0 = (uint32_t)(r0c * (GPAD * 2) + lc * 16);
        const uint32_t o1 = (uint32_t)(r1c * (GPAD * 2) + lc * 16);
        const size_t ga0 = (size_t)(m0 + r0c) * K + k0 + lc * 8;
        const size_t ga1 = (size_t)(m0 + r1c) * K + k0 + lc * 8;
        const size_t gb0 = (size_t)(n0 + r0c) * K + k0 + lc * 8;
        const size_t gb1 = (size_t)(n0 + r1c) * K + k0 + lc * 8;
        cp16(base + o0,                 Ah + ga0);
        cp16(base + o1,                 Ah + ga1);
        cp16(base + ARR_BYTES + o0,     Al + ga0);
        cp16(base + ARR_BYTES + o1,     Al + ga1);
        cp16(base + 2 * ARR_BYTES + o0, Bh + gb0);
        cp16(base + 2 * ARR_BYTES + o1, Bh + gb1);
        cp16(base + 3 * ARR_BYTES + o0, Bl + gb0);
        cp16(base + 3 * ARR_BYTES + o1, Bl + gb1);
        asm volatile("cp.async.commit_group;" ::: "memory");
    };

    float acc[2][8][4] = {};
    load_stage(0, 0);

#pragma unroll 1
    for (int kt = 0; kt < nk; kt++) {
        const int cur = kt & 1;
        __syncthreads();
        if (kt + 1 < nk) {
            load_stage(cur ^ 1, kt + 1);
            asm volatile("cp.async.wait_group 1;" ::: "memory");
        } else {
            asm volatile("cp.async.wait_group 0;" ::: "memory");
        }
        __syncthreads();

        const uint32_t bAh = sb + cur * STAGE_BYTES;
        const uint32_t bAl = bAh + ARR_BYTES;
        const uint32_t bBh = bAh + 2 * ARR_BYTES;
        const uint32_t bBl = bAh + 3 * ARR_BYTES;

#pragma unroll
        for (int kk = 0; kk < 2; kk++) {
            uint32_t Afh[2][4], Afl[2][4];
#pragma unroll
            for (int mi = 0; mi < 2; mi++) {
                uint32_t off = (uint32_t)(((wm * 32 + mi * 16) * GPAD + kk * 16 + la) << 1);
                ldsm4(Afh[mi], bAh + off);
                ldsm4(Afl[mi], bAl + off);
            }
            uint32_t Bfh[8][2], Bfl[8][2];
#pragma unroll
            for (int ni = 0; ni < 4; ni++) {
                uint32_t t4[4];
                uint32_t off = (uint32_t)(((wn * 64 + ni * 16) * GPAD + kk * 16 + lb) << 1);
                ldsm4(t4, bBh + off);
                Bfh[2 * ni][0] = t4[0]; Bfh[2 * ni][1] = t4[1];
                Bfh[2 * ni + 1][0] = t4[2]; Bfh[2 * ni + 1][1] = t4[3];
                ldsm4(t4, bBl + off);
                Bfl[2 * ni][0] = t4[0]; Bfl[2 * ni][1] = t4[1];
                Bfl[2 * ni + 1][0] = t4[2]; Bfl[2 * ni + 1][1] = t4[3];
            }
#pragma unroll
            for (int mi = 0; mi < 2; mi++)
#pragma unroll
                for (int nj = 0; nj < 8; nj++) {
                    mma_bf16(acc[mi][nj], Afh[mi], Bfh[nj]);
                    mma_bf16(acc[mi][nj], Afh[mi], Bfl[nj]);
                    mma_bf16(acc[mi][nj], Afl[mi], Bfh[nj]);
                }
        }
    }

    const int g = lane >> 2, t = lane & 3;
#pragma unroll
    for (int mi = 0; mi < 2; mi++) {
        int r = m0 + wm * 32 + mi * 16 + g;
#pragma unroll
        for (int nj = 0; nj < 8; nj++) {
            int c = n0 + wn * 64 + nj * 8 + t * 2;
            uint32_t hh, ll;
            split2(acc[mi][nj][0], acc[mi][nj][1], hh, ll);
            __stcs(reinterpret_cast<uint32_t*>(Ch + (size_t)r * N + c), hh);
            __stcs(reinterpret_cast<uint32_t*>(Cl + (size_t)r * N + c), ll);
            split2(acc[mi][nj][2], acc[mi][nj][3], hh, ll);
            __stcs(reinterpret_cast<uint32_t*>(Ch + (size_t)(r + 8) * N + c), hh);
            __stcs(reinterpret_cast<uint32_t*>(Cl + (size_t)(r + 8) * N + c), ll);
        }
    }
}

// ---------------- o_proj GEMM (fp16, 2-term): C = (Ah+Al) * Bh^T ----------
#define HARR 10240
#define HSTAGE (3 * HARR)                      // 30720
#define G2_SMEM (2 * HSTAGE)                   // 61440

__global__ __launch_bounds__(256, 2) void gemm_h2_kernel(
    const __half* __restrict__ Ah, const __half* __restrict__ Al,
    const __half* __restrict__ Bh, float* __restrict__ C, int N, int K)
{
    extern __shared__ char smem[];
    const uint32_t sb = cvta_s(smem);

    const int tid = threadIdx.x, warp = tid >> 5, lane = tid & 31;
    const int m0 = blockIdx.x * 128;
    const int n0 = blockIdx.y * 128;

    const int wm = warp >> 1, wn = warp & 1;
    const int la = (lane & 15) * GPAD + ((lane >> 4) << 3);
    const int lb = (((lane >> 4) << 3) + (lane & 7)) * GPAD + (((lane >> 3) & 1) << 3);

    const int r0c = tid >> 2, r1c = (tid + 256) >> 2;
    const int lc = tid & 3;
    const int nk = K >> 5;

    auto load_stage = [&](int s, int kt) {
        const uint32_t base = sb + s * HSTAGE;
        const int k0 = kt << 5;
        const uint32_t o0 = (uint32_t)(r0c * (GPAD * 2) + lc * 16);
        const uint32_t o1 = (uint32_t)(r1c * (GPAD * 2) + lc * 16);
        const size_t ga0 = (size_t)(m0 + r0c) * K + k0 + lc * 8;
        const size_t ga1 = (size_t)(m0 + r1c) * K + k0 + lc * 8;
        const size_t gb0 = (size_t)(n0 + r0c) * K + k0 + lc * 8;
        const size_t gb1 = (size_t)(n0 + r1c) * K + k0 + lc * 8;
        cp16(base + o0,            Ah + ga0);
        cp16(base + o1,            Ah + ga1);
        cp16(base + HARR + o0,     Al + ga0);
        cp16(base + HARR + o1,     Al + ga1);
        cp16(base + 2 * HARR + o0, Bh + gb0);
        cp16(base + 2 * HARR + o1, Bh + gb1);
        asm volatile("cp.async.commit_group;" ::: "memory");
    };

    float acc[2][8][4] = {};
    load_stage(0, 0);

#pragma unroll 1
    for (int kt = 0; kt < nk; kt++) {
        const int cur = kt & 1;
        __syncthreads();
        if (kt + 1 < nk) {
            load_stage(cur ^ 1, kt + 1);
            asm volatile("cp.async.wait_group 1;" ::: "memory");
        } else {
            asm volatile("cp.async.wait_group 0;" ::: "memory");
        }
        __syncthreads();

        const uint32_t bAh = sb + cur * HSTAGE;
        const uint32_t bAl = bAh + HARR;
        const uint32_t bBh = bAh + 2 * HARR;

#pragma unroll
        for (int kk = 0; kk < 2; kk++) {
            uint32_t Afh[2][4], Afl[2][4];
#pragma unroll
            for (int mi = 0; mi < 2; mi++) {
                uint32_t off = (uint32_t)(((wm * 32 + mi * 16) * GPAD + kk * 16 + la) << 1);
                ldsm4(Afh[mi], bAh + off);
                ldsm4(Afl[mi], bAl + off);
            }
            uint32_t Bfh[8][2];
#pragma unroll
            for (int ni = 0; ni < 4; ni++) {
                uint32_t t4[4];
                uint32_t off = (uint32_t)(((wn * 64 + ni * 16) * GPAD + kk * 16 + lb) << 1);
                ldsm4(t4, bBh + off);
                Bfh[2 * ni][0] = t4[0]; Bfh[2 * ni][1] = t4[1];
                Bfh[2 * ni + 1][0] = t4[2]; Bfh[2 * ni + 1][1] = t4[3];
            }
#pragma unroll
            for (int mi = 0; mi < 2; mi++)
#pragma unroll
                for (int nj = 0; nj < 8; nj++) {
                    mma_f16(acc[mi][nj], Afh[mi], Bfh[nj]);
                    mma_f16(acc[mi][nj], Afl[mi], Bfh[nj]);
                }
        }
    }

    const int g = lane >> 2, t = lane & 3;
#pragma unroll
    for (int mi = 0; mi < 2; mi++) {
        int r = m0 + wm * 32 + mi * 16 + g;
#pragma unroll
        for (int nj = 0; nj < 8; nj++) {
            int c = n0 + wn * 64 + nj * 8 + t * 2;
            __stcs(reinterpret_cast<float2*>(C + (size_t)r * N + c),
                   make_float2(acc[mi][nj][0], acc[mi][nj][1]));
            __stcs(reinterpret_cast<float2*>(C + (size_t)(r + 8) * N + c),
                   make_float2(acc[mi][nj][2], acc[mi][nj][3]));
        }
    }
}

// ---------------- flash attention v2: 128-row q-tiles, double-buffered KV --
#define APAD 136
#define KARR (64 * APAD * 2)                       // bytes per KV array
#define ATTN_SMEM ((2 * 128 + 8 * 64) * APAD * 2)  // 208896 B

__global__ __launch_bounds__(256) void attn_kernel(const __nv_bfloat16* __restrict__ qh,
                                                   const __nv_bfloat16* __restrict__ ql,
                                                   __half* __restrict__ ath,
                                                   __half* __restrict__ atl)
{
    extern __shared__ __nv_bfloat16 smA[];
    __nv_bfloat16* sQh = smA;
    __nv_bfloat16* sQl = sQh + 128 * APAD;
    const uint32_t QhB = cvta_s(sQh), QlB = cvta_s(sQl);
    const uint32_t KVB = cvta_s(sQl + 128 * APAD);

    const int tid = threadIdx.x, lane = tid & 31, warp = tid >> 5;
    const int bq = gridDim.x - 1 - blockIdx.x;    // heavy tiles first
    const int h = blockIdx.y;
    const int q0 = bq * 128;
    const int nkb = 2 * (bq + 1);
    const float slope = (h < 32) ? exp2f(-0.25f * (float)(h + 1))
                                 : exp2f(-0.125f * (float)(2 * (h - 32) + 1));
    const float scale = 0.08838834764831845f;

    // Q tile load (128 x 128 hi/lo)
#pragma unroll
    for (int j = 0; j < 8; j++) {
        int c = tid + j * 256;
        int row = c >> 4, col8 = c & 15;
        uint32_t off = (uint32_t)((row * APAD + col8 * 8) * 2);
        size_t gq = (size_t)(q0 + row) * QKVN + h * 128 + col8 * 8;
        cp16(QhB + off, qh + gq);
        cp16(QlB + off, ql + gq);
    }

    auto load_kv = [&](int buf, int kb) {
        const uint32_t base = KVB + (uint32_t)buf * (4 * KARR);
#pragma unroll
        for (int j = 0; j < 4; j++) {
            int c = tid + j * 256;
            int row = c >> 4, col8 = c & 15;
            uint32_t off = (uint32_t)((row * APAD + col8 * 8) * 2);
            size_t gk = (size_t)(kb * 64 + row) * QKVN + HID + h * 128 + col8 * 8;
            size_t gv = gk + HID;
            cp16(base + off,            qh + gk);
            cp16(base + KARR + off,     ql + gk);
            cp16(base + 2 * KARR + off, qh + gv);
            cp16(base + 3 * KARR + off, ql + gv);
        }
        asm volatile("cp.async.commit_group;" ::: "memory");
    };

    load_kv(0, 0);  // group 0 = Q + KV0

    float m0 = -1e30f, m1 = -1e30f, l0 = 0.f, l1 = 0.f;
    float o[16][4] = {};

    const int qm = warp * 16;
    const int g = lane >> 2, t = lane & 3;
    const int la = (lane & 15) * APAD + ((lane >> 4) << 3);
    const int lb = (((lane >> 4) << 3) + (lane & 7)) * APAD + (((lane >> 3) & 1) << 3);
    const int lv = ((((lane >> 3) & 1) << 3) + (lane & 7)) * APAD + ((lane >> 4) << 3);
    const int qpos0 = q0 + qm + g, qpos1 = qpos0 + 8;

#pragma unroll 1
    for (int kb = 0; kb < nkb; kb++) {
        const int cur = kb & 1;
        __syncthreads();  // buffer cur^1 fully consumed
        if (kb + 1 < nkb) {
            load_kv(cur ^ 1, kb + 1);
            asm volatile("cp.async.wait_group 1;" ::: "memory");
        } else {
            asm volatile("cp.async.wait_group 0;" ::: "memory");
        }
        __syncthreads();

        const uint32_t KhB = KVB + (uint32_t)cur * (4 * KARR);
        const uint32_t KlB = KhB + KARR;
        const uint32_t VhB = KhB + 2 * KARR;
        const uint32_t VlB = KhB + 3 * KARR;

        float sc[8][4];
#pragma unroll
        for (int i = 0; i < 8; i++)
#pragma unroll
            for (int j = 0; j < 4; j++) sc[i][j] = 0.f;

#pragma unroll
        for (int kc = 0; kc < 8; kc++) {
            uint32_t qfh[4], qfl[4];
            ldsm4(qfh, QhB + (uint32_t)((qm * APAD + kc * 16 + la) << 1));
            ldsm4(qfl, QlB + (uint32_t)((qm * APAD + kc * 16 + la) << 1));
#pragma unroll
            for (int np = 0; np < 4; np++) {
                uint32_t th[4], tl[4];
                uint32_t off = (uint32_t)(((np * 16) * APAD + kc * 16 + lb) << 1);
                ldsm4(th, KhB + off);
                ldsm4(tl, KlB + off);
                uint32_t bh0[2] = {th[0], th[1]}, bh1[2] = {th[2], th[3]};
                uint32_t bl0[2] = {tl[0], tl[1]}, bl1[2] = {tl[2], tl[3]};
                mma_bf16(sc[2 * np],     qfh, bh0);
                mma_bf16(sc[2 * np],     qfh, bl0);
                mma_bf16(sc[2 * np],     qfl, bh0);
                mma_bf16(sc[2 * np + 1], qfh, bh1);
                mma_bf16(sc[2 * np + 1], qfh, bl1);
                mma_bf16(sc[2 * np + 1], qfl, bh1);
            }
        }

        float mt0 = -1e30f, mt1 = -1e30f;
#pragma unroll
        for (int nt = 0; nt < 8; nt++) {
#pragma unroll
            for (int c = 0; c < 2; c++) {
                int kv = kb * 64 + nt * 8 + t * 2 + c;
                float s0 = (kv <= qpos0) ? fmaf(sc[nt][c], scale, -slope * (float)(qpos0 - kv)) : -1e30f;
                float s1 = (kv <= qpos1) ? fmaf(sc[nt][2 + c], scale, -slope * (float)(qpos1 - kv)) : -1e30f;
                sc[nt][c] = s0; sc[nt][2 + c] = s1;
                mt0 = fmaxf(mt0, s0); mt1 = fmaxf(mt1, s1);
            }
        }
        mt0 = fmaxf(mt0, __shfl_xor_sync(0xffffffffu, mt0, 1));
        mt0 = fmaxf(mt0, __shfl_xor_sync(0xffffffffu, mt0, 2));
        mt1 = fmaxf(mt1, __shfl_xor_sync(0xffffffffu, mt1, 1));
        mt1 = fmaxf(mt1, __shfl_xor_sync(0xffffffffu, mt1, 2));
        float mn0 = fmaxf(m0, mt0), mn1 = fmaxf(m1, mt1);
        float f0 = __expf(m0 - mn0), f1 = __expf(m1 - mn1);
        m0 = mn0; m1 = mn1;

        float s0 = 0.f, s1 = 0.f;
#pragma unroll
        for (int nt = 0; nt < 8; nt++) {
            float p0 = __expf(sc[nt][0] - m0), p1 = __expf(sc[nt][1] - m0);
            float p2 = __expf(sc[nt][2] - m1), p3 = __expf(sc[nt][3] - m1);
            sc[nt][0] = p0; sc[nt][1] = p1; sc[nt][2] = p2; sc[nt][3] = p3;
            s0 += p0 + p1; s1 += p2 + p3;
        }
        s0 += __shfl_xor_sync(0xffffffffu, s0, 1);
        s0 += __shfl_xor_sync(0xffffffffu, s0, 2);
        s1 += __shfl_xor_sync(0xffffffffu, s1, 1);
        s1 += __shfl_xor_sync(0xffffffffu, s1, 2);
        l0 = l0 * f0 + s0;
        l1 = l1 * f1 + s1;
#pragma unroll
        for (int db = 0; db < 16; db++) {
            o[db][0] *= f0; o[db][1] *= f0; o[db][2] *= f1; o[db][3] *= f1;
        }

#pragma unroll
        for (int kc2 = 0; kc2 < 4; kc2++) {
            uint32_t ph2[4], pl2[4];
            split2(sc[2 * kc2][0],     sc[2 * kc2][1],     ph2[0], pl2[0]);
            split2(sc[2 * kc2][2],     sc[2 * kc2][3],     ph2[1], pl2[1]);
            split2(sc[2 * kc2 + 1][0], sc[2 * kc2 + 1][1], ph2[2], pl2[2]);
            split2(sc[2 * kc2 + 1][2], sc[2 * kc2 + 1][3], ph2[3], pl2[3]);
#pragma unroll
            for (int d16 = 0; d16 < 8; d16++) {
                uint32_t vh[4], vl[4];
                uint32_t off = (uint32_t)((kc2 * 16 * APAD + d16 * 16 + lv) << 1);
                ldsm4t(vh, VhB + off);
                ldsm4t(vl, VlB + off);
                uint32_t bh0[2] = {vh[0], vh[1]}, bh1[2] = {vh[2], vh[3]};
                uint32_t bl0[2] = {vl[0], vl[1]}, bl1[2] = {vl[2], vl[3]};
                mma_bf16(o[2 * d16],     ph2, bh0);
                mma_bf16(o[2 * d16],     ph2, bl0);
                mma_bf16(o[2 * d16],     pl2, bh0);
                mma_bf16(o[2 * d16 + 1], ph2, bh1);
                mma_bf16(o[2 * d16 + 1], ph2, bl1);
                mma_bf16(o[2 * d16 + 1], pl2, bh1);
            }
        }
    }

    // epilogue: normalize, write fp16 hi/lo for o_proj
    float inv0 = 1.f / l0, inv1 = 1.f / l1;
#pragma unroll
    for (int db = 0; db < 16; db++) {
        int col = h * 128 + db * 8 + t * 2;
        int r0 = q0 + qm + g;
        uint32_t hh, ll;
        split2h(o[db][0] * inv0, o[db][1] * inv0, hh, ll);
        __stcs(reinterpret_cast<uint32_t*>(ath + (size_t)r0 * HID + col), hh);
        __stcs(reinterpret_cast<uint32_t*>(atl + (size_t)r0 * HID + col), ll);
        split2h(o[db][2] * inv1, o[db][3] * inv1, hh, ll);
        __stcs(reinterpret_cast<uint32_t*>(ath + (size_t)(r0 + 8) * HID + col), hh);
        __stcs(reinterpret_cast<uint32_t*>(atl + (size_t)(r0 + 8) * HID + col), ll);
    }
}

// ---------------------------------------------------------------------------
extern "C" void kernel_launch(void* const* d_in, const int* in_sizes, int n_in,
                              void* d_out, int out_size) {
    const float* hs = (const float*)d_in[0];   // [1,2048,5120]
    const float* wp = (const float*)d_in[1];   // [15360,5120]
    const float* wo = (const float*)d_in[2];   // [5120,5120]
    float* out = (float*)d_out;                // [1,2048,5120]

    __nv_bfloat16 *qkh, *qkl, *hsh, *hsl, *wph, *wpl;
    __half *woh, *ath, *atl;
    cudaGetSymbolAddress((void**)&qkh, g_qk_h);
    cudaGetSymbolAddress((void**)&qkl, g_qk_l);
    cudaGetSymbolAddress((void**)&hsh, g_hs_h);
    cudaGetSymbolAddress((void**)&hsl, g_hs_l);
    cudaGetSymbolAddress((void**)&wph, g_wp_h);
    cudaGetSymbolAddress((void**)&wpl, g_wp_l);
    cudaGetSymbolAddress((void**)&woh, g_wo_h);
    cudaGetSymbolAddress((void**)&ath, g_at_h);
    cudaGetSymbolAddress((void**)&atl, g_at_l);

    // prepass splits
    {
        int n4 = SEQ * HID / 4;
        split_kernel<<<(n4 + 255) / 256, 256>>>((const float4*)hs, (uint2*)hsh, (uint2*)hsl, n4);
        n4 = QKVN * HID / 4;
        split_kernel<<<(n4 + 255) / 256, 256>>>((const float4*)wp, (uint2*)wph, (uint2*)wpl, n4);
        n4 = HID * HID / 4;
        split_h16_kernel<<<(n4 + 255) / 256, 256>>>((const float4*)wo, (uint2*)woh, n4);
    }

    cudaFuncSetAttribute(gemm_cp_kernel, cudaFuncAttributeMaxDynamicSharedMemorySize, GEMM_SMEM);
    cudaFuncSetAttribute(gemm_h2_kernel, cudaFuncAttributeMaxDynamicSharedMemorySize, G2_SMEM);
    cudaFuncSetAttribute(attn_kernel, cudaFuncAttributeMaxDynamicSharedMemorySize, ATTN_SMEM);

    // QKV projection -> split bf16 [2048,15360]
    gemm_cp_kernel<<<dim3(SEQ / 128, QKVN / 128), 256, GEMM_SMEM>>>(
        hsh, hsl, wph, wpl, qkh, qkl, QKVN, HID);

    // attention (128-row q tiles, double-buffered KV; writes fp16 hi/lo)
    attn_kernel<<<dim3(SEQ / 128, 40), 256, ATTN_SMEM>>>(qkh, qkl, ath, atl);

    // o_proj (fp16 2-term): [2048,5120] x [5120,5120]^T -> fp32
    gemm_h2_kernel<<<dim3(SEQ / 128, HID / 128), 256, G2_SMEM>>>(
        ath, atl, woh, out, HID, HID);
}

// round 8
// speedup vs baseline: 1.7978x; 1.2776x over previous
#include <cuda_runtime.h>
#include <cuda_bf16.h>
#include <cuda_fp16.h>
#include <cstdint>

#define SEQ  2048
#define HID  5120
#define QKVN 15360

// ---------------- scratch (device globals; allocation-free) ----------------
__device__ __align__(256) __half g_qk_h[SEQ * QKVN];   // qkv hi fp16
__device__ __align__(256) __half g_qk_l[SEQ * QKVN];   // qkv lo fp16
__device__ __align__(256) __half g_hs_h[SEQ * HID];
__device__ __align__(256) __half g_hs_l[SEQ * HID];
__device__ __align__(256) __half g_wp_h[QKVN * HID];   // w_pack hi only
__device__ __align__(256) __half g_wo_h[HID * HID];    // w_o hi only
__device__ __align__(256) __half g_at_h[SEQ * HID];    // attn out fp16 hi
__device__ __align__(256) __half g_at_l[SEQ * HID];    // attn out fp16 lo

// ---------------- helpers ----------------
__device__ __forceinline__ uint32_t cvta_s(const void* p) {
    return (uint32_t)__cvta_generic_to_shared(p);
}
__device__ __forceinline__ void split2h(float f0, float f1, uint32_t& h, uint32_t& l) {
    __half h0 = __float2half_rn(f0), h1 = __float2half_rn(f1);
    float r0 = f0 - __half2float(h0), r1 = f1 - __half2float(h1);
    __half e0 = __float2half_rn(r0), e1 = __float2half_rn(r1);
    h = (uint32_t)__half_as_ushort(h0) | ((uint32_t)__half_as_ushort(h1) << 16);
    l = (uint32_t)__half_as_ushort(e0) | ((uint32_t)__half_as_ushort(e1) << 16);
}
__device__ __forceinline__ void ldsm4(uint32_t r[4], uint32_t a) {
    asm volatile("ldmatrix.sync.aligned.m8n8.x4.shared.b16 {%0,%1,%2,%3}, [%4];"
                 : "=r"(r[0]), "=r"(r[1]), "=r"(r[2]), "=r"(r[3]) : "r"(a));
}
__device__ __forceinline__ void ldsm4t(uint32_t r[4], uint32_t a) {
    asm volatile("ldmatrix.sync.aligned.m8n8.x4.trans.shared.b16 {%0,%1,%2,%3}, [%4];"
                 : "=r"(r[0]), "=r"(r[1]), "=r"(r[2]), "=r"(r[3]) : "r"(a));
}
__device__ __forceinline__ void mma_f16(float d[4], const uint32_t a[4], const uint32_t b[2]) {
    asm volatile("mma.sync.aligned.m16n8k16.row.col.f32.f16.f16.f32 "
                 "{%0,%1,%2,%3}, {%4,%5,%6,%7}, {%8,%9}, {%0,%1,%2,%3};"
                 : "+f"(d[0]), "+f"(d[1]), "+f"(d[2]), "+f"(d[3])
                 : "r"(a[0]), "r"(a[1]), "r"(a[2]), "r"(a[3]), "r"(b[0]), "r"(b[1]));
}
__device__ __forceinline__ void cp16(uint32_t dst, const void* src) {
    asm volatile("cp.async.cg.shared.global [%0], [%1], 16;" :: "r"(dst), "l"(src));
}

// ---------------- prepasses ----------------
__global__ __launch_bounds__(256) void split_h2_kernel(const float4* __restrict__ src,
                                                       uint2* __restrict__ hi,
                                                       uint2* __restrict__ lo, int n4) {
    int i = blockIdx.x * blockDim.x + threadIdx.x;
    if (i >= n4) return;
    float4 v = src[i];
    uint32_t h01, l01, h23, l23;
    split2h(v.x, v.y, h01, l01);
    split2h(v.z, v.w, h23, l23);
    hi[i] = make_uint2(h01, h23);
    lo[i] = make_uint2(l01, l23);
}
__global__ __launch_bounds__(256) void split_h16_kernel(const float4* __restrict__ src,
                                                        uint2* __restrict__ hi, int n4) {
    int i = blockIdx.x * blockDim.x + threadIdx.x;
    if (i >= n4) return;
    float4 v = src[i];
    __half2 a = __floats2half2_rn(v.x, v.y);
    __half2 b = __floats2half2_rn(v.z, v.w);
    hi[i] = make_uint2(*reinterpret_cast<uint32_t*>(&a), *reinterpret_cast<uint32_t*>(&b));
}

// ---------------- GEMM (fp16, 2-term): C = (Ah+Al) * Bh^T ------------------
// BM=128, BN=128, BK=32, 2 stages, 2 CTAs/SM. 8 warps 4(m)x2(n).
#define GPAD 40
#define HARR 10240                            // 128*GPAD*2 bytes per array
#define HSTAGE (3 * HARR)                     // Ah, Al, Bh = 30720
#define G2_SMEM (2 * HSTAGE)                  // 61440

template <bool SPLIT_OUT>
__global__ __launch_bounds__(256, 2) void gemm_h2_kernel(
    const __half* __restrict__ Ah, const __half* __restrict__ Al,
    const __half* __restrict__ Bh, float* __restrict__ C,
    __half* __restrict__ Ch, __half* __restrict__ Cl, int N, int K)
{
    extern __shared__ char smem[];
    const uint32_t sb = cvta_s(smem);

    const int tid = threadIdx.x, warp = tid >> 5, lane = tid & 31;
    const int m0 = blockIdx.x * 128;
    const int n0 = blockIdx.y * 128;

    const int wm = warp >> 1, wn = warp & 1;
    const int la = (lane & 15) * GPAD + ((lane >> 4) << 3);
    const int lb = (((lane >> 4) << 3) + (lane & 7)) * GPAD + (((lane >> 3) & 1) << 3);

    const int r0c = tid >> 2, r1c = (tid + 256) >> 2;
    const int lc = tid & 3;
    const int nk = K >> 5;

    auto load_stage = [&](int s, int kt) {
        const uint32_t base = sb + s * HSTAGE;
        const int k0 = kt << 5;
        const uint32_t o0 = (uint32_t)(r0c * (GPAD * 2) + lc * 16);
        const uint32_t o1 = (uint32_t)(r1c * (GPAD * 2) + lc * 16);
        const size_t ga0 = (size_t)(m0 + r0c) * K + k0 + lc * 8;
        const size_t ga1 = (size_t)(m0 + r1c) * K + k0 + lc * 8;
        const size_t gb0 = (size_t)(n0 + r0c) * K + k0 + lc * 8;
        const size_t gb1 = (size_t)(n0 + r1c) * K + k0 + lc * 8;
        cp16(base + o0,            Ah + ga0);
        cp16(base + o1,            Ah + ga1);
        cp16(base + HARR + o0,     Al + ga0);
        cp16(base + HARR + o1,     Al + ga1);
        cp16(base + 2 * HARR + o0, Bh + gb0);
        cp16(base + 2 * HARR + o1, Bh + gb1);
        asm volatile("cp.async.commit_group;" ::: "memory");
    };

    float acc[2][8][4] = {};
    load_stage(0, 0);

#pragma unroll 1
    for (int kt = 0; kt < nk; kt++) {
        const int cur = kt & 1;
        __syncthreads();
        if (kt + 1 < nk) {
            load_stage(cur ^ 1, kt + 1);
            asm volatile("cp.async.wait_group 1;" ::: "memory");
        } else {
            asm volatile("cp.async.wait_group 0;" ::: "memory");
        }
        __syncthreads();

        const uint32_t bAh = sb + cur * HSTAGE;
        const uint32_t bAl = bAh + HARR;
        const uint32_t bBh = bAh + 2 * HARR;

#pragma unroll
        for (int kk = 0; kk < 2; kk++) {
            uint32_t Afh[2][4], Afl[2][4];
#pragma unroll
            for (int mi = 0; mi < 2; mi++) {
                uint32_t off = (uint32_t)(((wm * 32 + mi * 16) * GPAD + kk * 16 + la) << 1);
                ldsm4(Afh[mi], bAh + off);
                ldsm4(Afl[mi], bAl + off);
            }
            uint32_t Bfh[8][2];
#pragma unroll
            for (int ni = 0; ni < 4; ni++) {
                uint32_t t4[4];
                uint32_t off = (uint32_t)(((wn * 64 + ni * 16) * GPAD + kk * 16 + lb) << 1);
                ldsm4(t4, bBh + off);
                Bfh[2 * ni][0] = t4[0]; Bfh[2 * ni][1] = t4[1];
                Bfh[2 * ni + 1][0] = t4[2]; Bfh[2 * ni + 1][1] = t4[3];
            }
#pragma unroll
            for (int mi = 0; mi < 2; mi++)
#pragma unroll
                for (int nj = 0; nj < 8; nj++) {
                    mma_f16(acc[mi][nj], Afh[mi], Bfh[nj]);
                    mma_f16(acc[mi][nj], Afl[mi], Bfh[nj]);
                }
        }
    }

    const int g = lane >> 2, t = lane & 3;
#pragma unroll
    for (int mi = 0; mi < 2; mi++) {
        int r = m0 + wm * 32 + mi * 16 + g;
#pragma unroll
        for (int nj = 0; nj < 8; nj++) {
            int c = n0 + wn * 64 + nj * 8 + t * 2;
            if (SPLIT_OUT) {
                uint32_t hh, ll;
                split2h(acc[mi][nj][0], acc[mi][nj][1], hh, ll);
                __stcs(reinterpret_cast<uint32_t*>(Ch + (size_t)r * N + c), hh);
                __stcs(reinterpret_cast<uint32_t*>(Cl + (size_t)r * N + c), ll);
                split2h(acc[mi][nj][2], acc[mi][nj][3], hh, ll);
                __stcs(reinterpret_cast<uint32_t*>(Ch + (size_t)(r + 8) * N + c), hh);
                __stcs(reinterpret_cast<uint32_t*>(Cl + (size_t)(r + 8) * N + c), ll);
            } else {
                __stcs(reinterpret_cast<float2*>(C + (size_t)r * N + c),
                       make_float2(acc[mi][nj][0], acc[mi][nj][1]));
                __stcs(reinterpret_cast<float2*>(C + (size_t)(r + 8) * N + c),
                       make_float2(acc[mi][nj][2], acc[mi][nj][3]));
            }
        }
    }
}

// ---------------- flash attention: 128-row q-tiles, double-buffered KV -----
// fp16 hi/lo operands, 3-term split mma, fp32 online softmax.
#define APAD 136
#define KARR (64 * APAD * 2)
#define ATTN_SMEM ((2 * 128 + 8 * 64) * APAD * 2)  // 208896 B

__global__ __launch_bounds__(256) void attn_kernel(const __half* __restrict__ qh,
                                                   const __half* __restrict__ ql,
                                                   __half* __restrict__ ath,
                                                   __half* __restrict__ atl)
{
    extern __shared__ __half smA[];
    __half* sQh = smA;
    __half* sQl = sQh + 128 * APAD;
    const uint32_t QhB = cvta_s(sQh), QlB = cvta_s(sQl);
    const uint32_t KVB = cvta_s(sQl + 128 * APAD);

    const int tid = threadIdx.x, lane = tid & 31, warp = tid >> 5;
    const int bq = gridDim.x - 1 - blockIdx.x;    // heavy tiles first
    const int h = blockIdx.y;
    const int q0 = bq * 128;
    const int nkb = 2 * (bq + 1);
    const float slope = (h < 32) ? exp2f(-0.25f * (float)(h + 1))
                                 : exp2f(-0.125f * (float)(2 * (h - 32) + 1));
    const float scale = 0.08838834764831845f;

#pragma unroll
    for (int j = 0; j < 8; j++) {
        int c = tid + j * 256;
        int row = c >> 4, col8 = c & 15;
        uint32_t off = (uint32_t)((row * APAD + col8 * 8) * 2);
        size_t gq = (size_t)(q0 + row) * QKVN + h * 128 + col8 * 8;
        cp16(QhB + off, qh + gq);
        cp16(QlB + off, ql + gq);
    }

    auto load_kv = [&](int buf, int kb) {
        const uint32_t base = KVB + (uint32_t)buf * (4 * KARR);
#pragma unroll
        for (int j = 0; j < 4; j++) {
            int c = tid + j * 256;
            int row = c >> 4, col8 = c & 15;
            uint32_t off = (uint32_t)((row * APAD + col8 * 8) * 2);
            size_t gk = (size_t)(kb * 64 + row) * QKVN + HID + h * 128 + col8 * 8;
            size_t gv = gk + HID;
            cp16(base + off,            qh + gk);
            cp16(base + KARR + off,     ql + gk);
            cp16(base + 2 * KARR + off, qh + gv);
            cp16(base + 3 * KARR + off, ql + gv);
        }
        asm volatile("cp.async.commit_group;" ::: "memory");
    };

    load_kv(0, 0);

    float m0 = -1e30f, m1 = -1e30f, l0 = 0.f, l1 = 0.f;
    float o[16][4] = {};

    const int qm = warp * 16;
    const int g = lane >> 2, t = lane & 3;
    const int la = (lane & 15) * APAD + ((lane >> 4) << 3);
    const int lb = (((lane >> 4) << 3) + (lane & 7)) * APAD + (((lane >> 3) & 1) << 3);
    const int lv = ((((lane >> 3) & 1) << 3) + (lane & 7)) * APAD + ((lane >> 4) << 3);
    const int qpos0 = q0 + qm + g, qpos1 = qpos0 + 8;

#pragma unroll 1
    for (int kb = 0; kb < nkb; kb++) {
        const int cur = kb & 1;
        __syncthreads();
        if (kb + 1 < nkb) {
            load_kv(cur ^ 1, kb + 1);
            asm volatile("cp.async.wait_group 1;" ::: "memory");
        } else {
            asm volatile("cp.async.wait_group 0;" ::: "memory");
        }
        __syncthreads();

        const uint32_t KhB = KVB + (uint32_t)cur * (4 * KARR);
        const uint32_t KlB = KhB + KARR;
        const uint32_t VhB = KhB + 2 * KARR;
        const uint32_t VlB = KhB + 3 * KARR;

        float sc[8][4];
#pragma unroll
        for (int i = 0; i < 8; i++)
#pragma unroll
            for (int j = 0; j < 4; j++) sc[i][j] = 0.f;

#pragma unroll
        for (int kc = 0; kc < 8; kc++) {
            uint32_t qfh[4], qfl[4];
            ldsm4(qfh, QhB + (uint32_t)((qm * APAD + kc * 16 + la) << 1));
            ldsm4(qfl, QlB + (uint32_t)((qm * APAD + kc * 16 + la) << 1));
#pragma unroll
            for (int np = 0; np < 4; np++) {
                uint32_t th[4], tl[4];
                uint32_t off = (uint32_t)(((np * 16) * APAD + kc * 16 + lb) << 1);
                ldsm4(th, KhB + off);
                ldsm4(tl, KlB + off);
                uint32_t bh0[2] = {th[0], th[1]}, bh1[2] = {th[2], th[3]};
                uint32_t bl0[2] = {tl[0], tl[1]}, bl1[2] = {tl[2], tl[3]};
                mma_f16(sc[2 * np],     qfh, bh0);
                mma_f16(sc[2 * np],     qfh, bl0);
                mma_f16(sc[2 * np],     qfl, bh0);
                mma_f16(sc[2 * np + 1], qfh, bh1);
                mma_f16(sc[2 * np + 1], qfh, bl1);
                mma_f16(sc[2 * np + 1], qfl, bh1);
            }
        }

        float mt0 = -1e30f, mt1 = -1e30f;
#pragma unroll
        for (int nt = 0; nt < 8; nt++) {
#pragma unroll
            for (int c = 0; c < 2; c++) {
                int kv = kb * 64 + nt * 8 + t * 2 + c;
                float s0 = (kv <= qpos0) ? fmaf(sc[nt][c], scale, -slope * (float)(qpos0 - kv)) : -1e30f;
                float s1 = (kv <= qpos1) ? fmaf(sc[nt][2 + c], scale, -slope * (float)(qpos1 - kv)) : -1e30f;
                sc[nt][c] = s0; sc[nt][2 + c] = s1;
                mt0 = fmaxf(mt0, s0); mt1 = fmaxf(mt1, s1);
            }
        }
        mt0 = fmaxf(mt0, __shfl_xor_sync(0xffffffffu, mt0, 1));
        mt0 = fmaxf(mt0, __shfl_xor_sync(0xffffffffu, mt0, 2));
        mt1 = fmaxf(mt1, __shfl_xor_sync(0xffffffffu, mt1, 1));
        mt1 = fmaxf(mt1, __shfl_xor_sync(0xffffffffu, mt1, 2));
        float mn0 = fmaxf(m0, mt0), mn1 = fmaxf(m1, mt1);
        float f0 = __expf(m0 - mn0), f1 = __expf(m1 - mn1);
        m0 = mn0; m1 = mn1;

        float s0 = 0.f, s1 = 0.f;
#pragma unroll
        for (int nt = 0; nt < 8; nt++) {
            float p0 = __expf(sc[nt][0] - m0), p1 = __expf(sc[nt][1] - m0);
            float p2 = __expf(sc[nt][2] - m1), p3 = __expf(sc[nt][3] - m1);
            sc[nt][0] = p0; sc[nt][1] = p1; sc[nt][2] = p2; sc[nt][3] = p3;
            s0 += p0 + p1; s1 += p2 + p3;
        }
        s0 += __shfl_xor_sync(0xffffffffu, s0, 1);
        s0 += __shfl_xor_sync(0xffffffffu, s0, 2);
        s1 += __shfl_xor_sync(0xffffffffu, s1, 1);
        s1 += __shfl_xor_sync(0xffffffffu, s1, 2);
        l0 = l0 * f0 + s0;
        l1 = l1 * f1 + s1;
#pragma unroll
        for (int db = 0; db < 16; db++) {
            o[db][0] *= f0; o[db][1] *= f0; o[db][2] *= f1; o[db][3] *= f1;
        }

#pragma unroll
        for (int kc2 = 0; kc2 < 4; kc2++) {
            uint32_t ph2[4], pl2[4];
            split2h(sc[2 * kc2][0],     sc[2 * kc2][1],     ph2[0], pl2[0]);
            split2h(sc[2 * kc2][2],     sc[2 * kc2][3],     ph2[1], pl2[1]);
            split2h(sc[2 * kc2 + 1][0], sc[2 * kc2 + 1][1], ph2[2], pl2[2]);
            split2h(sc[2 * kc2 + 1][2], sc[2 * kc2 + 1][3], ph2[3], pl2[3]);
#pragma unroll
            for (int d16 = 0; d16 < 8; d16++) {
                uint32_t vh[4], vl[4];
                uint32_t off = (uint32_t)((kc2 * 16 * APAD + d16 * 16 + lv) << 1);
                ldsm4t(vh, VhB + off);
                ldsm4t(vl, VlB + off);
                uint32_t bh0[2] = {vh[0], vh[1]}, bh1[2] = {vh[2], vh[3]};
                uint32_t bl0[2] = {vl[0], vl[1]}, bl1[2] = {vl[2], vl[3]};
                mma_f16(o[2 * d16],     ph2, bh0);
                mma_f16(o[2 * d16],     ph2, bl0);
                mma_f16(o[2 * d16],     pl2, bh0);
                mma_f16(o[2 * d16 + 1], ph2, bh1);
                mma_f16(o[2 * d16 + 1], ph2, bl1);
                mma_f16(o[2 * d16 + 1], pl2, bh1);
            }
        }
    }

    float inv0 = 1.f / l0, inv1 = 1.f / l1;
#pragma unroll
    for (int db = 0; db < 16; db++) {
        int col = h * 128 + db * 8 + t * 2;
        int r0 = q0 + qm + g;
        uint32_t hh, ll;
        split2h(o[db][0] * inv0, o[db][1] * inv0, hh, ll);
        __stcs(reinterpret_cast<uint32_t*>(ath + (size_t)r0 * HID + col), hh);
        __stcs(reinterpret_cast<uint32_t*>(atl + (size_t)r0 * HID + col), ll);
        split2h(o[db][2] * inv1, o[db][3] * inv1, hh, ll);
        __stcs(reinterpret_cast<uint32_t*>(ath + (size_t)(r0 + 8) * HID + col), hh);
        __stcs(reinterpret_cast<uint32_t*>(atl + (size_t)(r0 + 8) * HID + col), ll);
    }
}

// ---------------------------------------------------------------------------
extern "C" void kernel_launch(void* const* d_in, const int* in_sizes, int n_in,
                              void* d_out, int out_size) {
    const float* hs = (const float*)d_in[0];   // [1,2048,5120]
    const float* wp = (const float*)d_in[1];   // [15360,5120]
    const float* wo = (const float*)d_in[2];   // [5120,5120]
    float* out = (float*)d_out;                // [1,2048,5120]

    __half *qkh, *qkl, *hsh, *hsl, *wph, *woh, *ath, *atl;
    cudaGetSymbolAddress((void**)&qkh, g_qk_h);
    cudaGetSymbolAddress((void**)&qkl, g_qk_l);
    cudaGetSymbolAddress((void**)&hsh, g_hs_h);
    cudaGetSymbolAddress((void**)&hsl, g_hs_l);
    cudaGetSymbolAddress((void**)&wph, g_wp_h);
    cudaGetSymbolAddress((void**)&woh, g_wo_h);
    cudaGetSymbolAddress((void**)&ath, g_at_h);
    cudaGetSymbolAddress((void**)&atl, g_at_l);

    // prepass splits
    {
        int n4 = SEQ * HID / 4;
        split_h2_kernel<<<(n4 + 255) / 256, 256>>>((const float4*)hs, (uint2*)hsh, (uint2*)hsl, n4);
        n4 = QKVN * HID / 4;
        split_h16_kernel<<<(n4 + 255) / 256, 256>>>((const float4*)wp, (uint2*)wph, n4);
        n4 = HID * HID / 4;
        split_h16_kernel<<<(n4 + 255) / 256, 256>>>((const float4*)wo, (uint2*)woh, n4);
    }

    cudaFuncSetAttribute(gemm_h2_kernel<true>, cudaFuncAttributeMaxDynamicSharedMemorySize, G2_SMEM);
    cudaFuncSetAttribute(gemm_h2_kernel<false>, cudaFuncAttributeMaxDynamicSharedMemorySize, G2_SMEM);
    cudaFuncSetAttribute(attn_kernel, cudaFuncAttributeMaxDynamicSharedMemorySize, ATTN_SMEM);

    // QKV projection (fp16 2-term) -> split fp16 [2048,15360]
    gemm_h2_kernel<true><<<dim3(SEQ / 128, QKVN / 128), 256, G2_SMEM>>>(
        hsh, hsl, wph, nullptr, qkh, qkl, QKVN, HID);

    // attention (fp16 hi/lo, 3-term; writes fp16 hi/lo)
    attn_kernel<<<dim3(SEQ / 128, 40), 256, ATTN_SMEM>>>(qkh, qkl, ath, atl);

    // o_proj (fp16 2-term) -> fp32 out
    gemm_h2_kernel<false><<<dim3(SEQ / 128, HID / 128), 256, G2_SMEM>>>(
        ath, atl, woh, out, nullptr, nullptr, HID, HID);
}

// round 9
// speedup vs baseline: 1.8972x; 1.0553x over previous
#include <cuda_runtime.h>
#include <cuda_bf16.h>
#include <cuda_fp16.h>
#include <cstdint>

#define SEQ  2048
#define HID  5120
#define QKVN 15360

// ---------------- scratch (device globals; allocation-free) ----------------
__device__ __align__(256) __half g_qk_h[SEQ * QKVN];   // qkv hi fp16
__device__ __align__(256) __half g_qk_l[SEQ * QKVN];   // qkv lo (only Q cols used)
__device__ __align__(256) __half g_hs_h[SEQ * HID];
__device__ __align__(256) __half g_hs_l[SEQ * HID];
__device__ __align__(256) __half g_wp_h[QKVN * HID];   // w_pack hi only
__device__ __align__(256) __half g_wo_h[HID * HID];    // w_o hi only
__device__ __align__(256) __half g_at_h[SEQ * HID];    // attn out fp16 hi
__device__ __align__(256) __half g_at_l[SEQ * HID];    // attn out fp16 lo

// ---------------- helpers ----------------
__device__ __forceinline__ uint32_t cvta_s(const void* p) {
    return (uint32_t)__cvta_generic_to_shared(p);
}
__device__ __forceinline__ void split2h(float f0, float f1, uint32_t& h, uint32_t& l) {
    __half h0 = __float2half_rn(f0), h1 = __float2half_rn(f1);
    float r0 = f0 - __half2float(h0), r1 = f1 - __half2float(h1);
    __half e0 = __float2half_rn(r0), e1 = __float2half_rn(r1);
    h = (uint32_t)__half_as_ushort(h0) | ((uint32_t)__half_as_ushort(h1) << 16);
    l = (uint32_t)__half_as_ushort(e0) | ((uint32_t)__half_as_ushort(e1) << 16);
}
__device__ __forceinline__ void ldsm4(uint32_t r[4], uint32_t a) {
    asm volatile("ldmatrix.sync.aligned.m8n8.x4.shared.b16 {%0,%1,%2,%3}, [%4];"
                 : "=r"(r[0]), "=r"(r[1]), "=r"(r[2]), "=r"(r[3]) : "r"(a));
}
__device__ __forceinline__ void ldsm4t(uint32_t r[4], uint32_t a) {
    asm volatile("ldmatrix.sync.aligned.m8n8.x4.trans.shared.b16 {%0,%1,%2,%3}, [%4];"
                 : "=r"(r[0]), "=r"(r[1]), "=r"(r[2]), "=r"(r[3]) : "r"(a));
}
__device__ __forceinline__ void mma_f16(float d[4], const uint32_t a[4], const uint32_t b[2]) {
    asm volatile("mma.sync.aligned.m16n8k16.row.col.f32.f16.f16.f32 "
                 "{%0,%1,%2,%3}, {%4,%5,%6,%7}, {%8,%9}, {%0,%1,%2,%3};"
                 : "+f"(d[0]), "+f"(d[1]), "+f"(d[2]), "+f"(d[3])
                 : "r"(a[0]), "r"(a[1]), "r"(a[2]), "r"(a[3]), "r"(b[0]), "r"(b[1]));
}
__device__ __forceinline__ void cp16(uint32_t dst, const void* src) {
    asm volatile("cp.async.cg.shared.global [%0], [%1], 16;" :: "r"(dst), "l"(src));
}

// ---------------- prepasses ----------------
__global__ __launch_bounds__(256) void split_h2_kernel(const float4* __restrict__ src,
                                                       uint2* __restrict__ hi,
                                                       uint2* __restrict__ lo, int n4) {
    int i = blockIdx.x * blockDim.x + threadIdx.x;
    if (i >= n4) return;
    float4 v = src[i];
    uint32_t h01, l01, h23, l23;
    split2h(v.x, v.y, h01, l01);
    split2h(v.z, v.w, h23, l23);
    hi[i] = make_uint2(h01, h23);
    lo[i] = make_uint2(l01, l23);
}
__global__ __launch_bounds__(256) void split_h16_kernel(const float4* __restrict__ src,
                                                        uint2* __restrict__ hi, int n4) {
    int i = blockIdx.x * blockDim.x + threadIdx.x;
    if (i >= n4) return;
    float4 v = src[i];
    __half2 a = __floats2half2_rn(v.x, v.y);
    __half2 b = __floats2half2_rn(v.z, v.w);
    hi[i] = make_uint2(*reinterpret_cast<uint32_t*>(&a), *reinterpret_cast<uint32_t*>(&b));
}

// ---------------- GEMM (fp16, 2-term): C = (Ah+Al) * Bh^T ------------------
// BM=128, BN=128, BK=32, 2 stages, 2 CTAs/SM. 8 warps 4(m)x2(n).
// SPLIT_OUT: write fp16 hi always; write lo only for tiles with n0 < loLimit.
#define GPAD 40
#define HARR 10240                            // 128*GPAD*2 bytes per array
#define HSTAGE (3 * HARR)                     // Ah, Al, Bh = 30720
#define G2_SMEM (2 * HSTAGE)                  // 61440

template <bool SPLIT_OUT>
__global__ __launch_bounds__(256, 2) void gemm_h2_kernel(
    const __half* __restrict__ Ah, const __half* __restrict__ Al,
    const __half* __restrict__ Bh, float* __restrict__ C,
    __half* __restrict__ Ch, __half* __restrict__ Cl, int N, int K, int loLimit)
{
    extern __shared__ char smem[];
    const uint32_t sb = cvta_s(smem);

    const int tid = threadIdx.x, warp = tid >> 5, lane = tid & 31;
    const int m0 = blockIdx.x * 128;
    const int n0 = blockIdx.y * 128;

    const int wm = warp >> 1, wn = warp & 1;
    const int la = (lane & 15) * GPAD + ((lane >> 4) << 3);
    const int lb = (((lane >> 4) << 3) + (lane & 7)) * GPAD + (((lane >> 3) & 1) << 3);

    const int r0c = tid >> 2, r1c = (tid + 256) >> 2;
    const int lc = tid & 3;
    const int nk = K >> 5;

    auto load_stage = [&](int s, int kt) {
        const uint32_t base = sb + s * HSTAGE;
        const int k0 = kt << 5;
        const uint32_t o0 = (uint32_t)(r0c * (GPAD * 2) + lc * 16);
        const uint32_t o1 = (uint32_t)(r1c * (GPAD * 2) + lc * 16);
        const size_t ga0 = (size_t)(m0 + r0c) * K + k0 + lc * 8;
        const size_t ga1 = (size_t)(m0 + r1c) * K + k0 + lc * 8;
        const size_t gb0 = (size_t)(n0 + r0c) * K + k0 + lc * 8;
        const size_t gb1 = (size_t)(n0 + r1c) * K + k0 + lc * 8;
        cp16(base + o0,            Ah + ga0);
        cp16(base + o1,            Ah + ga1);
        cp16(base + HARR + o0,     Al + ga0);
        cp16(base + HARR + o1,     Al + ga1);
        cp16(base + 2 * HARR + o0, Bh + gb0);
        cp16(base + 2 * HARR + o1, Bh + gb1);
        asm volatile("cp.async.commit_group;" ::: "memory");
    };

    float acc[2][8][4] = {};
    load_stage(0, 0);

#pragma unroll 1
    for (int kt = 0; kt < nk; kt++) {
        const int cur = kt & 1;
        __syncthreads();
        if (kt + 1 < nk) {
            load_stage(cur ^ 1, kt + 1);
            asm volatile("cp.async.wait_group 1;" ::: "memory");
        } else {
            asm volatile("cp.async.wait_group 0;" ::: "memory");
        }
        __syncthreads();

        const uint32_t bAh = sb + cur * HSTAGE;
        const uint32_t bAl = bAh + HARR;
        const uint32_t bBh = bAh + 2 * HARR;

#pragma unroll
        for (int kk = 0; kk < 2; kk++) {
            uint32_t Afh[2][4], Afl[2][4];
#pragma unroll
            for (int mi = 0; mi < 2; mi++) {
                uint32_t off = (uint32_t)(((wm * 32 + mi * 16) * GPAD + kk * 16 + la) << 1);
                ldsm4(Afh[mi], bAh + off);
                ldsm4(Afl[mi], bAl + off);
            }
            uint32_t Bfh[8][2];
#pragma unroll
            for (int ni = 0; ni < 4; ni++) {
                uint32_t t4[4];
                uint32_t off = (uint32_t)(((wn * 64 + ni * 16) * GPAD + kk * 16 + lb) << 1);
                ldsm4(t4, bBh + off);
                Bfh[2 * ni][0] = t4[0]; Bfh[2 * ni][1] = t4[1];
                Bfh[2 * ni + 1][0] = t4[2]; Bfh[2 * ni + 1][1] = t4[3];
            }
#pragma unroll
            for (int mi = 0; mi < 2; mi++)
#pragma unroll
                for (int nj = 0; nj < 8; nj++) {
                    mma_f16(acc[mi][nj], Afh[mi], Bfh[nj]);
                    mma_f16(acc[mi][nj], Afl[mi], Bfh[nj]);
                }
        }
    }

    const int g = lane >> 2, t = lane & 3;
    const bool wlo = SPLIT_OUT && (n0 < loLimit);
#pragma unroll
    for (int mi = 0; mi < 2; mi++) {
        int r = m0 + wm * 32 + mi * 16 + g;
#pragma unroll
        for (int nj = 0; nj < 8; nj++) {
            int c = n0 + wn * 64 + nj * 8 + t * 2;
            if (SPLIT_OUT) {
                uint32_t hh, ll;
                split2h(acc[mi][nj][0], acc[mi][nj][1], hh, ll);
                __stcs(reinterpret_cast<uint32_t*>(Ch + (size_t)r * N + c), hh);
                if (wlo) __stcs(reinterpret_cast<uint32_t*>(Cl + (size_t)r * N + c), ll);
                split2h(acc[mi][nj][2], acc[mi][nj][3], hh, ll);
                __stcs(reinterpret_cast<uint32_t*>(Ch + (size_t)(r + 8) * N + c), hh);
                if (wlo) __stcs(reinterpret_cast<uint32_t*>(Cl + (size_t)(r + 8) * N + c), ll);
            } else {
                __stcs(reinterpret_cast<float2*>(C + (size_t)r * N + c),
                       make_float2(acc[mi][nj][0], acc[mi][nj][1]));
                __stcs(reinterpret_cast<float2*>(C + (size_t)(r + 8) * N + c),
                       make_float2(acc[mi][nj][2], acc[mi][nj][3]));
            }
        }
    }
}

// ---------------- flash attention: 128-row q tiles, 2-term fp16 ------------
// QK: Qh*Kh + Ql*Kh. PV: Ph*Vh + Pl*Vh. fp32 online softmax.
#define APAD 136
#define KARR (64 * APAD * 2)
#define ATTN_SMEM ((2 * 128 + 4 * 64) * APAD * 2)   // 139264 B

__global__ __launch_bounds__(256) void attn_kernel(const __half* __restrict__ qh,
                                                   const __half* __restrict__ ql,
                                                   __half* __restrict__ ath,
                                                   __half* __restrict__ atl)
{
    extern __shared__ __half smA[];
    __half* sQh = smA;
    __half* sQl = sQh + 128 * APAD;
    const uint32_t QhB = cvta_s(sQh), QlB = cvta_s(sQl);
    const uint32_t KVB = cvta_s(sQl + 128 * APAD);

    const int tid = threadIdx.x, lane = tid & 31, warp = tid >> 5;
    const int bq = gridDim.x - 1 - blockIdx.x;    // heavy tiles first
    const int h = blockIdx.y;
    const int q0 = bq * 128;
    const int nkb = 2 * (bq + 1);
    const float slope = (h < 32) ? exp2f(-0.25f * (float)(h + 1))
                                 : exp2f(-0.125f * (float)(2 * (h - 32) + 1));
    const float scale = 0.08838834764831845f;

#pragma unroll
    for (int j = 0; j < 8; j++) {
        int c = tid + j * 256;
        int row = c >> 4, col8 = c & 15;
        uint32_t off = (uint32_t)((row * APAD + col8 * 8) * 2);
        size_t gq = (size_t)(q0 + row) * QKVN + h * 128 + col8 * 8;
        cp16(QhB + off, qh + gq);
        cp16(QlB + off, ql + gq);
    }

    auto load_kv = [&](int buf, int kb) {
        const uint32_t base = KVB + (uint32_t)buf * (2 * KARR);
#pragma unroll
        for (int j = 0; j < 4; j++) {
            int c = tid + j * 256;
            int row = c >> 4, col8 = c & 15;
            uint32_t off = (uint32_t)((row * APAD + col8 * 8) * 2);
            size_t gk = (size_t)(kb * 64 + row) * QKVN + HID + h * 128 + col8 * 8;
            size_t gv = gk + HID;
            cp16(base + off,        qh + gk);
            cp16(base + KARR + off, qh + gv);
        }
        asm volatile("cp.async.commit_group;" ::: "memory");
    };

    load_kv(0, 0);

    float m0 = -1e30f, m1 = -1e30f, l0 = 0.f, l1 = 0.f;
    float o[16][4] = {};

    const int qm = warp * 16;
    const int g = lane >> 2, t = lane & 3;
    const int la = (lane & 15) * APAD + ((lane >> 4) << 3);
    const int lb = (((lane >> 4) << 3) + (lane & 7)) * APAD + (((lane >> 3) & 1) << 3);
    const int lv = ((((lane >> 3) & 1) << 3) + (lane & 7)) * APAD + ((lane >> 4) << 3);
    const int qpos0 = q0 + qm + g, qpos1 = qpos0 + 8;

#pragma unroll 1
    for (int kb = 0; kb < nkb; kb++) {
        const int cur = kb & 1;
        __syncthreads();
        if (kb + 1 < nkb) {
            load_kv(cur ^ 1, kb + 1);
            asm volatile("cp.async.wait_group 1;" ::: "memory");
        } else {
            asm volatile("cp.async.wait_group 0;" ::: "memory");
        }
        __syncthreads();

        const uint32_t KhB = KVB + (uint32_t)cur * (2 * KARR);
        const uint32_t VhB = KhB + KARR;

        float sc[8][4];
#pragma unroll
        for (int i = 0; i < 8; i++)
#pragma unroll
            for (int j = 0; j < 4; j++) sc[i][j] = 0.f;

#pragma unroll
        for (int kc = 0; kc < 8; kc++) {
            uint32_t qfh[4], qfl[4];
            ldsm4(qfh, QhB + (uint32_t)((qm * APAD + kc * 16 + la) << 1));
            ldsm4(qfl, QlB + (uint32_t)((qm * APAD + kc * 16 + la) << 1));
#pragma unroll
            for (int np = 0; np < 4; np++) {
                uint32_t th[4];
                uint32_t off = (uint32_t)(((np * 16) * APAD + kc * 16 + lb) << 1);
                ldsm4(th, KhB + off);
                uint32_t bh0[2] = {th[0], th[1]}, bh1[2] = {th[2], th[3]};
                mma_f16(sc[2 * np],     qfh, bh0);
                mma_f16(sc[2 * np],     qfl, bh0);
                mma_f16(sc[2 * np + 1], qfh, bh1);
                mma_f16(sc[2 * np + 1], qfl, bh1);
            }
        }

        float mt0 = -1e30f, mt1 = -1e30f;
#pragma unroll
        for (int nt = 0; nt < 8; nt++) {
#pragma unroll
            for (int c = 0; c < 2; c++) {
                int kv = kb * 64 + nt * 8 + t * 2 + c;
                float s0 = (kv <= qpos0) ? fmaf(sc[nt][c], scale, -slope * (float)(qpos0 - kv)) : -1e30f;
                float s1 = (kv <= qpos1) ? fmaf(sc[nt][2 + c], scale, -slope * (float)(qpos1 - kv)) : -1e30f;
                sc[nt][c] = s0; sc[nt][2 + c] = s1;
                mt0 = fmaxf(mt0, s0); mt1 = fmaxf(mt1, s1);
            }
        }
        mt0 = fmaxf(mt0, __shfl_xor_sync(0xffffffffu, mt0, 1));
        mt0 = fmaxf(mt0, __shfl_xor_sync(0xffffffffu, mt0, 2));
        mt1 = fmaxf(mt1, __shfl_xor_sync(0xffffffffu, mt1, 1));
        mt1 = fmaxf(mt1, __shfl_xor_sync(0xffffffffu, mt1, 2));
        float mn0 = fmaxf(m0, mt0), mn1 = fmaxf(m1, mt1);
        float f0 = __expf(m0 - mn0), f1 = __expf(m1 - mn1);
        m0 = mn0; m1 = mn1;

        float s0 = 0.f, s1 = 0.f;
#pragma unroll
        for (int nt = 0; nt < 8; nt++) {
            float p0 = __expf(sc[nt][0] - m0), p1 = __expf(sc[nt][1] - m0);
            float p2 = __expf(sc[nt][2] - m1), p3 = __expf(sc[nt][3] - m1);
            sc[nt][0] = p0; sc[nt][1] = p1; sc[nt][2] = p2; sc[nt][3] = p3;
            s0 += p0 + p1; s1 += p2 + p3;
        }
        s0 += __shfl_xor_sync(0xffffffffu, s0, 1);
        s0 += __shfl_xor_sync(0xffffffffu, s0, 2);
        s1 += __shfl_xor_sync(0xffffffffu, s1, 1);
        s1 += __shfl_xor_sync(0xffffffffu, s1, 2);
        l0 = l0 * f0 + s0;
        l1 = l1 * f1 + s1;
#pragma unroll
        for (int db = 0; db < 16; db++) {
            o[db][0] *= f0; o[db][1] *= f0; o[db][2] *= f1; o[db][3] *= f1;
        }

#pragma unroll
        for (int kc2 = 0; kc2 < 4; kc2++) {
            uint32_t ph2[4], pl2[4];
            split2h(sc[2 * kc2][0],     sc[2 * kc2][1],     ph2[0], pl2[0]);
            split2h(sc[2 * kc2][2],     sc[2 * kc2][3],     ph2[1], pl2[1]);
            split2h(sc[2 * kc2 + 1][0], sc[2 * kc2 + 1][1], ph2[2], pl2[2]);
            split2h(sc[2 * kc2 + 1][2], sc[2 * kc2 + 1][3], ph2[3], pl2[3]);
#pragma unroll
            for (int d16 = 0; d16 < 8; d16++) {
                uint32_t vh[4];
                uint32_t off = (uint32_t)((kc2 * 16 * APAD + d16 * 16 + lv) << 1);
                ldsm4t(vh, VhB + off);
                uint32_t bh0[2] = {vh[0], vh[1]}, bh1[2] = {vh[2], vh[3]};
                mma_f16(o[2 * d16],     ph2, bh0);
                mma_f16(o[2 * d16],     pl2, bh0);
                mma_f16(o[2 * d16 + 1], ph2, bh1);
                mma_f16(o[2 * d16 + 1], pl2, bh1);
            }
        }
    }

    float inv0 = 1.f / l0, inv1 = 1.f / l1;
#pragma unroll
    for (int db = 0; db < 16; db++) {
        int col = h * 128 + db * 8 + t * 2;
        int r0 = q0 + qm + g;
        uint32_t hh, ll;
        split2h(o[db][0] * inv0, o[db][1] * inv0, hh, ll);
        __stcs(reinterpret_cast<uint32_t*>(ath + (size_t)r0 * HID + col), hh);
        __stcs(reinterpret_cast<uint32_t*>(atl + (size_t)r0 * HID + col), ll);
        split2h(o[db][2] * inv1, o[db][3] * inv1, hh, ll);
        __stcs(reinterpret_cast<uint32_t*>(ath + (size_t)(r0 + 8) * HID + col), hh);
        __stcs(reinterpret_cast<uint32_t*>(atl + (size_t)(r0 + 8) * HID + col), ll);
    }
}

// ---------------------------------------------------------------------------
extern "C" void kernel_launch(void* const* d_in, const int* in_sizes, int n_in,
                              void* d_out, int out_size) {
    const float* hs = (const float*)d_in[0];   // [1,2048,5120]
    const float* wp = (const float*)d_in[1];   // [15360,5120]
    const float* wo = (const float*)d_in[2];   // [5120,5120]
    float* out = (float*)d_out;                // [1,2048,5120]

    __half *qkh, *qkl, *hsh, *hsl, *wph, *woh, *ath, *atl;
    cudaGetSymbolAddress((void**)&qkh, g_qk_h);
    cudaGetSymbolAddress((void**)&qkl, g_qk_l);
    cudaGetSymbolAddress((void**)&hsh, g_hs_h);
    cudaGetSymbolAddress((void**)&hsl, g_hs_l);
    cudaGetSymbolAddress((void**)&wph, g_wp_h);
    cudaGetSymbolAddress((void**)&woh, g_wo_h);
    cudaGetSymbolAddress((void**)&ath, g_at_h);
    cudaGetSymbolAddress((void**)&atl, g_at_l);

    // prepass splits
    {
        int n4 = SEQ * HID / 4;
        split_h2_kernel<<<(n4 + 255) / 256, 256>>>((const float4*)hs, (uint2*)hsh, (uint2*)hsl, n4);
        n4 = QKVN * HID / 4;
        split_h16_kernel<<<(n4 + 255) / 256, 256>>>((const float4*)wp, (uint2*)wph, n4);
        n4 = HID * HID / 4;
        split_h16_kernel<<<(n4 + 255) / 256, 256>>>((const float4*)wo, (uint2*)woh, n4);
    }

    cudaFuncSetAttribute(gemm_h2_kernel<true>, cudaFuncAttributeMaxDynamicSharedMemorySize, G2_SMEM);
    cudaFuncSetAttribute(gemm_h2_kernel<false>, cudaFuncAttributeMaxDynamicSharedMemorySize, G2_SMEM);
    cudaFuncSetAttribute(attn_kernel, cudaFuncAttributeMaxDynamicSharedMemorySize, ATTN_SMEM);

    // QKV projection (fp16 2-term) -> fp16 hi [2048,15360]; lo only for Q cols
    gemm_h2_kernel<true><<<dim3(SEQ / 128, QKVN / 128), 256, G2_SMEM>>>(
        hsh, hsl, wph, nullptr, qkh, qkl, QKVN, HID, HID);

    // attention (2-term fp16; writes fp16 hi/lo)
    attn_kernel<<<dim3(SEQ / 128, 40), 256, ATTN_SMEM>>>(qkh, qkl, ath, atl);

    // o_proj (fp16 2-term) -> fp32 out
    gemm_h2_kernel<false><<<dim3(SEQ / 128, HID / 128), 256, G2_SMEM>>>(
        ath, atl, woh, out, nullptr, nullptr, HID, HID, 0);
}

// round 10
// speedup vs baseline: 2.1077x; 1.1110x over previous
#include <cuda_runtime.h>
#include <cuda_bf16.h>
#include <cuda_fp16.h>
#include <cstdint>

#define SEQ  2048
#define HID  5120
#define QKVN 15360

// ---------------- scratch (device globals; allocation-free) ----------------
__device__ __align__(256) __half g_qk_h[SEQ * QKVN];   // qkv hi fp16
__device__ __align__(256) __half g_qk_l[SEQ * QKVN];   // qkv lo (only Q cols used)
__device__ __align__(256) __half g_hs_h[SEQ * HID];
__device__ __align__(256) __half g_hs_l[SEQ * HID];
__device__ __align__(256) __half g_wp_h[QKVN * HID];   // w_pack hi only
__device__ __align__(256) __half g_wo_h[HID * HID];    // w_o hi only
__device__ __align__(256) __half g_at_h[SEQ * HID];    // attn out fp16 (hi only)

// ---------------- helpers ----------------
__device__ __forceinline__ uint32_t cvta_s(const void* p) {
    return (uint32_t)__cvta_generic_to_shared(p);
}
__device__ __forceinline__ void split2h(float f0, float f1, uint32_t& h, uint32_t& l) {
    __half h0 = __float2half_rn(f0), h1 = __float2half_rn(f1);
    float r0 = f0 - __half2float(h0), r1 = f1 - __half2float(h1);
    __half e0 = __float2half_rn(r0), e1 = __float2half_rn(r1);
    h = (uint32_t)__half_as_ushort(h0) | ((uint32_t)__half_as_ushort(h1) << 16);
    l = (uint32_t)__half_as_ushort(e0) | ((uint32_t)__half_as_ushort(e1) << 16);
}
__device__ __forceinline__ uint32_t pack2h(float f0, float f1) {
    __half2 v = __floats2half2_rn(f0, f1);
    return *reinterpret_cast<uint32_t*>(&v);
}
__device__ __forceinline__ void ldsm4(uint32_t r[4], uint32_t a) {
    asm volatile("ldmatrix.sync.aligned.m8n8.x4.shared.b16 {%0,%1,%2,%3}, [%4];"
                 : "=r"(r[0]), "=r"(r[1]), "=r"(r[2]), "=r"(r[3]) : "r"(a));
}
__device__ __forceinline__ void ldsm4t(uint32_t r[4], uint32_t a) {
    asm volatile("ldmatrix.sync.aligned.m8n8.x4.trans.shared.b16 {%0,%1,%2,%3}, [%4];"
                 : "=r"(r[0]), "=r"(r[1]), "=r"(r[2]), "=r"(r[3]) : "r"(a));
}
__device__ __forceinline__ void mma_f16(float d[4], const uint32_t a[4], const uint32_t b[2]) {
    asm volatile("mma.sync.aligned.m16n8k16.row.col.f32.f16.f16.f32 "
                 "{%0,%1,%2,%3}, {%4,%5,%6,%7}, {%8,%9}, {%0,%1,%2,%3};"
                 : "+f"(d[0]), "+f"(d[1]), "+f"(d[2]), "+f"(d[3])
                 : "r"(a[0]), "r"(a[1]), "r"(a[2]), "r"(a[3]), "r"(b[0]), "r"(b[1]));
}
__device__ __forceinline__ void cp16(uint32_t dst, const void* src) {
    asm volatile("cp.async.cg.shared.global [%0], [%1], 16;" :: "r"(dst), "l"(src));
}

// ---------------- prepasses ----------------
__global__ __launch_bounds__(256) void split_h2_kernel(const float4* __restrict__ src,
                                                       uint2* __restrict__ hi,
                                                       uint2* __restrict__ lo, int n4) {
    int i = blockIdx.x * blockDim.x + threadIdx.x;
    if (i >= n4) return;
    float4 v = src[i];
    uint32_t h01, l01, h23, l23;
    split2h(v.x, v.y, h01, l01);
    split2h(v.z, v.w, h23, l23);
    hi[i] = make_uint2(h01, h23);
    lo[i] = make_uint2(l01, l23);
}
__global__ __launch_bounds__(256) void split_h16_kernel(const float4* __restrict__ src,
                                                        uint2* __restrict__ hi, int n4) {
    int i = blockIdx.x * blockDim.x + threadIdx.x;
    if (i >= n4) return;
    float4 v = src[i];
    hi[i] = make_uint2(pack2h(v.x, v.y), pack2h(v.z, v.w));
}

// ---------------- GEMM (fp16): C = (Ah [+ Al]) * Bh^T ----------------------
// BM=128, BN=128, BK=32, 2 stages, 2 CTAs/SM. 8 warps 4(m)x2(n).
// NTERMS=2: A split hi+lo. NTERMS=1: plain fp16 A.
// SPLIT_OUT: write fp16 hi always; lo only for tiles with n0 < loLimit.
#define GPAD 40
#define HARR 10240                            // 128*GPAD*2 bytes per array

template <int NTERMS, bool SPLIT_OUT>
__global__ __launch_bounds__(256, 2) void gemm_h_kernel(
    const __half* __restrict__ Ah, const __half* __restrict__ Al,
    const __half* __restrict__ Bh, float* __restrict__ C,
    __half* __restrict__ Ch, __half* __restrict__ Cl, int N, int K, int loLimit)
{
    constexpr uint32_t HSTAGE = (NTERMS + 1) * HARR;
    extern __shared__ char smem[];
    const uint32_t sb = cvta_s(smem);

    const int tid = threadIdx.x, warp = tid >> 5, lane = tid & 31;
    const int m0 = blockIdx.x * 128;
    const int n0 = blockIdx.y * 128;

    const int wm = warp >> 1, wn = warp & 1;
    const int la = (lane & 15) * GPAD + ((lane >> 4) << 3);
    const int lb = (((lane >> 4) << 3) + (lane & 7)) * GPAD + (((lane >> 3) & 1) << 3);

    const int r0c = tid >> 2, r1c = (tid + 256) >> 2;
    const int lc = tid & 3;
    const int nk = K >> 5;

    auto load_stage = [&](int s, int kt) {
        const uint32_t base = sb + s * HSTAGE;
        const int k0 = kt << 5;
        const uint32_t o0 = (uint32_t)(r0c * (GPAD * 2) + lc * 16);
        const uint32_t o1 = (uint32_t)(r1c * (GPAD * 2) + lc * 16);
        const size_t ga0 = (size_t)(m0 + r0c) * K + k0 + lc * 8;
        const size_t ga1 = (size_t)(m0 + r1c) * K + k0 + lc * 8;
        const size_t gb0 = (size_t)(n0 + r0c) * K + k0 + lc * 8;
        const size_t gb1 = (size_t)(n0 + r1c) * K + k0 + lc * 8;
        cp16(base + o0, Ah + ga0);
        cp16(base + o1, Ah + ga1);
        if (NTERMS == 2) {
            cp16(base + HARR + o0, Al + ga0);
            cp16(base + HARR + o1, Al + ga1);
        }
        cp16(base + (NTERMS)*HARR + o0, Bh + gb0);
        cp16(base + (NTERMS)*HARR + o1, Bh + gb1);
        asm volatile("cp.async.commit_group;" ::: "memory");
    };

    float acc[2][8][4] = {};
    load_stage(0, 0);

#pragma unroll 1
    for (int kt = 0; kt < nk; kt++) {
        const int cur = kt & 1;
        __syncthreads();
        if (kt + 1 < nk) {
            load_stage(cur ^ 1, kt + 1);
            asm volatile("cp.async.wait_group 1;" ::: "memory");
        } else {
            asm volatile("cp.async.wait_group 0;" ::: "memory");
        }
        __syncthreads();

        const uint32_t bAh = sb + cur * HSTAGE;
        const uint32_t bAl = bAh + HARR;
        const uint32_t bBh = bAh + (NTERMS)*HARR;

#pragma unroll
        for (int kk = 0; kk < 2; kk++) {
            uint32_t Afh[2][4], Afl[2][4];
#pragma unroll
            for (int mi = 0; mi < 2; mi++) {
                uint32_t off = (uint32_t)(((wm * 32 + mi * 16) * GPAD + kk * 16 + la) << 1);
                ldsm4(Afh[mi], bAh + off);
                if (NTERMS == 2) ldsm4(Afl[mi], bAl + off);
            }
            uint32_t Bfh[8][2];
#pragma unroll
            for (int ni = 0; ni < 4; ni++) {
                uint32_t t4[4];
                uint32_t off = (uint32_t)(((wn * 64 + ni * 16) * GPAD + kk * 16 + lb) << 1);
                ldsm4(t4, bBh + off);
                Bfh[2 * ni][0] = t4[0]; Bfh[2 * ni][1] = t4[1];
                Bfh[2 * ni + 1][0] = t4[2]; Bfh[2 * ni + 1][1] = t4[3];
            }
#pragma unroll
            for (int mi = 0; mi < 2; mi++)
#pragma unroll
                for (int nj = 0; nj < 8; nj++) {
                    mma_f16(acc[mi][nj], Afh[mi], Bfh[nj]);
                    if (NTERMS == 2) mma_f16(acc[mi][nj], Afl[mi], Bfh[nj]);
                }
        }
    }

    const int g = lane >> 2, t = lane & 3;
    const bool wlo = SPLIT_OUT && (n0 < loLimit);
#pragma unroll
    for (int mi = 0; mi < 2; mi++) {
        int r = m0 + wm * 32 + mi * 16 + g;
#pragma unroll
        for (int nj = 0; nj < 8; nj++) {
            int c = n0 + wn * 64 + nj * 8 + t * 2;
            if (SPLIT_OUT) {
                uint32_t hh, ll;
                split2h(acc[mi][nj][0], acc[mi][nj][1], hh, ll);
                __stcs(reinterpret_cast<uint32_t*>(Ch + (size_t)r * N + c), hh);
                if (wlo) __stcs(reinterpret_cast<uint32_t*>(Cl + (size_t)r * N + c), ll);
                split2h(acc[mi][nj][2], acc[mi][nj][3], hh, ll);
                __stcs(reinterpret_cast<uint32_t*>(Ch + (size_t)(r + 8) * N + c), hh);
                if (wlo) __stcs(reinterpret_cast<uint32_t*>(Cl + (size_t)(r + 8) * N + c), ll);
            } else {
                __stcs(reinterpret_cast<float2*>(C + (size_t)r * N + c),
                       make_float2(acc[mi][nj][0], acc[mi][nj][1]));
                __stcs(reinterpret_cast<float2*>(C + (size_t)(r + 8) * N + c),
                       make_float2(acc[mi][nj][2], acc[mi][nj][3]));
            }
        }
    }
}

// ---------------- flash attention: 128-row q tiles, 2-term fp16 ------------
// QK: Qh*Kh + Ql*Kh. PV: Ph*Vh + Pl*Vh. fp32 online softmax. hi-only output.
#define APAD 136
#define KARR (64 * APAD * 2)
#define ATTN_SMEM ((2 * 128 + 4 * 64) * APAD * 2)   // 139264 B

__global__ __launch_bounds__(256) void attn_kernel(const __half* __restrict__ qh,
                                                   const __half* __restrict__ ql,
                                                   __half* __restrict__ ath)
{
    extern __shared__ __half smA[];
    __half* sQh = smA;
    __half* sQl = sQh + 128 * APAD;
    const uint32_t QhB = cvta_s(sQh), QlB = cvta_s(sQl);
    const uint32_t KVB = cvta_s(sQl + 128 * APAD);

    const int tid = threadIdx.x, lane = tid & 31, warp = tid >> 5;
    const int bq = gridDim.x - 1 - blockIdx.x;    // heavy tiles first
    const int h = blockIdx.y;
    const int q0 = bq * 128;
    const int nkb = 2 * (bq + 1);
    const float slope = (h < 32) ? exp2f(-0.25f * (float)(h + 1))
                                 : exp2f(-0.125f * (float)(2 * (h - 32) + 1));
    const float scale = 0.08838834764831845f;

#pragma unroll
    for (int j = 0; j < 8; j++) {
        int c = tid + j * 256;
        int row = c >> 4, col8 = c & 15;
        uint32_t off = (uint32_t)((row * APAD + col8 * 8) * 2);
        size_t gq = (size_t)(q0 + row) * QKVN + h * 128 + col8 * 8;
        cp16(QhB + off, qh + gq);
        cp16(QlB + off, ql + gq);
    }

    auto load_kv = [&](int buf, int kb) {
        const uint32_t base = KVB + (uint32_t)buf * (2 * KARR);
#pragma unroll
        for (int j = 0; j < 4; j++) {
            int c = tid + j * 256;
            int row = c >> 4, col8 = c & 15;
            uint32_t off = (uint32_t)((row * APAD + col8 * 8) * 2);
            size_t gk = (size_t)(kb * 64 + row) * QKVN + HID + h * 128 + col8 * 8;
            size_t gv = gk + HID;
            cp16(base + off,        qh + gk);
            cp16(base + KARR + off, qh + gv);
        }
        asm volatile("cp.async.commit_group;" ::: "memory");
    };

    load_kv(0, 0);

    float m0 = -1e30f, m1 = -1e30f, l0 = 0.f, l1 = 0.f;
    float o[16][4] = {};

    const int qm = warp * 16;
    const int g = lane >> 2, t = lane & 3;
    const int la = (lane & 15) * APAD + ((lane >> 4) << 3);
    const int lb = (((lane >> 4) << 3) + (lane & 7)) * APAD + (((lane >> 3) & 1) << 3);
    const int lv = ((((lane >> 3) & 1) << 3) + (lane & 7)) * APAD + ((lane >> 4) << 3);
    const int qpos0 = q0 + qm + g, qpos1 = qpos0 + 8;

#pragma unroll 1
    for (int kb = 0; kb < nkb; kb++) {
        const int cur = kb & 1;
        __syncthreads();
        if (kb + 1 < nkb) {
            load_kv(cur ^ 1, kb + 1);
            asm volatile("cp.async.wait_group 1;" ::: "memory");
        } else {
            asm volatile("cp.async.wait_group 0;" ::: "memory");
        }
        __syncthreads();

        const uint32_t KhB = KVB + (uint32_t)cur * (2 * KARR);
        const uint32_t VhB = KhB + KARR;

        float sc[8][4];
#pragma unroll
        for (int i = 0; i < 8; i++)
#pragma unroll
            for (int j = 0; j < 4; j++) sc[i][j] = 0.f;

#pragma unroll
        for (int kc = 0; kc < 8; kc++) {
            uint32_t qfh[4], qfl[4];
            ldsm4(qfh, QhB + (uint32_t)((qm * APAD + kc * 16 + la) << 1));
            ldsm4(qfl, QlB + (uint32_t)((qm * APAD + kc * 16 + la) << 1));
#pragma unroll
            for (int np = 0; np < 4; np++) {
                uint32_t th[4];
                uint32_t off = (uint32_t)(((np * 16) * APAD + kc * 16 + lb) << 1);
                ldsm4(th, KhB + off);
                uint32_t bh0[2] = {th[0], th[1]}, bh1[2] = {th[2], th[3]};
                mma_f16(sc[2 * np],     qfh, bh0);
                mma_f16(sc[2 * np],     qfl, bh0);
                mma_f16(sc[2 * np + 1], qfh, bh1);
                mma_f16(sc[2 * np + 1], qfl, bh1);
            }
        }

        float mt0 = -1e30f, mt1 = -1e30f;
#pragma unroll
        for (int nt = 0; nt < 8; nt++) {
#pragma unroll
            for (int c = 0; c < 2; c++) {
                int kv = kb * 64 + nt * 8 + t * 2 + c;
                float s0 = (kv <= qpos0) ? fmaf(sc[nt][c], scale, -slope * (float)(qpos0 - kv)) : -1e30f;
                float s1 = (kv <= qpos1) ? fmaf(sc[nt][2 + c], scale, -slope * (float)(qpos1 - kv)) : -1e30f;
                sc[nt][c] = s0; sc[nt][2 + c] = s1;
                mt0 = fmaxf(mt0, s0); mt1 = fmaxf(mt1, s1);
            }
        }
        mt0 = fmaxf(mt0, __shfl_xor_sync(0xffffffffu, mt0, 1));
        mt0 = fmaxf(mt0, __shfl_xor_sync(0xffffffffu, mt0, 2));
        mt1 = fmaxf(mt1, __shfl_xor_sync(0xffffffffu, mt1, 1));
        mt1 = fmaxf(mt1, __shfl_xor_sync(0xffffffffu, mt1, 2));
        float mn0 = fmaxf(m0, mt0), mn1 = fmaxf(m1, mt1);
        float f0 = __expf(m0 - mn0), f1 = __expf(m1 - mn1);
        m0 = mn0; m1 = mn1;

        float s0 = 0.f, s1 = 0.f;
#pragma unroll
        for (int nt = 0; nt < 8; nt++) {
            float p0 = __expf(sc[nt][0] - m0), p1 = __expf(sc[nt][1] - m0);
            float p2 = __expf(sc[nt][2] - m1), p3 = __expf(sc[nt][3] - m1);
            sc[nt][0] = p0; sc[nt][1] = p1; sc[nt][2] = p2; sc[nt][3] = p3;
            s0 += p0 + p1; s1 += p2 + p3;
        }
        s0 += __shfl_xor_sync(0xffffffffu, s0, 1);
        s0 += __shfl_xor_sync(0xffffffffu, s0, 2);
        s1 += __shfl_xor_sync(0xffffffffu, s1, 1);
        s1 += __shfl_xor_sync(0xffffffffu, s1, 2);
        l0 = l0 * f0 + s0;
        l1 = l1 * f1 + s1;
#pragma unroll
        for (int db = 0; db < 16; db++) {
            o[db][0] *= f0; o[db][1] *= f0; o[db][2] *= f1; o[db][3] *= f1;
        }

#pragma unroll
        for (int kc2 = 0; kc2 < 4; kc2++) {
            uint32_t ph2[4], pl2[4];
            split2h(sc[2 * kc2][0],     sc[2 * kc2][1],     ph2[0], pl2[0]);
            split2h(sc[2 * kc2][2],     sc[2 * kc2][3],     ph2[1], pl2[1]);
            split2h(sc[2 * kc2 + 1][0], sc[2 * kc2 + 1][1], ph2[2], pl2[2]);
            split2h(sc[2 * kc2 + 1][2], sc[2 * kc2 + 1][3], ph2[3], pl2[3]);
#pragma unroll
            for (int d16 = 0; d16 < 8; d16++) {
                uint32_t vh[4];
                uint32_t off = (uint32_t)((kc2 * 16 * APAD + d16 * 16 + lv) << 1);
                ldsm4t(vh, VhB + off);
                uint32_t bh0[2] = {vh[0], vh[1]}, bh1[2] = {vh[2], vh[3]};
                mma_f16(o[2 * d16],     ph2, bh0);
                mma_f16(o[2 * d16],     pl2, bh0);
                mma_f16(o[2 * d16 + 1], ph2, bh1);
                mma_f16(o[2 * d16 + 1], pl2, bh1);
            }
        }
    }

    float inv0 = 1.f / l0, inv1 = 1.f / l1;
#pragma unroll
    for (int db = 0; db < 16; db++) {
        int col = h * 128 + db * 8 + t * 2;
        int r0 = q0 + qm + g;
        __stcs(reinterpret_cast<uint32_t*>(ath + (size_t)r0 * HID + col),
               pack2h(o[db][0] * inv0, o[db][1] * inv0));
        __stcs(reinterpret_cast<uint32_t*>(ath + (size_t)(r0 + 8) * HID + col),
               pack2h(o[db][2] * inv1, o[db][3] * inv1));
    }
}

// ---------------------------------------------------------------------------
extern "C" void kernel_launch(void* const* d_in, const int* in_sizes, int n_in,
                              void* d_out, int out_size) {
    const float* hs = (const float*)d_in[0];   // [1,2048,5120]
    const float* wp = (const float*)d_in[1];   // [15360,5120]
    const float* wo = (const float*)d_in[2];   // [5120,5120]
    float* out = (float*)d_out;                // [1,2048,5120]

    __half *qkh, *qkl, *hsh, *hsl, *wph, *woh, *ath;
    cudaGetSymbolAddress((void**)&qkh, g_qk_h);
    cudaGetSymbolAddress((void**)&qkl, g_qk_l);
    cudaGetSymbolAddress((void**)&hsh, g_hs_h);
    cudaGetSymbolAddress((void**)&hsl, g_hs_l);
    cudaGetSymbolAddress((void**)&wph, g_wp_h);
    cudaGetSymbolAddress((void**)&woh, g_wo_h);
    cudaGetSymbolAddress((void**)&ath, g_at_h);

    // prepass splits
    {
        int n4 = SEQ * HID / 4;
        split_h2_kernel<<<(n4 + 255) / 256, 256>>>((const float4*)hs, (uint2*)hsh, (uint2*)hsl, n4);
        n4 = QKVN * HID / 4;
        split_h16_kernel<<<(n4 + 255) / 256, 256>>>((const float4*)wp, (uint2*)wph, n4);
        n4 = HID * HID / 4;
        split_h16_kernel<<<(n4 + 255) / 256, 256>>>((const float4*)wo, (uint2*)woh, n4);
    }

    const int smem2 = 2 * 3 * HARR;  // 2-term stages
    const int smem1 = 2 * 2 * HARR;  // 1-term stages
    cudaFuncSetAttribute(gemm_h_kernel<2, true>, cudaFuncAttributeMaxDynamicSharedMemorySize, smem2);
    cudaFuncSetAttribute(gemm_h_kernel<1, false>, cudaFuncAttributeMaxDynamicSharedMemorySize, smem1);
    cudaFuncSetAttribute(attn_kernel, cudaFuncAttributeMaxDynamicSharedMemorySize, ATTN_SMEM);

    // QKV projection (fp16 2-term) -> fp16 hi [2048,15360]; lo only for Q cols
    gemm_h_kernel<2, true><<<dim3(SEQ / 128, QKVN / 128), 256, smem2>>>(
        hsh, hsl, wph, nullptr, qkh, qkl, QKVN, HID, HID);

    // attention (2-term fp16; writes fp16 hi only)
    attn_kernel<<<dim3(SEQ / 128, 40), 256, ATTN_SMEM>>>(qkh, qkl, ath);

    // o_proj (fp16 1-term) -> fp32 out
    gemm_h_kernel<1, false><<<dim3(SEQ / 128, HID / 128), 256, smem1>>>(
        ath, nullptr, woh, out, nullptr, nullptr, HID, HID, 0);
}

// round 11
// speedup vs baseline: 2.4196x; 1.1479x over previous
#include <cuda_runtime.h>
#include <cuda_bf16.h>
#include <cuda_fp16.h>
#include <cstdint>

#define SEQ  2048
#define HID  5120
#define QKVN 15360

// ---------------- scratch (device globals; allocation-free) ----------------
__device__ __align__(256) __half g_qk_h[SEQ * QKVN];   // qkv hi fp16
__device__ __align__(256) __half g_qk_l[SEQ * HID];    // q lo only
__device__ __align__(256) __half g_hs_h[SEQ * HID];
__device__ __align__(256) __half g_hs_l[SEQ * HID];
__device__ __align__(256) __half g_wp_h[QKVN * HID];   // w_pack hi only
__device__ __align__(256) __half g_wo_h[HID * HID];    // w_o hi only
__device__ __align__(256) __half g_at_h[SEQ * HID];    // attn out fp16 (hi only)

// ---------------- helpers ----------------
__device__ __forceinline__ uint32_t cvta_s(const void* p) {
    return (uint32_t)__cvta_generic_to_shared(p);
}
__device__ __forceinline__ void split2h(float f0, float f1, uint32_t& h, uint32_t& l) {
    __half h0 = __float2half_rn(f0), h1 = __float2half_rn(f1);
    float r0 = f0 - __half2float(h0), r1 = f1 - __half2float(h1);
    __half e0 = __float2half_rn(r0), e1 = __float2half_rn(r1);
    h = (uint32_t)__half_as_ushort(h0) | ((uint32_t)__half_as_ushort(h1) << 16);
    l = (uint32_t)__half_as_ushort(e0) | ((uint32_t)__half_as_ushort(e1) << 16);
}
__device__ __forceinline__ uint32_t pack2h(float f0, float f1) {
    __half2 v = __floats2half2_rn(f0, f1);
    return *reinterpret_cast<uint32_t*>(&v);
}
__device__ __forceinline__ void ldsm4(uint32_t r[4], uint32_t a) {
    asm volatile("ldmatrix.sync.aligned.m8n8.x4.shared.b16 {%0,%1,%2,%3}, [%4];"
                 : "=r"(r[0]), "=r"(r[1]), "=r"(r[2]), "=r"(r[3]) : "r"(a));
}
__device__ __forceinline__ void ldsm4t(uint32_t r[4], uint32_t a) {
    asm volatile("ldmatrix.sync.aligned.m8n8.x4.trans.shared.b16 {%0,%1,%2,%3}, [%4];"
                 : "=r"(r[0]), "=r"(r[1]), "=r"(r[2]), "=r"(r[3]) : "r"(a));
}
__device__ __forceinline__ void mma_f16(float d[4], const uint32_t a[4], const uint32_t b[2]) {
    asm volatile("mma.sync.aligned.m16n8k16.row.col.f32.f16.f16.f32 "
                 "{%0,%1,%2,%3}, {%4,%5,%6,%7}, {%8,%9}, {%0,%1,%2,%3};"
                 : "+f"(d[0]), "+f"(d[1]), "+f"(d[2]), "+f"(d[3])
                 : "r"(a[0]), "r"(a[1]), "r"(a[2]), "r"(a[3]), "r"(b[0]), "r"(b[1]));
}
__device__ __forceinline__ void cp16(uint32_t dst, const void* src) {
    asm volatile("cp.async.cg.shared.global [%0], [%1], 16;" :: "r"(dst), "l"(src));
}

// ---------------- prepasses ----------------
__global__ __launch_bounds__(256) void split_h2_kernel(const float4* __restrict__ src,
                                                       uint2* __restrict__ hi,
                                                       uint2* __restrict__ lo, int n4) {
    int i = blockIdx.x * blockDim.x + threadIdx.x;
    if (i >= n4) return;
    float4 v = src[i];
    uint32_t h01, l01, h23, l23;
    split2h(v.x, v.y, h01, l01);
    split2h(v.z, v.w, h23, l23);
    hi[i] = make_uint2(h01, h23);
    lo[i] = make_uint2(l01, l23);
}
__global__ __launch_bounds__(256) void split_h16_kernel(const float4* __restrict__ src,
                                                        uint2* __restrict__ hi, int n4) {
    int i = blockIdx.x * blockDim.x + threadIdx.x;
    if (i >= n4) return;
    float4 v = src[i];
    hi[i] = make_uint2(pack2h(v.x, v.y), pack2h(v.z, v.w));
}

// ---------------- GEMM (fp16): C = (Ah [+ Al]) * Bh^T ----------------------
// BM=128, BN=128, BK=32, 2 stages, 2 CTAs/SM. 8 warps 4(m)x2(n).
// NTERMS=2: A split hi+lo. NTERMS=1: plain fp16 A.
// SPLIT_OUT: write fp16 hi (Ch); lo (Cl) only if WRITE_LO.
#define GPAD 40
#define HARR 10240                            // 128*GPAD*2 bytes per array

template <int NTERMS, bool SPLIT_OUT, bool WRITE_LO>
__global__ __launch_bounds__(256, 2) void gemm_h_kernel(
    const __half* __restrict__ Ah, const __half* __restrict__ Al,
    const __half* __restrict__ Bh, float* __restrict__ C,
    __half* __restrict__ Ch, __half* __restrict__ Cl, int N, int K)
{
    constexpr uint32_t HSTAGE = (NTERMS + 1) * HARR;
    extern __shared__ char smem[];
    const uint32_t sb = cvta_s(smem);

    const int tid = threadIdx.x, warp = tid >> 5, lane = tid & 31;
    const int m0 = blockIdx.x * 128;
    const int n0 = blockIdx.y * 128;

    const int wm = warp >> 1, wn = warp & 1;
    const int la = (lane & 15) * GPAD + ((lane >> 4) << 3);
    const int lb = (((lane >> 4) << 3) + (lane & 7)) * GPAD + (((lane >> 3) & 1) << 3);

    const int r0c = tid >> 2, r1c = (tid + 256) >> 2;
    const int lc = tid & 3;
    const int nk = K >> 5;

    auto load_stage = [&](int s, int kt) {
        const uint32_t base = sb + s * HSTAGE;
        const int k0 = kt << 5;
        const uint32_t o0 = (uint32_t)(r0c * (GPAD * 2) + lc * 16);
        const uint32_t o1 = (uint32_t)(r1c * (GPAD * 2) + lc * 16);
        const size_t ga0 = (size_t)(m0 + r0c) * K + k0 + lc * 8;
        const size_t ga1 = (size_t)(m0 + r1c) * K + k0 + lc * 8;
        const size_t gb0 = (size_t)(n0 + r0c) * K + k0 + lc * 8;
        const size_t gb1 = (size_t)(n0 + r1c) * K + k0 + lc * 8;
        cp16(base + o0, Ah + ga0);
        cp16(base + o1, Ah + ga1);
        if (NTERMS == 2) {
            cp16(base + HARR + o0, Al + ga0);
            cp16(base + HARR + o1, Al + ga1);
        }
        cp16(base + (NTERMS)*HARR + o0, Bh + gb0);
        cp16(base + (NTERMS)*HARR + o1, Bh + gb1);
        asm volatile("cp.async.commit_group;" ::: "memory");
    };

    float acc[2][8][4] = {};
    load_stage(0, 0);

#pragma unroll 1
    for (int kt = 0; kt < nk; kt++) {
        const int cur = kt & 1;
        __syncthreads();
        if (kt + 1 < nk) {
            load_stage(cur ^ 1, kt + 1);
            asm volatile("cp.async.wait_group 1;" ::: "memory");
        } else {
            asm volatile("cp.async.wait_group 0;" ::: "memory");
        }
        __syncthreads();

        const uint32_t bAh = sb + cur * HSTAGE;
        const uint32_t bAl = bAh + HARR;
        const uint32_t bBh = bAh + (NTERMS)*HARR;

#pragma unroll
        for (int kk = 0; kk < 2; kk++) {
            uint32_t Afh[2][4], Afl[2][4];
#pragma unroll
            for (int mi = 0; mi < 2; mi++) {
                uint32_t off = (uint32_t)(((wm * 32 + mi * 16) * GPAD + kk * 16 + la) << 1);
                ldsm4(Afh[mi], bAh + off);
                if (NTERMS == 2) ldsm4(Afl[mi], bAl + off);
            }
            uint32_t Bfh[8][2];
#pragma unroll
            for (int ni = 0; ni < 4; ni++) {
                uint32_t t4[4];
                uint32_t off = (uint32_t)(((wn * 64 + ni * 16) * GPAD + kk * 16 + lb) << 1);
                ldsm4(t4, bBh + off);
                Bfh[2 * ni][0] = t4[0]; Bfh[2 * ni][1] = t4[1];
                Bfh[2 * ni + 1][0] = t4[2]; Bfh[2 * ni + 1][1] = t4[3];
            }
#pragma unroll
            for (int mi = 0; mi < 2; mi++)
#pragma unroll
                for (int nj = 0; nj < 8; nj++) {
                    mma_f16(acc[mi][nj], Afh[mi], Bfh[nj]);
                    if (NTERMS == 2) mma_f16(acc[mi][nj], Afl[mi], Bfh[nj]);
                }
        }
    }

    const int g = lane >> 2, t = lane & 3;
#pragma unroll
    for (int mi = 0; mi < 2; mi++) {
        int r = m0 + wm * 32 + mi * 16 + g;
#pragma unroll
        for (int nj = 0; nj < 8; nj++) {
            int c = n0 + wn * 64 + nj * 8 + t * 2;
            if (SPLIT_OUT) {
                uint32_t hh, ll;
                split2h(acc[mi][nj][0], acc[mi][nj][1], hh, ll);
                __stcs(reinterpret_cast<uint32_t*>(Ch + (size_t)r * N + c), hh);
                if (WRITE_LO) __stcs(reinterpret_cast<uint32_t*>(Cl + (size_t)r * HID + c), ll);
                split2h(acc[mi][nj][2], acc[mi][nj][3], hh, ll);
                __stcs(reinterpret_cast<uint32_t*>(Ch + (size_t)(r + 8) * N + c), hh);
                if (WRITE_LO) __stcs(reinterpret_cast<uint32_t*>(Cl + (size_t)(r + 8) * HID + c), ll);
            } else {
                __stcs(reinterpret_cast<float2*>(C + (size_t)r * N + c),
                       make_float2(acc[mi][nj][0], acc[mi][nj][1]));
                __stcs(reinterpret_cast<float2*>(C + (size_t)(r + 8) * N + c),
                       make_float2(acc[mi][nj][2], acc[mi][nj][3]));
            }
        }
    }
}

// ---------------- flash attention: 128-row q tiles, 2-term fp16 ------------
// QK: Qh*Kh + Ql*Kh. PV: Ph*Vh + Pl*Vh. fp32 online softmax. hi-only output.
#define APAD 136
#define KARR (64 * APAD * 2)
#define ATTN_SMEM ((2 * 128 + 4 * 64) * APAD * 2)   // 139264 B

__global__ __launch_bounds__(256) void attn_kernel(const __half* __restrict__ qh,
                                                   const __half* __restrict__ ql,
                                                   __half* __restrict__ ath)
{
    extern __shared__ __half smA[];
    __half* sQh = smA;
    __half* sQl = sQh + 128 * APAD;
    const uint32_t QhB = cvta_s(sQh), QlB = cvta_s(sQl);
    const uint32_t KVB = cvta_s(sQl + 128 * APAD);

    const int tid = threadIdx.x, lane = tid & 31, warp = tid >> 5;
    const int bq = gridDim.x - 1 - blockIdx.x;    // heavy tiles first
    const int h = blockIdx.y;
    const int q0 = bq * 128;
    const int nkb = 2 * (bq + 1);
    const float slope = (h < 32) ? exp2f(-0.25f * (float)(h + 1))
                                 : exp2f(-0.125f * (float)(2 * (h - 32) + 1));
    const float scale = 0.08838834764831845f;

#pragma unroll
    for (int j = 0; j < 8; j++) {
        int c = tid + j * 256;
        int row = c >> 4, col8 = c & 15;
        uint32_t off = (uint32_t)((row * APAD + col8 * 8) * 2);
        cp16(QhB + off, qh + (size_t)(q0 + row) * QKVN + h * 128 + col8 * 8);
        cp16(QlB + off, ql + (size_t)(q0 + row) * HID + h * 128 + col8 * 8);
    }

    auto load_kv = [&](int buf, int kb) {
        const uint32_t base = KVB + (uint32_t)buf * (2 * KARR);
#pragma unroll
        for (int j = 0; j < 4; j++) {
            int c = tid + j * 256;
            int row = c >> 4, col8 = c & 15;
            uint32_t off = (uint32_t)((row * APAD + col8 * 8) * 2);
            size_t gk = (size_t)(kb * 64 + row) * QKVN + HID + h * 128 + col8 * 8;
            size_t gv = gk + HID;
            cp16(base + off,        qh + gk);
            cp16(base + KARR + off, qh + gv);
        }
        asm volatile("cp.async.commit_group;" ::: "memory");
    };

    load_kv(0, 0);

    float m0 = -1e30f, m1 = -1e30f, l0 = 0.f, l1 = 0.f;
    float o[16][4] = {};

    const int qm = warp * 16;
    const int g = lane >> 2, t = lane & 3;
    const int la = (lane & 15) * APAD + ((lane >> 4) << 3);
    const int lb = (((lane >> 4) << 3) + (lane & 7)) * APAD + (((lane >> 3) & 1) << 3);
    const int lv = ((((lane >> 3) & 1) << 3) + (lane & 7)) * APAD + ((lane >> 4) << 3);
    const int qpos0 = q0 + qm + g, qpos1 = qpos0 + 8;

#pragma unroll 1
    for (int kb = 0; kb < nkb; kb++) {
        const int cur = kb & 1;
        __syncthreads();
        if (kb + 1 < nkb) {
            load_kv(cur ^ 1, kb + 1);
            asm volatile("cp.async.wait_group 1;" ::: "memory");
        } else {
            asm volatile("cp.async.wait_group 0;" ::: "memory");
        }
        __syncthreads();

        const uint32_t KhB = KVB + (uint32_t)cur * (2 * KARR);
        const uint32_t VhB = KhB + KARR;

        float sc[8][4];
#pragma unroll
        for (int i = 0; i < 8; i++)
#pragma unroll
            for (int j = 0; j < 4; j++) sc[i][j] = 0.f;

#pragma unroll
        for (int kc = 0; kc < 8; kc++) {
            uint32_t qfh[4], qfl[4];
            ldsm4(qfh, QhB + (uint32_t)((qm * APAD + kc * 16 + la) << 1));
            ldsm4(qfl, QlB + (uint32_t)((qm * APAD + kc * 16 + la) << 1));
#pragma unroll
            for (int np = 0; np < 4; np++) {
                uint32_t th[4];
                uint32_t off = (uint32_t)(((np * 16) * APAD + kc * 16 + lb) << 1);
                ldsm4(th, KhB + off);
                uint32_t bh0[2] = {th[0], th[1]}, bh1[2] = {th[2], th[3]};
                mma_f16(sc[2 * np],     qfh, bh0);
                mma_f16(sc[2 * np],     qfl, bh0);
                mma_f16(sc[2 * np + 1], qfh, bh1);
                mma_f16(sc[2 * np + 1], qfl, bh1);
            }
        }

        float mt0 = -1e30f, mt1 = -1e30f;
#pragma unroll
        for (int nt = 0; nt < 8; nt++) {
#pragma unroll
            for (int c = 0; c < 2; c++) {
                int kv = kb * 64 + nt * 8 + t * 2 + c;
                float s0 = (kv <= qpos0) ? fmaf(sc[nt][c], scale, -slope * (float)(qpos0 - kv)) : -1e30f;
                float s1 = (kv <= qpos1) ? fmaf(sc[nt][2 + c], scale, -slope * (float)(qpos1 - kv)) : -1e30f;
                sc[nt][c] = s0; sc[nt][2 + c] = s1;
                mt0 = fmaxf(mt0, s0); mt1 = fmaxf(mt1, s1);
            }
        }
        mt0 = fmaxf(mt0, __shfl_xor_sync(0xffffffffu, mt0, 1));
        mt0 = fmaxf(mt0, __shfl_xor_sync(0xffffffffu, mt0, 2));
        mt1 = fmaxf(mt1, __shfl_xor_sync(0xffffffffu, mt1, 1));
        mt1 = fmaxf(mt1, __shfl_xor_sync(0xffffffffu, mt1, 2));
        float mn0 = fmaxf(m0, mt0), mn1 = fmaxf(m1, mt1);
        float f0 = __expf(m0 - mn0), f1 = __expf(m1 - mn1);
        m0 = mn0; m1 = mn1;

        float s0 = 0.f, s1 = 0.f;
#pragma unroll
        for (int nt = 0; nt < 8; nt++) {
            float p0 = __expf(sc[nt][0] - m0), p1 = __expf(sc[nt][1] - m0);
            float p2 = __expf(sc[nt][2] - m1), p3 = __expf(sc[nt][3] - m1);
            sc[nt][0] = p0; sc[nt][1] = p1; sc[nt][2] = p2; sc[nt][3] = p3;
            s0 += p0 + p1; s1 += p2 + p3;
        }
        s0 += __shfl_xor_sync(0xffffffffu, s0, 1);
        s0 += __shfl_xor_sync(0xffffffffu, s0, 2);
        s1 += __shfl_xor_sync(0xffffffffu, s1, 1);
        s1 += __shfl_xor_sync(0xffffffffu, s1, 2);
        l0 = l0 * f0 + s0;
        l1 = l1 * f1 + s1;
#pragma unroll
        for (int db = 0; db < 16; db++) {
            o[db][0] *= f0; o[db][1] *= f0; o[db][2] *= f1; o[db][3] *= f1;
        }

#pragma unroll
        for (int kc2 = 0; kc2 < 4; kc2++) {
            uint32_t ph2[4], pl2[4];
            split2h(sc[2 * kc2][0],     sc[2 * kc2][1],     ph2[0], pl2[0]);
            split2h(sc[2 * kc2][2],     sc[2 * kc2][3],     ph2[1], pl2[1]);
            split2h(sc[2 * kc2 + 1][0], sc[2 * kc2 + 1][1], ph2[2], pl2[2]);
            split2h(sc[2 * kc2 + 1][2], sc[2 * kc2 + 1][3], ph2[3], pl2[3]);
#pragma unroll
            for (int d16 = 0; d16 < 8; d16++) {
                uint32_t vh[4];
                uint32_t off = (uint32_t)((kc2 * 16 * APAD + d16 * 16 + lv) << 1);
                ldsm4t(vh, VhB + off);
                uint32_t bh0[2] = {vh[0], vh[1]}, bh1[2] = {vh[2], vh[3]};
                mma_f16(o[2 * d16],     ph2, bh0);
                mma_f16(o[2 * d16],     pl2, bh0);
                mma_f16(o[2 * d16 + 1], ph2, bh1);
                mma_f16(o[2 * d16 + 1], pl2, bh1);
            }
        }
    }

    float inv0 = 1.f / l0, inv1 = 1.f / l1;
#pragma unroll
    for (int db = 0; db < 16; db++) {
        int col = h * 128 + db * 8 + t * 2;
        int r0 = q0 + qm + g;
        __stcs(reinterpret_cast<uint32_t*>(ath + (size_t)r0 * HID + col),
               pack2h(o[db][0] * inv0, o[db][1] * inv0));
        __stcs(reinterpret_cast<uint32_t*>(ath + (size_t)(r0 + 8) * HID + col),
               pack2h(o[db][2] * inv1, o[db][3] * inv1));
    }
}

// ---------------------------------------------------------------------------
extern "C" void kernel_launch(void* const* d_in, const int* in_sizes, int n_in,
                              void* d_out, int out_size) {
    const float* hs = (const float*)d_in[0];   // [1,2048,5120]
    const float* wp = (const float*)d_in[1];   // [15360,5120]
    const float* wo = (const float*)d_in[2];   // [5120,5120]
    float* out = (float*)d_out;                // [1,2048,5120]

    __half *qkh, *qkl, *hsh, *hsl, *wph, *woh, *ath;
    cudaGetSymbolAddress((void**)&qkh, g_qk_h);
    cudaGetSymbolAddress((void**)&qkl, g_qk_l);
    cudaGetSymbolAddress((void**)&hsh, g_hs_h);
    cudaGetSymbolAddress((void**)&hsl, g_hs_l);
    cudaGetSymbolAddress((void**)&wph, g_wp_h);
    cudaGetSymbolAddress((void**)&woh, g_wo_h);
    cudaGetSymbolAddress((void**)&ath, g_at_h);

    // prepass splits
    {
        int n4 = SEQ * HID / 4;
        split_h2_kernel<<<(n4 + 255) / 256, 256>>>((const float4*)hs, (uint2*)hsh, (uint2*)hsl, n4);
        n4 = QKVN * HID / 4;
        split_h16_kernel<<<(n4 + 255) / 256, 256>>>((const float4*)wp, (uint2*)wph, n4);
        n4 = HID * HID / 4;
        split_h16_kernel<<<(n4 + 255) / 256, 256>>>((const float4*)wo, (uint2*)woh, n4);
    }

    const int smem2 = 2 * 3 * HARR;  // 2-term stages (61440)
    const int smem1 = 2 * 2 * HARR;  // 1-term stages (40960)
    cudaFuncSetAttribute((const void*)gemm_h_kernel<2, true, true>,
                         cudaFuncAttributeMaxDynamicSharedMemorySize, smem2);
    cudaFuncSetAttribute((const void*)gemm_h_kernel<1, true, false>,
                         cudaFuncAttributeMaxDynamicSharedMemorySize, smem1);
    cudaFuncSetAttribute((const void*)gemm_h_kernel<1, false, false>,
                         cudaFuncAttributeMaxDynamicSharedMemorySize, smem1);
    cudaFuncSetAttribute((const void*)attn_kernel,
                         cudaFuncAttributeMaxDynamicSharedMemorySize, ATTN_SMEM);

    // Q projection (fp16 2-term) -> fp16 hi + lo, columns [0, 5120)
    gemm_h_kernel<2, true, true><<<dim3(SEQ / 128, HID / 128), 256, smem2>>>(
        hsh, hsl, wph, nullptr, qkh, qkl, QKVN, HID);

    // K,V projection (fp16 1-term) -> fp16 hi only, columns [5120, 15360)
    gemm_h_kernel<1, true, false><<<dim3(SEQ / 128, (QKVN - HID) / 128), 256, smem1>>>(
        hsh, nullptr, wph + (size_t)HID * HID, nullptr, qkh + HID, nullptr, QKVN, HID);

    // attention (2-term fp16 Q; K,V hi; writes fp16 hi only)
    attn_kernel<<<dim3(SEQ / 128, 40), 256, ATTN_SMEM>>>(qkh, qkl, ath);

    // o_proj (fp16 1-term) -> fp32 out
    gemm_h_kernel<1, false, false><<<dim3(SEQ / 128, HID / 128), 256, smem1>>>(
        ath, nullptr, woh, out, nullptr, nullptr, HID, HID);
}

// round 12
// speedup vs baseline: 2.9805x; 1.2318x over previous
#include <cuda_runtime.h>
#include <cuda_bf16.h>
#include <cuda_fp16.h>
#include <cstdint>

#define SEQ  2048
#define HID  5120
#define QKVN 15360

// ---------------- scratch (device globals; allocation-free) ----------------
__device__ __align__(256) __half g_qk_h[SEQ * QKVN];   // qkv fp16 (hi only)
__device__ __align__(256) __half g_hs_h[SEQ * HID];
__device__ __align__(256) __half g_wp_h[QKVN * HID];   // w_pack hi only
__device__ __align__(256) __half g_wo_h[HID * HID];    // w_o hi only
__device__ __align__(256) __half g_at_h[SEQ * HID];    // attn out fp16 (hi only)

// ---------------- helpers ----------------
__device__ __forceinline__ uint32_t cvta_s(const void* p) {
    return (uint32_t)__cvta_generic_to_shared(p);
}
__device__ __forceinline__ void split2h(float f0, float f1, uint32_t& h, uint32_t& l) {
    __half h0 = __float2half_rn(f0), h1 = __float2half_rn(f1);
    float r0 = f0 - __half2float(h0), r1 = f1 - __half2float(h1);
    __half e0 = __float2half_rn(r0), e1 = __float2half_rn(r1);
    h = (uint32_t)__half_as_ushort(h0) | ((uint32_t)__half_as_ushort(h1) << 16);
    l = (uint32_t)__half_as_ushort(e0) | ((uint32_t)__half_as_ushort(e1) << 16);
}
__device__ __forceinline__ uint32_t pack2h(float f0, float f1) {
    __half2 v = __floats2half2_rn(f0, f1);
    return *reinterpret_cast<uint32_t*>(&v);
}
__device__ __forceinline__ void ldsm4(uint32_t r[4], uint32_t a) {
    asm volatile("ldmatrix.sync.aligned.m8n8.x4.shared.b16 {%0,%1,%2,%3}, [%4];"
                 : "=r"(r[0]), "=r"(r[1]), "=r"(r[2]), "=r"(r[3]) : "r"(a));
}
__device__ __forceinline__ void ldsm4t(uint32_t r[4], uint32_t a) {
    asm volatile("ldmatrix.sync.aligned.m8n8.x4.trans.shared.b16 {%0,%1,%2,%3}, [%4];"
                 : "=r"(r[0]), "=r"(r[1]), "=r"(r[2]), "=r"(r[3]) : "r"(a));
}
__device__ __forceinline__ void mma_f16(float d[4], const uint32_t a[4], const uint32_t b[2]) {
    asm volatile("mma.sync.aligned.m16n8k16.row.col.f32.f16.f16.f32 "
                 "{%0,%1,%2,%3}, {%4,%5,%6,%7}, {%8,%9}, {%0,%1,%2,%3};"
                 : "+f"(d[0]), "+f"(d[1]), "+f"(d[2]), "+f"(d[3])
                 : "r"(a[0]), "r"(a[1]), "r"(a[2]), "r"(a[3]), "r"(b[0]), "r"(b[1]));
}
__device__ __forceinline__ void cp16(uint32_t dst, const void* src) {
    asm volatile("cp.async.cg.shared.global [%0], [%1], 16;" :: "r"(dst), "l"(src));
}

// ---------------- prepass: fp32 -> fp16 ----------------
__global__ __launch_bounds__(256) void split_h16_kernel(const float4* __restrict__ src,
                                                        uint2* __restrict__ hi, int n4) {
    int i = blockIdx.x * blockDim.x + threadIdx.x;
    if (i >= n4) return;
    float4 v = src[i];
    hi[i] = make_uint2(pack2h(v.x, v.y), pack2h(v.z, v.w));
}

// ---------------- GEMM (fp16, 1-term): C = Ah * Bh^T ------------------------
// BM=128, BN=128, BK=32, 2 stages, 2 CTAs/SM. 8 warps 4(m)x2(n).
// HALF_OUT: write fp16 (Ch); else fp32 (C).
#define GPAD 40
#define HARR 10240                            // 128*GPAD*2 bytes per array
#define HSTAGE (2 * HARR)
#define G1_SMEM (2 * HSTAGE)                  // 40960

template <bool HALF_OUT>
__global__ __launch_bounds__(256, 2) void gemm_h_kernel(
    const __half* __restrict__ Ah, const __half* __restrict__ Bh,
    float* __restrict__ C, __half* __restrict__ Ch, int N, int K)
{
    extern __shared__ char smem[];
    const uint32_t sb = cvta_s(smem);

    const int tid = threadIdx.x, warp = tid >> 5, lane = tid & 31;
    const int m0 = blockIdx.x * 128;
    const int n0 = blockIdx.y * 128;

    const int wm = warp >> 1, wn = warp & 1;
    const int la = (lane & 15) * GPAD + ((lane >> 4) << 3);
    const int lb = (((lane >> 4) << 3) + (lane & 7)) * GPAD + (((lane >> 3) & 1) << 3);

    const int r0c = tid >> 2, r1c = (tid + 256) >> 2;
    const int lc = tid & 3;
    const int nk = K >> 5;

    auto load_stage = [&](int s, int kt) {
        const uint32_t base = sb + s * HSTAGE;
        const int k0 = kt << 5;
        const uint32_t o0 = (uint32_t)(r0c * (GPAD * 2) + lc * 16);
        const uint32_t o1 = (uint32_t)(r1c * (GPAD * 2) + lc * 16);
        cp16(base + o0,        Ah + (size_t)(m0 + r0c) * K + k0 + lc * 8);
        cp16(base + o1,        Ah + (size_t)(m0 + r1c) * K + k0 + lc * 8);
        cp16(base + HARR + o0, Bh + (size_t)(n0 + r0c) * K + k0 + lc * 8);
        cp16(base + HARR + o1, Bh + (size_t)(n0 + r1c) * K + k0 + lc * 8);
        asm volatile("cp.async.commit_group;" ::: "memory");
    };

    float acc[2][8][4] = {};
    load_stage(0, 0);

#pragma unroll 1
    for (int kt = 0; kt < nk; kt++) {
        const int cur = kt & 1;
        __syncthreads();
        if (kt + 1 < nk) {
            load_stage(cur ^ 1, kt + 1);
            asm volatile("cp.async.wait_group 1;" ::: "memory");
        } else {
            asm volatile("cp.async.wait_group 0;" ::: "memory");
        }
        __syncthreads();

        const uint32_t bAh = sb + cur * HSTAGE;
        const uint32_t bBh = bAh + HARR;

#pragma unroll
        for (int kk = 0; kk < 2; kk++) {
            uint32_t Afh[2][4];
#pragma unroll
            for (int mi = 0; mi < 2; mi++) {
                uint32_t off = (uint32_t)(((wm * 32 + mi * 16) * GPAD + kk * 16 + la) << 1);
                ldsm4(Afh[mi], bAh + off);
            }
            uint32_t Bfh[8][2];
#pragma unroll
            for (int ni = 0; ni < 4; ni++) {
                uint32_t t4[4];
                uint32_t off = (uint32_t)(((wn * 64 + ni * 16) * GPAD + kk * 16 + lb) << 1);
                ldsm4(t4, bBh + off);
                Bfh[2 * ni][0] = t4[0]; Bfh[2 * ni][1] = t4[1];
                Bfh[2 * ni + 1][0] = t4[2]; Bfh[2 * ni + 1][1] = t4[3];
            }
#pragma unroll
            for (int mi = 0; mi < 2; mi++)
#pragma unroll
                for (int nj = 0; nj < 8; nj++)
                    mma_f16(acc[mi][nj], Afh[mi], Bfh[nj]);
        }
    }

    const int g = lane >> 2, t = lane & 3;
#pragma unroll
    for (int mi = 0; mi < 2; mi++) {
        int r = m0 + wm * 32 + mi * 16 + g;
#pragma unroll
        for (int nj = 0; nj < 8; nj++) {
            int c = n0 + wn * 64 + nj * 8 + t * 2;
            if (HALF_OUT) {
                __stcs(reinterpret_cast<uint32_t*>(Ch + (size_t)r * N + c),
                       pack2h(acc[mi][nj][0], acc[mi][nj][1]));
                __stcs(reinterpret_cast<uint32_t*>(Ch + (size_t)(r + 8) * N + c),
                       pack2h(acc[mi][nj][2], acc[mi][nj][3]));
            } else {
                __stcs(reinterpret_cast<float2*>(C + (size_t)r * N + c),
                       make_float2(acc[mi][nj][0], acc[mi][nj][1]));
                __stcs(reinterpret_cast<float2*>(C + (size_t)(r + 8) * N + c),
                       make_float2(acc[mi][nj][2], acc[mi][nj][3]));
            }
        }
    }
}

// ---------------- flash attention: 128-row q tiles ------------------------
// QK: Qh*Kh (1-term). PV: Ph*Vh + Pl*Vh (P split). fp32 online softmax.
#define APAD 136
#define KARR (64 * APAD * 2)
#define ATTN_SMEM ((128 + 4 * 64) * APAD * 2)   // 104448 B

__global__ __launch_bounds__(256) void attn_kernel(const __half* __restrict__ qh,
                                                   __half* __restrict__ ath)
{
    extern __shared__ __half smA[];
    __half* sQh = smA;
    const uint32_t QhB = cvta_s(sQh);
    const uint32_t KVB = cvta_s(sQh + 128 * APAD);

    const int tid = threadIdx.x, lane = tid & 31, warp = tid >> 5;
    const int bq = gridDim.x - 1 - blockIdx.x;    // heavy tiles first
    const int h = blockIdx.y;
    const int q0 = bq * 128;
    const int nkb = 2 * (bq + 1);
    const float slope = (h < 32) ? exp2f(-0.25f * (float)(h + 1))
                                 : exp2f(-0.125f * (float)(2 * (h - 32) + 1));
    const float scale = 0.08838834764831845f;

#pragma unroll
    for (int j = 0; j < 8; j++) {
        int c = tid + j * 256;
        int row = c >> 4, col8 = c & 15;
        uint32_t off = (uint32_t)((row * APAD + col8 * 8) * 2);
        cp16(QhB + off, qh + (size_t)(q0 + row) * QKVN + h * 128 + col8 * 8);
    }

    auto load_kv = [&](int buf, int kb) {
        const uint32_t base = KVB + (uint32_t)buf * (2 * KARR);
#pragma unroll
        for (int j = 0; j < 4; j++) {
            int c = tid + j * 256;
            int row = c >> 4, col8 = c & 15;
            uint32_t off = (uint32_t)((row * APAD + col8 * 8) * 2);
            size_t gk = (size_t)(kb * 64 + row) * QKVN + HID + h * 128 + col8 * 8;
            cp16(base + off,        qh + gk);
            cp16(base + KARR + off, qh + gk + HID);
        }
        asm volatile("cp.async.commit_group;" ::: "memory");
    };

    load_kv(0, 0);

    float m0 = -1e30f, m1 = -1e30f, l0 = 0.f, l1 = 0.f;
    float o[16][4] = {};

    const int qm = warp * 16;
    const int g = lane >> 2, t = lane & 3;
    const int la = (lane & 15) * APAD + ((lane >> 4) << 3);
    const int lb = (((lane >> 4) << 3) + (lane & 7)) * APAD + (((lane >> 3) & 1) << 3);
    const int lv = ((((lane >> 3) & 1) << 3) + (lane & 7)) * APAD + ((lane >> 4) << 3);
    const int qpos0 = q0 + qm + g, qpos1 = qpos0 + 8;

#pragma unroll 1
    for (int kb = 0; kb < nkb; kb++) {
        const int cur = kb & 1;
        __syncthreads();
        if (kb + 1 < nkb) {
            load_kv(cur ^ 1, kb + 1);
            asm volatile("cp.async.wait_group 1;" ::: "memory");
        } else {
            asm volatile("cp.async.wait_group 0;" ::: "memory");
        }
        __syncthreads();

        const uint32_t KhB = KVB + (uint32_t)cur * (2 * KARR);
        const uint32_t VhB = KhB + KARR;

        float sc[8][4];
#pragma unroll
        for (int i = 0; i < 8; i++)
#pragma unroll
            for (int j = 0; j < 4; j++) sc[i][j] = 0.f;

#pragma unroll
        for (int kc = 0; kc < 8; kc++) {
            uint32_t qfh[4];
            ldsm4(qfh, QhB + (uint32_t)((qm * APAD + kc * 16 + la) << 1));
#pragma unroll
            for (int np = 0; np < 4; np++) {
                uint32_t th[4];
                uint32_t off = (uint32_t)(((np * 16) * APAD + kc * 16 + lb) << 1);
                ldsm4(th, KhB + off);
                uint32_t bh0[2] = {th[0], th[1]}, bh1[2] = {th[2], th[3]};
                mma_f16(sc[2 * np],     qfh, bh0);
                mma_f16(sc[2 * np + 1], qfh, bh1);
            }
        }

        float mt0 = -1e30f, mt1 = -1e30f;
#pragma unroll
        for (int nt = 0; nt < 8; nt++) {
#pragma unroll
            for (int c = 0; c < 2; c++) {
                int kv = kb * 64 + nt * 8 + t * 2 + c;
                float s0 = (kv <= qpos0) ? fmaf(sc[nt][c], scale, -slope * (float)(qpos0 - kv)) : -1e30f;
                float s1 = (kv <= qpos1) ? fmaf(sc[nt][2 + c], scale, -slope * (float)(qpos1 - kv)) : -1e30f;
                sc[nt][c] = s0; sc[nt][2 + c] = s1;
                mt0 = fmaxf(mt0, s0); mt1 = fmaxf(mt1, s1);
            }
        }
        mt0 = fmaxf(mt0, __shfl_xor_sync(0xffffffffu, mt0, 1));
        mt0 = fmaxf(mt0, __shfl_xor_sync(0xffffffffu, mt0, 2));
        mt1 = fmaxf(mt1, __shfl_xor_sync(0xffffffffu, mt1, 1));
        mt1 = fmaxf(mt1, __shfl_xor_sync(0xffffffffu, mt1, 2));
        float mn0 = fmaxf(m0, mt0), mn1 = fmaxf(m1, mt1);
        float f0 = __expf(m0 - mn0), f1 = __expf(m1 - mn1);
        m0 = mn0; m1 = mn1;

        float s0 = 0.f, s1 = 0.f;
#pragma unroll
        for (int nt = 0; nt < 8; nt++) {
            float p0 = __expf(sc[nt][0] - m0), p1 = __expf(sc[nt][1] - m0);
            float p2 = __expf(sc[nt][2] - m1), p3 = __expf(sc[nt][3] - m1);
            sc[nt][0] = p0; sc[nt][1] = p1; sc[nt][2] = p2; sc[nt][3] = p3;
            s0 += p0 + p1; s1 += p2 + p3;
        }
        s0 += __shfl_xor_sync(0xffffffffu, s0, 1);
        s0 += __shfl_xor_sync(0xffffffffu, s0, 2);
        s1 += __shfl_xor_sync(0xffffffffu, s1, 1);
        s1 += __shfl_xor_sync(0xffffffffu, s1, 2);
        l0 = l0 * f0 + s0;
        l1 = l1 * f1 + s1;
#pragma unroll
        for (int db = 0; db < 16; db++) {
            o[db][0] *= f0; o[db][1] *= f0; o[db][2] *= f1; o[db][3] *= f1;
        }

#pragma unroll
        for (int kc2 = 0; kc2 < 4; kc2++) {
            uint32_t ph2[4], pl2[4];
            split2h(sc[2 * kc2][0],     sc[2 * kc2][1],     ph2[0], pl2[0]);
            split2h(sc[2 * kc2][2],     sc[2 * kc2][3],     ph2[1], pl2[1]);
            split2h(sc[2 * kc2 + 1][0], sc[2 * kc2 + 1][1], ph2[2], pl2[2]);
            split2h(sc[2 * kc2 + 1][2], sc[2 * kc2 + 1][3], ph2[3], pl2[3]);
#pragma unroll
            for (int d16 = 0; d16 < 8; d16++) {
                uint32_t vh[4];
                uint32_t off = (uint32_t)((kc2 * 16 * APAD + d16 * 16 + lv) << 1);
                ldsm4t(vh, VhB + off);
                uint32_t bh0[2] = {vh[0], vh[1]}, bh1[2] = {vh[2], vh[3]};
                mma_f16(o[2 * d16],     ph2, bh0);
                mma_f16(o[2 * d16],     pl2, bh0);
                mma_f16(o[2 * d16 + 1], ph2, bh1);
                mma_f16(o[2 * d16 + 1], pl2, bh1);
            }
        }
    }

    float inv0 = 1.f / l0, inv1 = 1.f / l1;
#pragma unroll
    for (int db = 0; db < 16; db++) {
        int col = h * 128 + db * 8 + t * 2;
        int r0 = q0 + qm + g;
        __stcs(reinterpret_cast<uint32_t*>(ath + (size_t)r0 * HID + col),
               pack2h(o[db][0] * inv0, o[db][1] * inv0));
        __stcs(reinterpret_cast<uint32_t*>(ath + (size_t)(r0 + 8) * HID + col),
               pack2h(o[db][2] * inv1, o[db][3] * inv1));
    }
}

// ---------------------------------------------------------------------------
extern "C" void kernel_launch(void* const* d_in, const int* in_sizes, int n_in,
                              void* d_out, int out_size) {
    const float* hs = (const float*)d_in[0];   // [1,2048,5120]
    const float* wp = (const float*)d_in[1];   // [15360,5120]
    const float* wo = (const float*)d_in[2];   // [5120,5120]
    float* out = (float*)d_out;                // [1,2048,5120]

    __half *qkh, *hsh, *wph, *woh, *ath;
    cudaGetSymbolAddress((void**)&qkh, g_qk_h);
    cudaGetSymbolAddress((void**)&hsh, g_hs_h);
    cudaGetSymbolAddress((void**)&wph, g_wp_h);
    cudaGetSymbolAddress((void**)&woh, g_wo_h);
    cudaGetSymbolAddress((void**)&ath, g_at_h);

    // prepasses: fp32 -> fp16
    {
        int n4 = SEQ * HID / 4;
        split_h16_kernel<<<(n4 + 255) / 256, 256>>>((const float4*)hs, (uint2*)hsh, n4);
        n4 = QKVN * HID / 4;
        split_h16_kernel<<<(n4 + 255) / 256, 256>>>((const float4*)wp, (uint2*)wph, n4);
        n4 = HID * HID / 4;
        split_h16_kernel<<<(n4 + 255) / 256, 256>>>((const float4*)wo, (uint2*)woh, n4);
    }

    cudaFuncSetAttribute((const void*)gemm_h_kernel<true>,
                         cudaFuncAttributeMaxDynamicSharedMemorySize, G1_SMEM);
    cudaFuncSetAttribute((const void*)gemm_h_kernel<false>,
                         cudaFuncAttributeMaxDynamicSharedMemorySize, G1_SMEM);
    cudaFuncSetAttribute((const void*)attn_kernel,
                         cudaFuncAttributeMaxDynamicSharedMemorySize, ATTN_SMEM);

    // QKV projection (fp16 1-term) -> fp16 [2048,15360], single launch
    gemm_h_kernel<true><<<dim3(SEQ / 128, QKVN / 128), 256, G1_SMEM>>>(
        hsh, wph, nullptr, qkh, QKVN, HID);

    // attention (QK 1-term; PV 2-term P-split; writes fp16)
    attn_kernel<<<dim3(SEQ / 128, 40), 256, ATTN_SMEM>>>(qkh, ath);

    // o_proj (fp16 1-term) -> fp32 out
    gemm_h_kernel<false><<<dim3(SEQ / 128, HID / 128), 256, G1_SMEM>>>(
        ath, woh, out, nullptr, HID, HID);
}

// round 13
// speedup vs baseline: 3.2982x; 1.1066x over previous
#include <cuda_runtime.h>
#include <cuda_bf16.h>
#include <cuda_fp16.h>
#include <cstdint>

#define SEQ  2048
#define HID  5120
#define QKVN 15360

// ---------------- scratch (device globals; allocation-free) ----------------
__device__ __align__(256) __half g_qk_h[SEQ * QKVN];   // qkv fp16 (hi only)
__device__ __align__(256) __half g_hs_h[SEQ * HID];
__device__ __align__(256) __half g_wp_h[QKVN * HID];   // w_pack hi only
__device__ __align__(256) __half g_wo_h[HID * HID];    // w_o hi only
__device__ __align__(256) __half g_at_h[SEQ * HID];    // attn out fp16 (hi only)

// ---------------- helpers ----------------
__device__ __forceinline__ uint32_t cvta_s(const void* p) {
    return (uint32_t)__cvta_generic_to_shared(p);
}
__device__ __forceinline__ void split2h(float f0, float f1, uint32_t& h, uint32_t& l) {
    __half h0 = __float2half_rn(f0), h1 = __float2half_rn(f1);
    float r0 = f0 - __half2float(h0), r1 = f1 - __half2float(h1);
    __half e0 = __float2half_rn(r0), e1 = __float2half_rn(r1);
    h = (uint32_t)__half_as_ushort(h0) | ((uint32_t)__half_as_ushort(h1) << 16);
    l = (uint32_t)__half_as_ushort(e0) | ((uint32_t)__half_as_ushort(e1) << 16);
}
__device__ __forceinline__ uint32_t pack2h(float f0, float f1) {
    __half2 v = __floats2half2_rn(f0, f1);
    return *reinterpret_cast<uint32_t*>(&v);
}
__device__ __forceinline__ void ldsm4(uint32_t r[4], uint32_t a) {
    asm volatile("ldmatrix.sync.aligned.m8n8.x4.shared.b16 {%0,%1,%2,%3}, [%4];"
                 : "=r"(r[0]), "=r"(r[1]), "=r"(r[2]), "=r"(r[3]) : "r"(a));
}
__device__ __forceinline__ void ldsm4t(uint32_t r[4], uint32_t a) {
    asm volatile("ldmatrix.sync.aligned.m8n8.x4.trans.shared.b16 {%0,%1,%2,%3}, [%4];"
                 : "=r"(r[0]), "=r"(r[1]), "=r"(r[2]), "=r"(r[3]) : "r"(a));
}
__device__ __forceinline__ void mma_f16(float d[4], const uint32_t a[4], const uint32_t b[2]) {
    asm volatile("mma.sync.aligned.m16n8k16.row.col.f32.f16.f16.f32 "
                 "{%0,%1,%2,%3}, {%4,%5,%6,%7}, {%8,%9}, {%0,%1,%2,%3};"
                 : "+f"(d[0]), "+f"(d[1]), "+f"(d[2]), "+f"(d[3])
                 : "r"(a[0]), "r"(a[1]), "r"(a[2]), "r"(a[3]), "r"(b[0]), "r"(b[1]));
}
__device__ __forceinline__ void cp16(uint32_t dst, const void* src) {
    asm volatile("cp.async.cg.shared.global [%0], [%1], 16;" :: "r"(dst), "l"(src));
}

// ---------------- prepass: fp32 -> fp16 ----------------
__global__ __launch_bounds__(256) void split_h16_kernel(const float4* __restrict__ src,
                                                        uint2* __restrict__ hi, int n4) {
    int i = blockIdx.x * blockDim.x + threadIdx.x;
    if (i >= n4) return;
    float4 v = src[i];
    hi[i] = make_uint2(pack2h(v.x, v.y), pack2h(v.z, v.w));
}

// ---------------- GEMM (fp16, 1-term): C = Ah * Bh^T ------------------------
// BM=128, BN=128, BK=64, 2 stages, 2 CTAs/SM. 8 warps 4(m)x2(n).
// HALF_OUT: write fp16 (Ch); else fp32 (C).
#define GPAD 72
#define HARR (128 * GPAD * 2)                 // 18432 B per array
#define HSTAGE (2 * HARR)                     // 36864
#define G1_SMEM (2 * HSTAGE)                  // 73728 -> 2 CTAs/SM

template <bool HALF_OUT>
__global__ __launch_bounds__(256, 2) void gemm_h_kernel(
    const __half* __restrict__ Ah, const __half* __restrict__ Bh,
    float* __restrict__ C, __half* __restrict__ Ch, int N, int K)
{
    extern __shared__ char smem[];
    const uint32_t sb = cvta_s(smem);

    const int tid = threadIdx.x, warp = tid >> 5, lane = tid & 31;
    const int m0 = blockIdx.x * 128;
    const int n0 = blockIdx.y * 128;

    const int wm = warp >> 1, wn = warp & 1;
    const int la = (lane & 15) * GPAD + ((lane >> 4) << 3);
    const int lb = (((lane >> 4) << 3) + (lane & 7)) * GPAD + (((lane >> 3) & 1) << 3);

    const int nk = K >> 6;  // K / 64

    auto load_stage = [&](int s, int kt) {
        const uint32_t base = sb + s * HSTAGE;
        const int k0 = kt << 6;
#pragma unroll
        for (int t = 0; t < 4; t++) {
            int idx = tid + t * 256;
            int r = idx >> 3, c = idx & 7;
            uint32_t off = (uint32_t)(r * (GPAD * 2) + c * 16);
            cp16(base + off,        Ah + (size_t)(m0 + r) * K + k0 + c * 8);
            cp16(base + HARR + off, Bh + (size_t)(n0 + r) * K + k0 + c * 8);
        }
        asm volatile("cp.async.commit_group;" ::: "memory");
    };

    float acc[2][8][4] = {};
    load_stage(0, 0);

#pragma unroll 1
    for (int kt = 0; kt < nk; kt++) {
        const int cur = kt & 1;
        __syncthreads();
        if (kt + 1 < nk) {
            load_stage(cur ^ 1, kt + 1);
            asm volatile("cp.async.wait_group 1;" ::: "memory");
        } else {
            asm volatile("cp.async.wait_group 0;" ::: "memory");
        }
        __syncthreads();

        const uint32_t bAh = sb + cur * HSTAGE;
        const uint32_t bBh = bAh + HARR;

#pragma unroll
        for (int kk = 0; kk < 4; kk++) {
            uint32_t Afh[2][4];
#pragma unroll
            for (int mi = 0; mi < 2; mi++) {
                uint32_t off = (uint32_t)(((wm * 32 + mi * 16) * GPAD + kk * 16 + la) << 1);
                ldsm4(Afh[mi], bAh + off);
            }
            uint32_t Bfh[8][2];
#pragma unroll
            for (int ni = 0; ni < 4; ni++) {
                uint32_t t4[4];
                uint32_t off = (uint32_t)(((wn * 64 + ni * 16) * GPAD + kk * 16 + lb) << 1);
                ldsm4(t4, bBh + off);
                Bfh[2 * ni][0] = t4[0]; Bfh[2 * ni][1] = t4[1];
                Bfh[2 * ni + 1][0] = t4[2]; Bfh[2 * ni + 1][1] = t4[3];
            }
#pragma unroll
            for (int mi = 0; mi < 2; mi++)
#pragma unroll
                for (int nj = 0; nj < 8; nj++)
                    mma_f16(acc[mi][nj], Afh[mi], Bfh[nj]);
        }
    }

    const int g = lane >> 2, t = lane & 3;
#pragma unroll
    for (int mi = 0; mi < 2; mi++) {
        int r = m0 + wm * 32 + mi * 16 + g;
#pragma unroll
        for (int nj = 0; nj < 8; nj++) {
            int c = n0 + wn * 64 + nj * 8 + t * 2;
            if (HALF_OUT) {
                __stcs(reinterpret_cast<uint32_t*>(Ch + (size_t)r * N + c),
                       pack2h(acc[mi][nj][0], acc[mi][nj][1]));
                __stcs(reinterpret_cast<uint32_t*>(Ch + (size_t)(r + 8) * N + c),
                       pack2h(acc[mi][nj][2], acc[mi][nj][3]));
            } else {
                __stcs(reinterpret_cast<float2*>(C + (size_t)r * N + c),
                       make_float2(acc[mi][nj][0], acc[mi][nj][1]));
                __stcs(reinterpret_cast<float2*>(C + (size_t)(r + 8) * N + c),
                       make_float2(acc[mi][nj][2], acc[mi][nj][3]));
            }
        }
    }
}

// ---------------- flash attention: 128-row q tiles ------------------------
// QK: Qh*Kh (1-term). PV: Ph*Vh + Pl*Vh (P split). fp32 online softmax.
#define APAD 136
#define KARR (64 * APAD * 2)
#define ATTN_SMEM ((128 + 4 * 64) * APAD * 2)   // 104448 B

__global__ __launch_bounds__(256) void attn_kernel(const __half* __restrict__ qh,
                                                   __half* __restrict__ ath)
{
    extern __shared__ __half smA[];
    __half* sQh = smA;
    const uint32_t QhB = cvta_s(sQh);
    const uint32_t KVB = cvta_s(sQh + 128 * APAD);

    const int tid = threadIdx.x, lane = tid & 31, warp = tid >> 5;
    const int bq = gridDim.x - 1 - blockIdx.x;    // heavy tiles first
    const int h = blockIdx.y;
    const int q0 = bq * 128;
    const int nkb = 2 * (bq + 1);
    const float slope = (h < 32) ? exp2f(-0.25f * (float)(h + 1))
                                 : exp2f(-0.125f * (float)(2 * (h - 32) + 1));
    const float scale = 0.08838834764831845f;

#pragma unroll
    for (int j = 0; j < 8; j++) {
        int c = tid + j * 256;
        int row = c >> 4, col8 = c & 15;
        uint32_t off = (uint32_t)((row * APAD + col8 * 8) * 2);
        cp16(QhB + off, qh + (size_t)(q0 + row) * QKVN + h * 128 + col8 * 8);
    }

    auto load_kv = [&](int buf, int kb) {
        const uint32_t base = KVB + (uint32_t)buf * (2 * KARR);
#pragma unroll
        for (int j = 0; j < 4; j++) {
            int c = tid + j * 256;
            int row = c >> 4, col8 = c & 15;
            uint32_t off = (uint32_t)((row * APAD + col8 * 8) * 2);
            size_t gk = (size_t)(kb * 64 + row) * QKVN + HID + h * 128 + col8 * 8;
            cp16(base + off,        qh + gk);
            cp16(base + KARR + off, qh + gk + HID);
        }
        asm volatile("cp.async.commit_group;" ::: "memory");
    };

    load_kv(0, 0);

    float m0 = -1e30f, m1 = -1e30f, l0 = 0.f, l1 = 0.f;
    float o[16][4] = {};

    const int qm = warp * 16;
    const int g = lane >> 2, t = lane & 3;
    const int la = (lane & 15) * APAD + ((lane >> 4) << 3);
    const int lb = (((lane >> 4) << 3) + (lane & 7)) * APAD + (((lane >> 3) & 1) << 3);
    const int lv = ((((lane >> 3) & 1) << 3) + (lane & 7)) * APAD + ((lane >> 4) << 3);
    const int qpos0 = q0 + qm + g, qpos1 = qpos0 + 8;

#pragma unroll 1
    for (int kb = 0; kb < nkb; kb++) {
        const int cur = kb & 1;
        __syncthreads();
        if (kb + 1 < nkb) {
            load_kv(cur ^ 1, kb + 1);
            asm volatile("cp.async.wait_group 1;" ::: "memory");
        } else {
            asm volatile("cp.async.wait_group 0;" ::: "memory");
        }
        __syncthreads();

        const uint32_t KhB = KVB + (uint32_t)cur * (2 * KARR);
        const uint32_t VhB = KhB + KARR;

        float sc[8][4];
#pragma unroll
        for (int i = 0; i < 8; i++)
#pragma unroll
            for (int j = 0; j < 4; j++) sc[i][j] = 0.f;

#pragma unroll
        for (int kc = 0; kc < 8; kc++) {
            uint32_t qfh[4];
            ldsm4(qfh, QhB + (uint32_t)((qm * APAD + kc * 16 + la) << 1));
#pragma unroll
            for (int np = 0; np < 4; np++) {
                uint32_t th[4];
                uint32_t off = (uint32_t)(((np * 16) * APAD + kc * 16 + lb) << 1);
                ldsm4(th, KhB + off);
                uint32_t bh0[2] = {th[0], th[1]}, bh1[2] = {th[2], th[3]};
                mma_f16(sc[2 * np],     qfh, bh0);
                mma_f16(sc[2 * np + 1], qfh, bh1);
            }
        }

        float mt0 = -1e30f, mt1 = -1e30f;
#pragma unroll
        for (int nt = 0; nt < 8; nt++) {
#pragma unroll
            for (int c = 0; c < 2; c++) {
                int kv = kb * 64 + nt * 8 + t * 2 + c;
                float s0 = (kv <= qpos0) ? fmaf(sc[nt][c], scale, -slope * (float)(qpos0 - kv)) : -1e30f;
                float s1 = (kv <= qpos1) ? fmaf(sc[nt][2 + c], scale, -slope * (float)(qpos1 - kv)) : -1e30f;
                sc[nt][c] = s0; sc[nt][2 + c] = s1;
                mt0 = fmaxf(mt0, s0); mt1 = fmaxf(mt1, s1);
            }
        }
        mt0 = fmaxf(mt0, __shfl_xor_sync(0xffffffffu, mt0, 1));
        mt0 = fmaxf(mt0, __shfl_xor_sync(0xffffffffu, mt0, 2));
        mt1 = fmaxf(mt1, __shfl_xor_sync(0xffffffffu, mt1, 1));
        mt1 = fmaxf(mt1, __shfl_xor_sync(0xffffffffu, mt1, 2));
        float mn0 = fmaxf(m0, mt0), mn1 = fmaxf(m1, mt1);
        float f0 = __expf(m0 - mn0), f1 = __expf(m1 - mn1);
        m0 = mn0; m1 = mn1;

        float s0 = 0.f, s1 = 0.f;
#pragma unroll
        for (int nt = 0; nt < 8; nt++) {
            float p0 = __expf(sc[nt][0] - m0), p1 = __expf(sc[nt][1] - m0);
            float p2 = __expf(sc[nt][2] - m1), p3 = __expf(sc[nt][3] - m1);
            sc[nt][0] = p0; sc[nt][1] = p1; sc[nt][2] = p2; sc[nt][3] = p3;
            s0 += p0 + p1; s1 += p2 + p3;
        }
        s0 += __shfl_xor_sync(0xffffffffu, s0, 1);
        s0 += __shfl_xor_sync(0xffffffffu, s0, 2);
        s1 += __shfl_xor_sync(0xffffffffu, s1, 1);
        s1 += __shfl_xor_sync(0xffffffffu, s1, 2);
        l0 = l0 * f0 + s0;
        l1 = l1 * f1 + s1;
#pragma unroll
        for (int db = 0; db < 16; db++) {
            o[db][0] *= f0; o[db][1] *= f0; o[db][2] *= f1; o[db][3] *= f1;
        }

#pragma unroll
        for (int kc2 = 0; kc2 < 4; kc2++) {
            uint32_t ph2[4], pl2[4];
            split2h(sc[2 * kc2][0],     sc[2 * kc2][1],     ph2[0], pl2[0]);
            split2h(sc[2 * kc2][2],     sc[2 * kc2][3],     ph2[1], pl2[1]);
            split2h(sc[2 * kc2 + 1][0], sc[2 * kc2 + 1][1], ph2[2], pl2[2]);
            split2h(sc[2 * kc2 + 1][2], sc[2 * kc2 + 1][3], ph2[3], pl2[3]);
#pragma unroll
            for (int d16 = 0; d16 < 8; d16++) {
                uint32_t vh[4];
                uint32_t off = (uint32_t)((kc2 * 16 * APAD + d16 * 16 + lv) << 1);
                ldsm4t(vh, VhB + off);
                uint32_t bh0[2] = {vh[0], vh[1]}, bh1[2] = {vh[2], vh[3]};
                mma_f16(o[2 * d16],     ph2, bh0);
                mma_f16(o[2 * d16],     pl2, bh0);
                mma_f16(o[2 * d16 + 1], ph2, bh1);
                mma_f16(o[2 * d16 + 1], pl2, bh1);
            }
        }
    }

    float inv0 = 1.f / l0, inv1 = 1.f / l1;
#pragma unroll
    for (int db = 0; db < 16; db++) {
        int col = h * 128 + db * 8 + t * 2;
        int r0 = q0 + qm + g;
        __stcs(reinterpret_cast<uint32_t*>(ath + (size_t)r0 * HID + col),
               pack2h(o[db][0] * inv0, o[db][1] * inv0));
        __stcs(reinterpret_cast<uint32_t*>(ath + (size_t)(r0 + 8) * HID + col),
               pack2h(o[db][2] * inv1, o[db][3] * inv1));
    }
}

// ---------------------------------------------------------------------------
extern "C" void kernel_launch(void* const* d_in, const int* in_sizes, int n_in,
                              void* d_out, int out_size) {
    const float* hs = (const float*)d_in[0];   // [1,2048,5120]
    const float* wp = (const float*)d_in[1];   // [15360,5120]
    const float* wo = (const float*)d_in[2];   // [5120,5120]
    float* out = (float*)d_out;                // [1,2048,5120]

    __half *qkh, *hsh, *wph, *woh, *ath;
    cudaGetSymbolAddress((void**)&qkh, g_qk_h);
    cudaGetSymbolAddress((void**)&hsh, g_hs_h);
    cudaGetSymbolAddress((void**)&wph, g_wp_h);
    cudaGetSymbolAddress((void**)&woh, g_wo_h);
    cudaGetSymbolAddress((void**)&ath, g_at_h);

    // prepasses: fp32 -> fp16
    {
        int n4 = SEQ * HID / 4;
        split_h16_kernel<<<(n4 + 255) / 256, 256>>>((const float4*)hs, (uint2*)hsh, n4);
        n4 = QKVN * HID / 4;
        split_h16_kernel<<<(n4 + 255) / 256, 256>>>((const float4*)wp, (uint2*)wph, n4);
        n4 = HID * HID / 4;
        split_h16_kernel<<<(n4 + 255) / 256, 256>>>((const float4*)wo, (uint2*)woh, n4);
    }

    cudaFuncSetAttribute((const void*)gemm_h_kernel<true>,
                         cudaFuncAttributeMaxDynamicSharedMemorySize, G1_SMEM);
    cudaFuncSetAttribute((const void*)gemm_h_kernel<false>,
                         cudaFuncAttributeMaxDynamicSharedMemorySize, G1_SMEM);
    cudaFuncSetAttribute((const void*)attn_kernel,
                         cudaFuncAttributeMaxDynamicSharedMemorySize, ATTN_SMEM);

    // QKV projection (fp16 1-term, BK=64) -> fp16 [2048,15360]
    gemm_h_kernel<true><<<dim3(SEQ / 128, QKVN / 128), 256, G1_SMEM>>>(
        hsh, wph, nullptr, qkh, QKVN, HID);

    // attention (QK 1-term; PV 2-term P-split; writes fp16)
    attn_kernel<<<dim3(SEQ / 128, 40), 256, ATTN_SMEM>>>(qkh, ath);

    // o_proj (fp16 1-term, BK=64) -> fp32 out
    gemm_h_kernel<false><<<dim3(SEQ / 128, HID / 128), 256, G1_SMEM>>>(
        ath, woh, out, nullptr, HID, HID);
}